// round 10
// baseline (speedup 1.0000x reference)
#include <cuda_runtime.h>
#include <math.h>

#define N_NODES 50000
#define NFEAT   64
#define NHID    64
#define E_REAL  200000
#define E_NHOP  40000
#define E_ALL   240000
#define N_REL   200
#define OUTF    128
#define ALPHA   0.2f

typedef unsigned long long ull;

// ---------------- device scratch ----------------
__device__ __align__(16) float g_P1all[(size_t)N_NODES * 512];     // [i][dir*256+role*128+h*64+j]
__device__ __align__(16) float g_Q1all[(size_t)E_REAL * 256];      // [e][c*64+j]
__device__ __align__(16) float g_R1proj[N_REL * 256];              // [r*256 + c*64 + j]
__device__ __align__(16) float g_R2proj[N_REL * OUTF];
__device__ __align__(16) float g_rowsum1T[(size_t)N_NODES * 4];    // [i*4 + c]
__device__ __align__(16) float g_hp1[2][(size_t)N_NODES * 128];
__device__ __align__(16) float g_xs[2][(size_t)N_NODES * OUTF];
__device__ __align__(16) float g_P2all[2][(size_t)N_NODES * 256];
__device__ float g_rowsum2[2][N_NODES];
__device__ __align__(16) float g_hp2[2][(size_t)N_NODES * OUTF];
__device__ __align__(16) float g_y[2][(size_t)N_NODES * OUTF];
__device__ float g_wsum[2];
// packed weights (row-major [n][K])
__device__ __align__(16) float g_Wp1[512 * 64];
__device__ __align__(16) float g_WpQ[256 * 64];
__device__ __align__(16) float g_Wp2[256 * 128];
__device__ __align__(16) float g_WeP[64 * 128];                    // [j][k]
// factorized attention scalars
__device__ __align__(16) float g_S1[(size_t)N_NODES * 8];
__device__ __align__(16) float g_SQ1[(size_t)E_REAL * 4];
__device__ __align__(16) float g_Sr1[N_REL * 4];
__device__ __align__(16) float g_S2[2][(size_t)N_NODES * 4];
__device__ float g_Srel2[N_REL];
// per-column dot weights
__device__ __align__(16) float g_a2cat1[512];
__device__ __align__(16) float g_a2catQ[256];
__device__ __align__(16) float g_a2cat2[256];

#define RED4(ptr, a, b, c, d) \
    asm volatile("red.global.add.v4.f32 [%0], {%1, %2, %3, %4};" :: "l"(ptr), "f"(a), "f"(b), "f"(c), "f"(d) : "memory")
#define PACK64(dst, lo, hi) \
    asm("mov.b64 %0, {%1, %2};" : "=l"(dst) : "f"(lo), "f"(hi))

// ---------------- fused setup ----------------
__global__ void setup(const float* __restrict__ a_in, const float* __restrict__ a_out,
                      const float* __restrict__ a_o,
                      const float* __restrict__ a2_in, const float* __restrict__ a2_out,
                      const float* __restrict__ a2_o,
                      const float* __restrict__ rel, const float* __restrict__ W,
                      const float* __restrict__ We, float* __restrict__ out_tail) {
    int b = blockIdx.x, t = threadIdx.x;
    if (b < 512) {
        size_t tid = (size_t)b * 256 + t, stride = (size_t)512 * 256;
        float4 z = make_float4(0.f, 0.f, 0.f, 0.f);
        float4* hp1 = (float4*)&g_hp1[0][0];
        for (size_t i = tid; i < (size_t)2 * N_NODES * 32; i += stride) hp1[i] = z;
        float4* hp2 = (float4*)&g_hp2[0][0];
        for (size_t i = tid; i < (size_t)2 * N_NODES * 32; i += stride) hp2[i] = z;
        float4* rs1 = (float4*)&g_rowsum1T[0];
        for (size_t i = tid; i < (size_t)N_NODES; i += stride) rs1[i] = z;
        float4* rs2 = (float4*)&g_rowsum2[0][0];
        for (size_t i = tid; i < (size_t)N_NODES / 2; i += stride) rs2[i] = z;
        if (tid < 2) g_wsum[tid] = 0.f;
    } else if (b < 516) {
        for (int idx = (b - 512) * 256 + t; idx < 512 * 64; idx += 4 * 256) {
            int n = idx >> 6, k = idx & 63;
            int dir = n >> 8, role = (n >> 7) & 1, h = (n >> 6) & 1, j = n & 63;
            const float* A = (dir ? a_out : a_in) + (size_t)h * 64 * 192;
            g_Wp1[idx] = A[j * 192 + role * 64 + k];
        }
    } else if (b < 518) {
        for (int idx = (b - 516) * 256 + t; idx < 256 * 64; idx += 2 * 256) {
            int n = idx >> 6, k = idx & 63;
            int c = n >> 6, j = n & 63;
            const float* A = ((c >> 1) ? a_out : a_in) + (size_t)(c & 1) * 64 * 192;
            g_WpQ[idx] = A[j * 192 + 128 + k];
        }
    } else if (b < 522) {
        for (int idx = (b - 518) * 256 + t; idx < 256 * 128; idx += 4 * 256) {
            int n = idx >> 7, k = idx & 127;
            int role = n >> 7, j = n & 127;
            g_Wp2[idx] = a_o[j * 384 + role * 128 + k];
        }
    } else if (b < 524) {
        for (int idx = (b - 522) * 256 + t; idx < 64 * 128; idx += 2 * 256) {
            int j = idx >> 7, k = idx & 127;
            g_WeP[idx] = We[k * 64 + j];
        }
    } else if (b == 524) {
        for (int n = t; n < 512; n += 256) {
            int dir = n >> 8, h = (n >> 6) & 1, j = n & 63;
            g_a2cat1[n] = (dir ? a2_out : a2_in)[h * 64 + j];
        }
        for (int n = t; n < 256; n += 256) {
            int c = n >> 6, j = n & 63;
            g_a2catQ[n] = ((c >> 1) ? a2_out : a2_in)[(c & 1) * 64 + j];
        }
        if (t < 256) g_a2cat2[t] = a2_o[t & 127];
    } else {
        int r = b - 525;  // [0, 200)
        __shared__ float relrow[64];
        __shared__ float rel2row[128];
        __shared__ float red[8];
        if (t < 64) relrow[t] = rel[r * 64 + t];
        __syncthreads();
        if (t < 128) {
            float acc = 0.f;
            #pragma unroll
            for (int k = 0; k < 64; k++) acc += relrow[k] * W[k * 128 + t];
            rel2row[t] = acc;
            out_tail[(size_t)N_NODES * OUTF + r * 128 + t] = acc;
        }
        __syncthreads();
        {
            int c = t >> 6, j = t & 63;
            const float* A = ((c >> 1) ? a_out : a_in) + (size_t)(c & 1) * 64 * 192;
            float acc = 0.f;
            #pragma unroll
            for (int k = 0; k < 64; k++) acc += relrow[k] * A[j * 192 + 128 + k];
            g_R1proj[r * 256 + t] = acc;
            float part = acc * ((c >> 1) ? a2_out : a2_in)[(c & 1) * 64 + j];
            #pragma unroll
            for (int o = 16; o; o >>= 1) part += __shfl_xor_sync(0xffffffffu, part, o);
            if ((t & 31) == 0) red[t >> 5] = part;
        }
        __syncthreads();
        if (t < 4) g_Sr1[r * 4 + t] = red[2 * t] + red[2 * t + 1];
        __syncthreads();
        {
            float part = 0.f;
            if (t < 128) {
                float acc = 0.f;
                #pragma unroll 16
                for (int k = 0; k < 128; k++) acc += rel2row[k] * a_o[t * 384 + 256 + k];
                g_R2proj[r * 128 + t] = acc;
                part = acc * a2_o[t];
            }
            #pragma unroll
            for (int o = 16; o; o >>= 1) part += __shfl_xor_sync(0xffffffffu, part, o);
            if ((t & 31) == 0 && t < 128) red[t >> 5] = part;
        }
        __syncthreads();
        if (t == 0) g_Srel2[r] = red[0] + red[1] + red[2] + red[3];
    }
}

// ---------------- f32x2 GEMM: contiguous-8 column ownership, float4 smem loads ----------------
#define KC 16
__global__ void __launch_bounds__(256, 2)
gemm_f32x2(const float* __restrict__ X,
           const float* __restrict__ Wp,
           float* __restrict__ C,
           const float* __restrict__ a2cat,
           float* __restrict__ sOut,
           int M, int N, int K) {
    __shared__ __align__(16) float2 Xs2[KC][130];  // {x,x} pre-dup
    __shared__ __align__(16) float  As[KC][132];
    int t = threadIdx.x;
    int tx = t & 15, ty = t >> 4;
    int lane = t & 31;
    int ib = blockIdx.x * 128;
    int jb = blockIdx.y * 128;
    ull acc[8][4];
    #pragma unroll
    for (int ii = 0; ii < 8; ii++)
        #pragma unroll
        for (int q = 0; q < 4; q++) acc[ii][q] = 0ull;

    for (int kc = 0; kc < K; kc += KC) {
        #pragma unroll
        for (int p = t; p < 512; p += 256) {
            int i = p & 127, kq = (p >> 7) * 4;
            int gi = ib + i;
            float4 v = make_float4(0.f, 0.f, 0.f, 0.f);
            if (gi < M) v = *(const float4*)&X[(size_t)gi * K + kc + kq];
            Xs2[kq + 0][i] = make_float2(v.x, v.x);
            Xs2[kq + 1][i] = make_float2(v.y, v.y);
            Xs2[kq + 2][i] = make_float2(v.z, v.z);
            Xs2[kq + 3][i] = make_float2(v.w, v.w);
        }
        #pragma unroll
        for (int p = t; p < 512; p += 256) {
            int j = p & 127, kq = (p >> 7) * 4;
            float4 v = *(const float4*)&Wp[(size_t)(jb + j) * K + kc + kq];
            As[kq + 0][j] = v.x; As[kq + 1][j] = v.y;
            As[kq + 2][j] = v.z; As[kq + 3][j] = v.w;
        }
        __syncthreads();
        #pragma unroll
        for (int kk = 0; kk < KC; kk++) {
            float4 a0 = *(const float4*)&As[kk][8 * tx];
            float4 a1 = *(const float4*)&As[kk][8 * tx + 4];
            ull av[4];
            PACK64(av[0], a0.x, a0.y); PACK64(av[1], a0.z, a0.w);
            PACK64(av[2], a1.x, a1.y); PACK64(av[3], a1.z, a1.w);
            const float4* xp = (const float4*)&Xs2[kk][ty * 8];
            #pragma unroll
            for (int u = 0; u < 4; u++) {
                float4 xv = xp[u];
                ull x0, x1;
                PACK64(x0, xv.x, xv.y);
                PACK64(x1, xv.z, xv.w);
                #pragma unroll
                for (int q = 0; q < 4; q++)
                    asm("fma.rn.f32x2 %0, %1, %2, %0;"
                        : "+l"(acc[2 * u][q]) : "l"(x0), "l"(av[q]));
                #pragma unroll
                for (int q = 0; q < 4; q++)
                    asm("fma.rn.f32x2 %0, %1, %2, %0;"
                        : "+l"(acc[2 * u + 1][q]) : "l"(x1), "l"(av[q]));
            }
        }
        __syncthreads();
    }
    int nBlk = N >> 6;
    float4 w0 = *(const float4*)&a2cat[jb + 8 * tx];
    float4 w1 = *(const float4*)&a2cat[jb + 8 * tx + 4];
    #pragma unroll
    for (int ii = 0; ii < 8; ii++) {
        int gi = ib + ty * 8 + ii;
        float lo[4], hi[4];
        #pragma unroll
        for (int q = 0; q < 4; q++)
            asm("mov.b64 {%0, %1}, %2;" : "=f"(lo[q]), "=f"(hi[q]) : "l"(acc[ii][q]));
        if (gi < M) {
            *(float4*)&C[(size_t)gi * N + jb + 8 * tx]     = make_float4(lo[0], hi[0], lo[1], hi[1]);
            *(float4*)&C[(size_t)gi * N + jb + 8 * tx + 4] = make_float4(lo[2], hi[2], lo[3], hi[3]);
        }
        float s = lo[0] * w0.x + hi[0] * w0.y + lo[1] * w0.z + hi[1] * w0.w
                + lo[2] * w1.x + hi[2] * w1.y + lo[3] * w1.z + hi[3] * w1.w;
        #pragma unroll
        for (int o = 4; o; o >>= 1) s += __shfl_xor_sync(0xffffffffu, s, o);
        if ((lane & 7) == 0 && gi < M)
            sOut[(size_t)gi * nBlk + (jb >> 6) + ((lane >> 3) & 1)] = s;
    }
}

// ---------------- gemm_we: y@We with fused tanh-dot epilogue (no tw buffer) ----------------
__global__ void __launch_bounds__(256, 2)
gemm_we(const float* __restrict__ X, const float* __restrict__ Wp,
        const float* __restrict__ be, const float* __restrict__ qe) {
    __shared__ __align__(16) float2 Xs2[KC][130];
    __shared__ __align__(16) float  As[KC][68];
    __shared__ float s_sh[2];
    int t = threadIdx.x;
    int tx = t & 7, ty = t >> 3;    // 8 col-groups x 32 row-groups (4 rows each)
    int lane = t & 31;
    int ib = blockIdx.x * 128;
    const int M = 2 * N_NODES;
    if (t < 2) s_sh[t] = 0.f;
    ull acc[4][4];
    #pragma unroll
    for (int ii = 0; ii < 4; ii++)
        #pragma unroll
        for (int q = 0; q < 4; q++) acc[ii][q] = 0ull;

    for (int kc = 0; kc < 128; kc += KC) {
        #pragma unroll
        for (int p = t; p < 512; p += 256) {
            int i = p & 127, kq = (p >> 7) * 4;
            int gi = ib + i;
            float4 v = make_float4(0.f, 0.f, 0.f, 0.f);
            if (gi < M) v = *(const float4*)&X[(size_t)gi * 128 + kc + kq];
            Xs2[kq + 0][i] = make_float2(v.x, v.x);
            Xs2[kq + 1][i] = make_float2(v.y, v.y);
            Xs2[kq + 2][i] = make_float2(v.z, v.z);
            Xs2[kq + 3][i] = make_float2(v.w, v.w);
        }
        {
            int p = t & 255;
            int j = p & 63, kq = (p >> 6) * 4;
            float4 v = *(const float4*)&Wp[j * 128 + kc + kq];
            As[kq + 0][j] = v.x; As[kq + 1][j] = v.y;
            As[kq + 2][j] = v.z; As[kq + 3][j] = v.w;
        }
        __syncthreads();
        #pragma unroll
        for (int kk = 0; kk < KC; kk++) {
            float4 a0 = *(const float4*)&As[kk][8 * tx];
            float4 a1 = *(const float4*)&As[kk][8 * tx + 4];
            ull av[4];
            PACK64(av[0], a0.x, a0.y); PACK64(av[1], a0.z, a0.w);
            PACK64(av[2], a1.x, a1.y); PACK64(av[3], a1.z, a1.w);
            const float4* xp = (const float4*)&Xs2[kk][ty * 4];
            #pragma unroll
            for (int u = 0; u < 2; u++) {
                float4 xv = xp[u];
                ull x0, x1;
                PACK64(x0, xv.x, xv.y);
                PACK64(x1, xv.z, xv.w);
                #pragma unroll
                for (int q = 0; q < 4; q++)
                    asm("fma.rn.f32x2 %0, %1, %2, %0;"
                        : "+l"(acc[2 * u][q]) : "l"(x0), "l"(av[q]));
                #pragma unroll
                for (int q = 0; q < 4; q++)
                    asm("fma.rn.f32x2 %0, %1, %2, %0;"
                        : "+l"(acc[2 * u + 1][q]) : "l"(x1), "l"(av[q]));
            }
        }
        __syncthreads();
    }
    float4 b0 = *(const float4*)&be[8 * tx];
    float4 b1 = *(const float4*)&be[8 * tx + 4];
    float4 q0 = *(const float4*)&qe[8 * tx];
    float4 q1 = *(const float4*)&qe[8 * tx + 4];
    #pragma unroll
    for (int ii = 0; ii < 4; ii++) {
        int gi = ib + ty * 4 + ii;
        float lo[4], hi[4];
        #pragma unroll
        for (int q = 0; q < 4; q++)
            asm("mov.b64 {%0, %1}, %2;" : "=f"(lo[q]), "=f"(hi[q]) : "l"(acc[ii][q]));
        float s = tanhf(lo[0] + b0.x) * q0.x + tanhf(hi[0] + b0.y) * q0.y
                + tanhf(lo[1] + b0.z) * q0.z + tanhf(hi[1] + b0.w) * q0.w
                + tanhf(lo[2] + b1.x) * q1.x + tanhf(hi[2] + b1.y) * q1.y
                + tanhf(lo[3] + b1.z) * q1.z + tanhf(hi[3] + b1.w) * q1.w;
        #pragma unroll
        for (int o = 4; o; o >>= 1) s += __shfl_xor_sync(0xffffffffu, s, o);
        if ((lane & 7) == 0 && gi < M)
            atomicAdd(&s_sh[gi >= N_NODES], s);
    }
    __syncthreads();
    if (t < 2) atomicAdd(&g_wsum[t], s_sh[t]);
}

// ---------------- layer-1 edge pass ----------------
__global__ void edge_pass1(const int* __restrict__ el, const int* __restrict__ eln,
                           const int* __restrict__ etn) {
    int dir = blockIdx.y;
    int e = blockIdx.x * 8 + (threadIdx.x >> 5);
    int lane = threadIdx.x & 31;
    int h = lane >> 4;
    int jj = 4 * (lane & 15);
    int i0, i1;
    float4 q;
    float sq;
    if (e < E_REAL) {
        i0 = el[e]; i1 = el[E_REAL + e];
        q = *(const float4*)&g_Q1all[(size_t)e * 256 + dir * 128 + h * 64 + jj];
        sq = g_SQ1[(size_t)e * 4 + dir * 2 + h];
    } else {
        int en = e - E_REAL;
        i0 = eln[en]; i1 = eln[E_NHOP + en];
        int t0 = etn[2 * en], t1 = etn[2 * en + 1];
        float4 qa = *(const float4*)&g_R1proj[t0 * 256 + dir * 128 + h * 64 + jj];
        float4 qb = *(const float4*)&g_R1proj[t1 * 256 + dir * 128 + h * 64 + jj];
        q.x = qa.x + qb.x; q.y = qa.y + qb.y; q.z = qa.z + qb.z; q.w = qa.w + qb.w;
        sq = g_Sr1[t0 * 4 + dir * 2 + h] + g_Sr1[t1 * 4 + dir * 2 + h];
    }
    int src = dir ? i1 : i0;
    int dst = dir ? i0 : i1;
    float score = g_S1[(size_t)src * 8 + dir * 4 + h]
                + g_S1[(size_t)dst * 8 + dir * 4 + 2 + h] + sq;
    float lk = score > 0.f ? score : ALPHA * score;
    float ev = __expf(-lk);
    float4 d = *(const float4*)&g_P1all[(size_t)dst * 512 + dir * 256 + 128 + h * 64 + jj];
    float* hp = &g_hp1[dir][(size_t)src * 128 + h * 64 + jj];
    RED4(hp, ev * (d.x + q.x), ev * (d.y + q.y), ev * (d.z + q.z), ev * (d.w + q.w));
    if ((lane & 15) == 0) atomicAdd(&g_rowsum1T[(size_t)src * 4 + dir * 2 + h], ev);
}

// ---------------- normalize (+ fold p_src) + elu -> x_s ----------------
__global__ void norm1() {
    int dir = blockIdx.y;
    int idx = blockIdx.x * 256 + threadIdx.x;
    if (idx >= N_NODES * 128) return;
    int i = idx >> 7, kk = idx & 127;
    float rs = g_rowsum1T[(size_t)i * 4 + dir * 2 + (kk >> 6)];
    float v = g_hp1[dir][idx];
    v = (rs > 0.f) ? v / rs + g_P1all[(size_t)i * 512 + dir * 256 + kk] : 0.f;
    v = (v > 0.f) ? v : expm1f(v);
    g_xs[dir][idx] = v;
}

// ---------------- layer-2 edge pass ----------------
__global__ void edge_pass2(const int* __restrict__ el, const int* __restrict__ eln,
                           const int* __restrict__ et, const int* __restrict__ etn) {
    int dir = blockIdx.y;
    int e = blockIdx.x * 8 + (threadIdx.x >> 5);
    if (e >= E_ALL) return;
    int lane = threadIdx.x & 31;
    int i0, i1;
    float q0, q1, q2, q3, sq;
    if (e < E_REAL) {
        i0 = el[e]; i1 = el[E_REAL + e];
        int ty = et[e];
        float4 qv = *(const float4*)&g_R2proj[ty * 128 + 4 * lane];
        q0 = qv.x; q1 = qv.y; q2 = qv.z; q3 = qv.w;
        sq = g_Srel2[ty];
    } else {
        int en = e - E_REAL;
        i0 = eln[en]; i1 = eln[E_NHOP + en];
        int t0 = etn[2 * en], t1 = etn[2 * en + 1];
        float4 qa = *(const float4*)&g_R2proj[t0 * 128 + 4 * lane];
        float4 qb = *(const float4*)&g_R2proj[t1 * 128 + 4 * lane];
        q0 = qa.x + qb.x; q1 = qa.y + qb.y; q2 = qa.z + qb.z; q3 = qa.w + qb.w;
        sq = g_Srel2[t0] + g_Srel2[t1];
    }
    int seg = dir ? i1 : i0;
    int nbr = dir ? i0 : i1;
    float4 sA = *(const float4*)&g_S2[dir][(size_t)seg * 4];
    float4 sB = *(const float4*)&g_S2[dir][(size_t)nbr * 4];
    float score = sA.x + sA.y + sB.z + sB.w + sq;
    float lk = score > 0.f ? score : ALPHA * score;
    float ev = __expf(-lk);
    float4 dv = *(const float4*)&g_P2all[dir][(size_t)nbr * 256 + 128 + 4 * lane];
    float* hp = &g_hp2[dir][(size_t)seg * 128 + 4 * lane];
    RED4(hp, ev * (dv.x + q0), ev * (dv.y + q1), ev * (dv.z + q2), ev * (dv.w + q3));
    if (lane == 0) atomicAdd(&g_rowsum2[dir][seg], ev);
}

// ---------------- layer-2 normalize (+ fold p_seg) + elu -> y ----------------
__global__ void norm2() {
    int xs = blockIdx.y;
    int idx = blockIdx.x * 256 + threadIdx.x;
    if (idx >= N_NODES * 128) return;
    int i = idx >> 7, k = idx & 127;
    float rs = g_rowsum2[xs][i];
    float v = (rs > 0.f)
        ? g_hp2[xs][idx] / rs + g_P2all[xs][(size_t)i * 256 + k]
        : 0.f;
    v = (v > 0.f) ? v : expm1f(v);
    g_y[xs][idx] = v;
}

// ---------------- beta + combine ----------------
__global__ void combine(float* __restrict__ out) {
    float m0 = g_wsum[0] / (float)N_NODES;
    float m1 = g_wsum[1] / (float)N_NODES;
    float mx = fmaxf(m0, m1);
    float e0 = expf(m0 - mx), e1 = expf(m1 - mx);
    float b0 = e0 / (e0 + e1), b1 = e1 / (e0 + e1);
    size_t i = (size_t)blockIdx.x * 256 + threadIdx.x;
    if (i >= (size_t)N_NODES * OUTF) return;
    out[i] = b0 * g_y[0][i] + b1 * g_y[1][i];
}

// ---------------- launch ----------------
extern "C" void kernel_launch(void* const* d_in, const int* in_sizes, int n_in,
                              void* d_out, int out_size) {
    const float* ent   = (const float*)d_in[0];
    const float* rel   = (const float*)d_in[1];
    const int*   el    = (const int*)d_in[2];
    const int*   et    = (const int*)d_in[3];
    const float* eemb  = (const float*)d_in[4];
    const int*   eln   = (const int*)d_in[5];
    const int*   etn   = (const int*)d_in[6];
    const float* a_in  = (const float*)d_in[7];
    const float* a2_in = (const float*)d_in[8];
    const float* a_out = (const float*)d_in[9];
    const float* a2_out= (const float*)d_in[10];
    const float* a_o   = (const float*)d_in[11];
    const float* a2_o  = (const float*)d_in[12];
    const float* W     = (const float*)d_in[13];
    const float* We    = (const float*)d_in[14];
    const float* be    = (const float*)d_in[15];
    const float* qe    = (const float*)d_in[16];
    float* out = (float*)d_out;

    float *p1 = 0, *q1 = 0, *xsb = 0, *p2 = 0, *wp1 = 0, *wpq = 0, *wp2 = 0, *wep = 0;
    float *a2c1 = 0, *a2cq = 0, *a2c2 = 0, *s1 = 0, *sq1 = 0, *s2 = 0, *yb = 0;
    cudaGetSymbolAddress((void**)&p1, g_P1all);
    cudaGetSymbolAddress((void**)&q1, g_Q1all);
    cudaGetSymbolAddress((void**)&xsb, g_xs);
    cudaGetSymbolAddress((void**)&p2, g_P2all);
    cudaGetSymbolAddress((void**)&wp1, g_Wp1);
    cudaGetSymbolAddress((void**)&wpq, g_WpQ);
    cudaGetSymbolAddress((void**)&wp2, g_Wp2);
    cudaGetSymbolAddress((void**)&wep, g_WeP);
    cudaGetSymbolAddress((void**)&a2c1, g_a2cat1);
    cudaGetSymbolAddress((void**)&a2cq, g_a2catQ);
    cudaGetSymbolAddress((void**)&a2c2, g_a2cat2);
    cudaGetSymbolAddress((void**)&s1, g_S1);
    cudaGetSymbolAddress((void**)&sq1, g_SQ1);
    cudaGetSymbolAddress((void**)&s2, g_S2);
    cudaGetSymbolAddress((void**)&yb, g_y);

    setup<<<725, 256>>>(a_in, a_out, a_o, a2_in, a2_out, a2_o, rel, W, We, out);

    gemm_f32x2<<<dim3((N_NODES + 127) / 128, 4), 256>>>(ent, wp1, p1, a2c1, s1,
                                                        N_NODES, 512, 64);
    gemm_f32x2<<<dim3((E_REAL + 127) / 128, 2), 256>>>(eemb, wpq, q1, a2cq, sq1,
                                                       E_REAL, 256, 64);

    edge_pass1<<<dim3(E_ALL / 8, 2), 256>>>(el, eln, etn);
    norm1<<<dim3((N_NODES * 128 + 255) / 256, 2), 256>>>();

    for (int xs = 0; xs < 2; xs++)
        gemm_f32x2<<<dim3((N_NODES + 127) / 128, 2), 256>>>(
            xsb + (size_t)xs * N_NODES * 128, wp2,
            p2 + (size_t)xs * N_NODES * 256,
            a2c2, s2 + (size_t)xs * N_NODES * 4,
            N_NODES, 256, 128);

    edge_pass2<<<dim3(E_ALL / 8, 2), 256>>>(el, eln, et, etn);
    norm2<<<dim3((N_NODES * 128 + 255) / 256, 2), 256>>>();

    gemm_we<<<(2 * N_NODES + 127) / 128, 256>>>(yb, wep, be, qe);
    combine<<<(N_NODES * OUTF + 255) / 256, 256>>>(out);
}

// round 11
// speedup vs baseline: 1.1303x; 1.1303x over previous
#include <cuda_runtime.h>
#include <math.h>

#define N_NODES 50000
#define NFEAT   64
#define NHID    64
#define E_REAL  200000
#define E_NHOP  40000
#define E_ALL   240000
#define N_REL   200
#define OUTF    128
#define ALPHA   0.2f

typedef unsigned long long ull;

// ---------------- device scratch ----------------
__device__ __align__(16) float g_P1all[(size_t)N_NODES * 512];     // [i][dir*256+role*128+h*64+j]
__device__ __align__(16) float g_Q1all[(size_t)E_REAL * 256];      // [e][c*64+j]
__device__ __align__(16) float g_R1proj[N_REL * 256];              // [r*256 + c*64 + j]
__device__ __align__(16) float g_R2proj[N_REL * OUTF];
__device__ __align__(16) float g_rowsum1T[(size_t)N_NODES * 4];    // [i*4 + c]
__device__ __align__(16) float g_hp1[2][(size_t)N_NODES * 128];
__device__ __align__(16) float g_xs[2][(size_t)N_NODES * OUTF];
__device__ __align__(16) float g_P2all[2][(size_t)N_NODES * 256];
__device__ float g_rowsum2[2][N_NODES];
__device__ __align__(16) float g_hp2[2][(size_t)N_NODES * OUTF];
__device__ __align__(16) float g_y[2][(size_t)N_NODES * OUTF];
__device__ float g_wsum[2];
// packed weights (row-major [n][K])
__device__ __align__(16) float g_Wp1[512 * 64];
__device__ __align__(16) float g_WpQ[256 * 64];
__device__ __align__(16) float g_Wp2[256 * 128];
__device__ __align__(16) float g_WeP[64 * 128];                    // [j][k]
// factorized attention scalars
__device__ __align__(16) float g_S1[(size_t)N_NODES * 8];
__device__ __align__(16) float g_SQ1[(size_t)E_REAL * 4];
__device__ __align__(16) float g_Sr1[N_REL * 4];
__device__ __align__(16) float g_S2[2][(size_t)N_NODES * 4];
__device__ float g_Srel2[N_REL];
// per-column dot weights
__device__ __align__(16) float g_a2cat1[512];
__device__ __align__(16) float g_a2catQ[256];
__device__ __align__(16) float g_a2cat2[256];

#define RED4(ptr, a, b, c, d) \
    asm volatile("red.global.add.v4.f32 [%0], {%1, %2, %3, %4};" :: "l"(ptr), "f"(a), "f"(b), "f"(c), "f"(d) : "memory")

// ---------------- fused setup ----------------
__global__ void setup(const float* __restrict__ a_in, const float* __restrict__ a_out,
                      const float* __restrict__ a_o,
                      const float* __restrict__ a2_in, const float* __restrict__ a2_out,
                      const float* __restrict__ a2_o,
                      const float* __restrict__ rel, const float* __restrict__ W,
                      const float* __restrict__ We, float* __restrict__ out_tail) {
    int b = blockIdx.x, t = threadIdx.x;
    if (b < 512) {
        size_t tid = (size_t)b * 256 + t, stride = (size_t)512 * 256;
        float4 z = make_float4(0.f, 0.f, 0.f, 0.f);
        float4* hp1 = (float4*)&g_hp1[0][0];
        for (size_t i = tid; i < (size_t)2 * N_NODES * 32; i += stride) hp1[i] = z;
        float4* hp2 = (float4*)&g_hp2[0][0];
        for (size_t i = tid; i < (size_t)2 * N_NODES * 32; i += stride) hp2[i] = z;
        float4* rs1 = (float4*)&g_rowsum1T[0];
        for (size_t i = tid; i < (size_t)N_NODES; i += stride) rs1[i] = z;
        float4* rs2 = (float4*)&g_rowsum2[0][0];
        for (size_t i = tid; i < (size_t)N_NODES / 2; i += stride) rs2[i] = z;
        if (tid < 2) g_wsum[tid] = 0.f;
    } else if (b < 516) {
        for (int idx = (b - 512) * 256 + t; idx < 512 * 64; idx += 4 * 256) {
            int n = idx >> 6, k = idx & 63;
            int dir = n >> 8, role = (n >> 7) & 1, h = (n >> 6) & 1, j = n & 63;
            const float* A = (dir ? a_out : a_in) + (size_t)h * 64 * 192;
            g_Wp1[idx] = A[j * 192 + role * 64 + k];
        }
    } else if (b < 518) {
        for (int idx = (b - 516) * 256 + t; idx < 256 * 64; idx += 2 * 256) {
            int n = idx >> 6, k = idx & 63;
            int c = n >> 6, j = n & 63;
            const float* A = ((c >> 1) ? a_out : a_in) + (size_t)(c & 1) * 64 * 192;
            g_WpQ[idx] = A[j * 192 + 128 + k];
        }
    } else if (b < 522) {
        for (int idx = (b - 518) * 256 + t; idx < 256 * 128; idx += 4 * 256) {
            int n = idx >> 7, k = idx & 127;
            int role = n >> 7, j = n & 127;
            g_Wp2[idx] = a_o[j * 384 + role * 128 + k];
        }
    } else if (b < 524) {
        for (int idx = (b - 522) * 256 + t; idx < 64 * 128; idx += 2 * 256) {
            int j = idx >> 7, k = idx & 127;
            g_WeP[idx] = We[k * 64 + j];
        }
    } else if (b == 524) {
        for (int n = t; n < 512; n += 256) {
            int dir = n >> 8, h = (n >> 6) & 1, j = n & 63;
            g_a2cat1[n] = (dir ? a2_out : a2_in)[h * 64 + j];
        }
        for (int n = t; n < 256; n += 256) {
            int c = n >> 6, j = n & 63;
            g_a2catQ[n] = ((c >> 1) ? a2_out : a2_in)[(c & 1) * 64 + j];
        }
        if (t < 256) g_a2cat2[t] = a2_o[t & 127];
    } else {
        int r = b - 525;  // [0, 200)
        __shared__ float relrow[64];
        __shared__ float rel2row[128];
        __shared__ float red[8];
        if (t < 64) relrow[t] = rel[r * 64 + t];
        __syncthreads();
        if (t < 128) {
            float acc = 0.f;
            #pragma unroll
            for (int k = 0; k < 64; k++) acc += relrow[k] * W[k * 128 + t];
            rel2row[t] = acc;
            out_tail[(size_t)N_NODES * OUTF + r * 128 + t] = acc;
        }
        __syncthreads();
        {
            int c = t >> 6, j = t & 63;
            const float* A = ((c >> 1) ? a_out : a_in) + (size_t)(c & 1) * 64 * 192;
            float acc = 0.f;
            #pragma unroll
            for (int k = 0; k < 64; k++) acc += relrow[k] * A[j * 192 + 128 + k];
            g_R1proj[r * 256 + t] = acc;
            float part = acc * ((c >> 1) ? a2_out : a2_in)[(c & 1) * 64 + j];
            #pragma unroll
            for (int o = 16; o; o >>= 1) part += __shfl_xor_sync(0xffffffffu, part, o);
            if ((t & 31) == 0) red[t >> 5] = part;
        }
        __syncthreads();
        if (t < 4) g_Sr1[r * 4 + t] = red[2 * t] + red[2 * t + 1];
        __syncthreads();
        {
            float part = 0.f;
            if (t < 128) {
                float acc = 0.f;
                #pragma unroll 16
                for (int k = 0; k < 128; k++) acc += rel2row[k] * a_o[t * 384 + 256 + k];
                g_R2proj[r * 128 + t] = acc;
                part = acc * a2_o[t];
            }
            #pragma unroll
            for (int o = 16; o; o >>= 1) part += __shfl_xor_sync(0xffffffffu, part, o);
            if ((t & 31) == 0 && t < 128) red[t >> 5] = part;
        }
        __syncthreads();
        if (t == 0) g_Srel2[r] = red[0] + red[1] + red[2] + red[3];
    }
}

// ---------------- f32x2 GEMM: R9 adjacent-pair inner loop + register prefetch ----------------
#define KC 16
__global__ void __launch_bounds__(256, 2)
gemm_f32x2(const float* __restrict__ X,
           const float* __restrict__ Wp,
           float* __restrict__ C,
           const float* __restrict__ a2cat,
           float* __restrict__ sOut,
           int M, int N, int K) {
    __shared__ __align__(16) float2 Xs2[KC][130];  // {x,x} pre-dup
    __shared__ __align__(16) float  As[KC][132];   // transposed, adjacent-pair columns
    int t = threadIdx.x;
    int tx = t & 15, ty = t >> 4;
    int ib = blockIdx.x * 128;
    int jb = blockIdx.y * 128;
    ull acc[8][4];
    #pragma unroll
    for (int ii = 0; ii < 8; ii++)
        #pragma unroll
        for (int q = 0; q < 4; q++) acc[ii][q] = 0ull;

    // prefetch registers: 2 positions per thread (512 float4s / 256 threads)
    float4 xb[2], ab[2];
    int pi0 = t & 127, pk0 = (t >> 7) * 4;           // u = 0
    int pk1 = pk0 + 8;                               // u = 1 (p = t + 256)
    {
        int gi = ib + pi0;
        xb[0] = make_float4(0.f, 0.f, 0.f, 0.f);
        xb[1] = make_float4(0.f, 0.f, 0.f, 0.f);
        if (gi < M) {
            xb[0] = *(const float4*)&X[(size_t)gi * K + pk0];
            xb[1] = *(const float4*)&X[(size_t)gi * K + pk1];
        }
        ab[0] = *(const float4*)&Wp[(size_t)(jb + pi0) * K + pk0];
        ab[1] = *(const float4*)&Wp[(size_t)(jb + pi0) * K + pk1];
    }

    for (int kc = 0; kc < K; kc += KC) {
        // store prefetched chunk
        #pragma unroll
        for (int u = 0; u < 2; u++) {
            int kq = u ? pk1 : pk0;
            float4 v = xb[u];
            Xs2[kq + 0][pi0] = make_float2(v.x, v.x);
            Xs2[kq + 1][pi0] = make_float2(v.y, v.y);
            Xs2[kq + 2][pi0] = make_float2(v.z, v.z);
            Xs2[kq + 3][pi0] = make_float2(v.w, v.w);
            float4 a = ab[u];
            As[kq + 0][pi0] = a.x; As[kq + 1][pi0] = a.y;
            As[kq + 2][pi0] = a.z; As[kq + 3][pi0] = a.w;
        }
        __syncthreads();
        // prefetch next chunk (overlaps compute)
        if (kc + KC < K) {
            int gi = ib + pi0;
            xb[0] = make_float4(0.f, 0.f, 0.f, 0.f);
            xb[1] = make_float4(0.f, 0.f, 0.f, 0.f);
            if (gi < M) {
                xb[0] = *(const float4*)&X[(size_t)gi * K + kc + KC + pk0];
                xb[1] = *(const float4*)&X[(size_t)gi * K + kc + KC + pk1];
            }
            ab[0] = *(const float4*)&Wp[(size_t)(jb + pi0) * K + kc + KC + pk0];
            ab[1] = *(const float4*)&Wp[(size_t)(jb + pi0) * K + kc + KC + pk1];
        }
        // compute (pack-free adjacent-pair loop)
        #pragma unroll
        for (int kk = 0; kk < KC; kk++) {
            ull av[4];
            #pragma unroll
            for (int q = 0; q < 4; q++)
                av[q] = *(const ull*)&As[kk][2 * (tx + 16 * q)];
            #pragma unroll
            for (int ii = 0; ii < 8; ii++) {
                ull xx = *(const ull*)&Xs2[kk][ty * 8 + ii];
                #pragma unroll
                for (int q = 0; q < 4; q++)
                    asm("fma.rn.f32x2 %0, %1, %2, %0;"
                        : "+l"(acc[ii][q]) : "l"(xx), "l"(av[q]));
            }
        }
        __syncthreads();
    }
    int nBlk = N >> 6;
    float2 w[4];
    #pragma unroll
    for (int q = 0; q < 4; q++)
        w[q] = *(const float2*)&a2cat[jb + 2 * (tx + 16 * q)];
    #pragma unroll
    for (int ii = 0; ii < 8; ii++) {
        int gi = ib + ty * 8 + ii;
        float lo[4], hi[4];
        #pragma unroll
        for (int q = 0; q < 4; q++)
            asm("mov.b64 {%0, %1}, %2;" : "=f"(lo[q]), "=f"(hi[q]) : "l"(acc[ii][q]));
        if (gi < M) {
            #pragma unroll
            for (int q = 0; q < 4; q++)
                *(float2*)&C[(size_t)gi * N + jb + 2 * (tx + 16 * q)] = make_float2(lo[q], hi[q]);
        }
        float s0 = lo[0] * w[0].x + hi[0] * w[0].y + lo[1] * w[1].x + hi[1] * w[1].y;
        float s1 = lo[2] * w[2].x + hi[2] * w[2].y + lo[3] * w[3].x + hi[3] * w[3].y;
        #pragma unroll
        for (int o = 8; o; o >>= 1) {
            s0 += __shfl_xor_sync(0xffffffffu, s0, o);
            s1 += __shfl_xor_sync(0xffffffffu, s1, o);
        }
        if (tx == 0 && gi < M) {
            size_t base = (size_t)gi * nBlk + (jb >> 6);
            sOut[base] = s0;
            sOut[base + 1] = s1;
        }
    }
}

// ---------------- gemm_we: norm2 fused into loader + tanh-dot epilogue ----------------
__global__ void __launch_bounds__(256, 2)
gemm_we(const float* __restrict__ be, const float* __restrict__ qe) {
    __shared__ __align__(16) float2 Xs2[KC][130];
    __shared__ __align__(16) float  As[KC][68];
    __shared__ float s_sh[2];
    int t = threadIdx.x;
    int tx = t & 7, ty = t >> 3;
    int lane = t & 31;
    int ib = blockIdx.x * 128;
    const int M = 2 * N_NODES;
    if (t < 2) s_sh[t] = 0.f;
    const float* hp2f = &g_hp2[0][0];
    const float* rs2f = &g_rowsum2[0][0];
    float* yf = &g_y[0][0];
    ull acc[4][4];
    #pragma unroll
    for (int ii = 0; ii < 4; ii++)
        #pragma unroll
        for (int q = 0; q < 4; q++) acc[ii][q] = 0ull;

    for (int kc = 0; kc < 128; kc += KC) {
        // fused norm2: compute y tile elements, write to gmem, stash to smem
        #pragma unroll
        for (int p = t; p < 512; p += 256) {
            int i = p & 127, kq = (p >> 7) * 4;
            int gi = ib + i;
            float4 v = make_float4(0.f, 0.f, 0.f, 0.f);
            if (gi < M) {
                int xs = gi >= N_NODES;
                int ii2 = xs ? gi - N_NODES : gi;
                float rs = rs2f[gi];
                if (rs > 0.f) {
                    float inv = 1.f / rs;
                    float4 hv = *(const float4*)&hp2f[(size_t)gi * 128 + kc + kq];
                    float4 pv = *(const float4*)&g_P2all[xs][(size_t)ii2 * 256 + kc + kq];
                    v.x = hv.x * inv + pv.x;
                    v.y = hv.y * inv + pv.y;
                    v.z = hv.z * inv + pv.z;
                    v.w = hv.w * inv + pv.w;
                }
                v.x = (v.x > 0.f) ? v.x : expm1f(v.x);
                v.y = (v.y > 0.f) ? v.y : expm1f(v.y);
                v.z = (v.z > 0.f) ? v.z : expm1f(v.z);
                v.w = (v.w > 0.f) ? v.w : expm1f(v.w);
                *(float4*)&yf[(size_t)gi * 128 + kc + kq] = v;
            }
            Xs2[kq + 0][i] = make_float2(v.x, v.x);
            Xs2[kq + 1][i] = make_float2(v.y, v.y);
            Xs2[kq + 2][i] = make_float2(v.z, v.z);
            Xs2[kq + 3][i] = make_float2(v.w, v.w);
        }
        {
            int j = t & 63, kq = ((t >> 6) & 3) * 4;
            float4 w = *(const float4*)&g_WeP[j * 128 + kc + kq];
            As[kq + 0][j] = w.x; As[kq + 1][j] = w.y;
            As[kq + 2][j] = w.z; As[kq + 3][j] = w.w;
        }
        __syncthreads();
        #pragma unroll
        for (int kk = 0; kk < KC; kk++) {
            ull av[4];
            #pragma unroll
            for (int q = 0; q < 4; q++)
                av[q] = *(const ull*)&As[kk][2 * (tx + 8 * q)];
            #pragma unroll
            for (int ii = 0; ii < 4; ii++) {
                ull xx = *(const ull*)&Xs2[kk][ty * 4 + ii];
                #pragma unroll
                for (int q = 0; q < 4; q++)
                    asm("fma.rn.f32x2 %0, %1, %2, %0;"
                        : "+l"(acc[ii][q]) : "l"(xx), "l"(av[q]));
            }
        }
        __syncthreads();
    }
    float2 bb[4], qq[4];
    #pragma unroll
    for (int q = 0; q < 4; q++) {
        bb[q] = *(const float2*)&be[2 * (tx + 8 * q)];
        qq[q] = *(const float2*)&qe[2 * (tx + 8 * q)];
    }
    #pragma unroll
    for (int ii = 0; ii < 4; ii++) {
        int gi = ib + ty * 4 + ii;
        float lo[4], hi[4];
        #pragma unroll
        for (int q = 0; q < 4; q++)
            asm("mov.b64 {%0, %1}, %2;" : "=f"(lo[q]), "=f"(hi[q]) : "l"(acc[ii][q]));
        float s = 0.f;
        #pragma unroll
        for (int q = 0; q < 4; q++)
            s += tanhf(lo[q] + bb[q].x) * qq[q].x + tanhf(hi[q] + bb[q].y) * qq[q].y;
        #pragma unroll
        for (int o = 4; o; o >>= 1) s += __shfl_xor_sync(0xffffffffu, s, o);
        if ((lane & 7) == 0 && gi < M)
            atomicAdd(&s_sh[gi >= N_NODES], s);
    }
    __syncthreads();
    if (t < 2) atomicAdd(&g_wsum[t], s_sh[t]);
}

// ---------------- layer-1 edge pass ----------------
__global__ void edge_pass1(const int* __restrict__ el, const int* __restrict__ eln,
                           const int* __restrict__ etn) {
    int dir = blockIdx.y;
    int e = blockIdx.x * 8 + (threadIdx.x >> 5);
    int lane = threadIdx.x & 31;
    int h = lane >> 4;
    int jj = 4 * (lane & 15);
    int i0, i1;
    float4 q;
    float sq;
    if (e < E_REAL) {
        i0 = el[e]; i1 = el[E_REAL + e];
        q = *(const float4*)&g_Q1all[(size_t)e * 256 + dir * 128 + h * 64 + jj];
        sq = g_SQ1[(size_t)e * 4 + dir * 2 + h];
    } else {
        int en = e - E_REAL;
        i0 = eln[en]; i1 = eln[E_NHOP + en];
        int t0 = etn[2 * en], t1 = etn[2 * en + 1];
        float4 qa = *(const float4*)&g_R1proj[t0 * 256 + dir * 128 + h * 64 + jj];
        float4 qb = *(const float4*)&g_R1proj[t1 * 256 + dir * 128 + h * 64 + jj];
        q.x = qa.x + qb.x; q.y = qa.y + qb.y; q.z = qa.z + qb.z; q.w = qa.w + qb.w;
        sq = g_Sr1[t0 * 4 + dir * 2 + h] + g_Sr1[t1 * 4 + dir * 2 + h];
    }
    int src = dir ? i1 : i0;
    int dst = dir ? i0 : i1;
    float score = g_S1[(size_t)src * 8 + dir * 4 + h]
                + g_S1[(size_t)dst * 8 + dir * 4 + 2 + h] + sq;
    float lk = score > 0.f ? score : ALPHA * score;
    float ev = __expf(-lk);
    float4 d = *(const float4*)&g_P1all[(size_t)dst * 512 + dir * 256 + 128 + h * 64 + jj];
    float* hp = &g_hp1[dir][(size_t)src * 128 + h * 64 + jj];
    RED4(hp, ev * (d.x + q.x), ev * (d.y + q.y), ev * (d.z + q.z), ev * (d.w + q.w));
    if ((lane & 15) == 0) atomicAdd(&g_rowsum1T[(size_t)src * 4 + dir * 2 + h], ev);
}

// ---------------- normalize (+ fold p_src) + elu -> x_s ----------------
__global__ void norm1() {
    int dir = blockIdx.y;
    int idx = blockIdx.x * 256 + threadIdx.x;
    if (idx >= N_NODES * 128) return;
    int i = idx >> 7, kk = idx & 127;
    float rs = g_rowsum1T[(size_t)i * 4 + dir * 2 + (kk >> 6)];
    float v = g_hp1[dir][idx];
    v = (rs > 0.f) ? v / rs + g_P1all[(size_t)i * 512 + dir * 256 + kk] : 0.f;
    v = (v > 0.f) ? v : expm1f(v);
    g_xs[dir][idx] = v;
}

// ---------------- layer-2 edge pass ----------------
__global__ void edge_pass2(const int* __restrict__ el, const int* __restrict__ eln,
                           const int* __restrict__ et, const int* __restrict__ etn) {
    int dir = blockIdx.y;
    int e = blockIdx.x * 8 + (threadIdx.x >> 5);
    if (e >= E_ALL) return;
    int lane = threadIdx.x & 31;
    int i0, i1;
    float q0, q1, q2, q3, sq;
    if (e < E_REAL) {
        i0 = el[e]; i1 = el[E_REAL + e];
        int ty = et[e];
        float4 qv = *(const float4*)&g_R2proj[ty * 128 + 4 * lane];
        q0 = qv.x; q1 = qv.y; q2 = qv.z; q3 = qv.w;
        sq = g_Srel2[ty];
    } else {
        int en = e - E_REAL;
        i0 = eln[en]; i1 = eln[E_NHOP + en];
        int t0 = etn[2 * en], t1 = etn[2 * en + 1];
        float4 qa = *(const float4*)&g_R2proj[t0 * 128 + 4 * lane];
        float4 qb = *(const float4*)&g_R2proj[t1 * 128 + 4 * lane];
        q0 = qa.x + qb.x; q1 = qa.y + qb.y; q2 = qa.z + qb.z; q3 = qa.w + qb.w;
        sq = g_Srel2[t0] + g_Srel2[t1];
    }
    int seg = dir ? i1 : i0;
    int nbr = dir ? i0 : i1;
    float4 sA = *(const float4*)&g_S2[dir][(size_t)seg * 4];
    float4 sB = *(const float4*)&g_S2[dir][(size_t)nbr * 4];
    float score = sA.x + sA.y + sB.z + sB.w + sq;
    float lk = score > 0.f ? score : ALPHA * score;
    float ev = __expf(-lk);
    float4 dv = *(const float4*)&g_P2all[dir][(size_t)nbr * 256 + 128 + 4 * lane];
    float* hp = &g_hp2[dir][(size_t)seg * 128 + 4 * lane];
    RED4(hp, ev * (dv.x + q0), ev * (dv.y + q1), ev * (dv.z + q2), ev * (dv.w + q3));
    if (lane == 0) atomicAdd(&g_rowsum2[dir][seg], ev);
}

// ---------------- beta + combine ----------------
__global__ void combine(float* __restrict__ out) {
    float m0 = g_wsum[0] / (float)N_NODES;
    float m1 = g_wsum[1] / (float)N_NODES;
    float mx = fmaxf(m0, m1);
    float e0 = expf(m0 - mx), e1 = expf(m1 - mx);
    float b0 = e0 / (e0 + e1), b1 = e1 / (e0 + e1);
    size_t i = (size_t)blockIdx.x * 256 + threadIdx.x;
    if (i >= (size_t)N_NODES * OUTF) return;
    out[i] = b0 * g_y[0][i] + b1 * g_y[1][i];
}

// ---------------- launch ----------------
extern "C" void kernel_launch(void* const* d_in, const int* in_sizes, int n_in,
                              void* d_out, int out_size) {
    const float* ent   = (const float*)d_in[0];
    const float* rel   = (const float*)d_in[1];
    const int*   el    = (const int*)d_in[2];
    const int*   et    = (const int*)d_in[3];
    const float* eemb  = (const float*)d_in[4];
    const int*   eln   = (const int*)d_in[5];
    const int*   etn   = (const int*)d_in[6];
    const float* a_in  = (const float*)d_in[7];
    const float* a2_in = (const float*)d_in[8];
    const float* a_out = (const float*)d_in[9];
    const float* a2_out= (const float*)d_in[10];
    const float* a_o   = (const float*)d_in[11];
    const float* a2_o  = (const float*)d_in[12];
    const float* W     = (const float*)d_in[13];
    const float* We    = (const float*)d_in[14];
    const float* be    = (const float*)d_in[15];
    const float* qe    = (const float*)d_in[16];
    float* out = (float*)d_out;

    float *p1 = 0, *q1 = 0, *xsb = 0, *p2 = 0, *wp1 = 0, *wpq = 0, *wp2 = 0;
    float *a2c1 = 0, *a2cq = 0, *a2c2 = 0, *s1 = 0, *sq1 = 0, *s2 = 0;
    cudaGetSymbolAddress((void**)&p1, g_P1all);
    cudaGetSymbolAddress((void**)&q1, g_Q1all);
    cudaGetSymbolAddress((void**)&xsb, g_xs);
    cudaGetSymbolAddress((void**)&p2, g_P2all);
    cudaGetSymbolAddress((void**)&wp1, g_Wp1);
    cudaGetSymbolAddress((void**)&wpq, g_WpQ);
    cudaGetSymbolAddress((void**)&wp2, g_Wp2);
    cudaGetSymbolAddress((void**)&a2c1, g_a2cat1);
    cudaGetSymbolAddress((void**)&a2cq, g_a2catQ);
    cudaGetSymbolAddress((void**)&a2c2, g_a2cat2);
    cudaGetSymbolAddress((void**)&s1, g_S1);
    cudaGetSymbolAddress((void**)&sq1, g_SQ1);
    cudaGetSymbolAddress((void**)&s2, g_S2);

    setup<<<725, 256>>>(a_in, a_out, a_o, a2_in, a2_out, a2_o, rel, W, We, out);

    gemm_f32x2<<<dim3((N_NODES + 127) / 128, 4), 256>>>(ent, wp1, p1, a2c1, s1,
                                                        N_NODES, 512, 64);
    gemm_f32x2<<<dim3((E_REAL + 127) / 128, 2), 256>>>(eemb, wpq, q1, a2cq, sq1,
                                                       E_REAL, 256, 64);

    edge_pass1<<<dim3(E_ALL / 8, 2), 256>>>(el, eln, etn);
    norm1<<<dim3((N_NODES * 128 + 255) / 256, 2), 256>>>();

    for (int xs = 0; xs < 2; xs++)
        gemm_f32x2<<<dim3((N_NODES + 127) / 128, 2), 256>>>(
            xsb + (size_t)xs * N_NODES * 128, wp2,
            p2 + (size_t)xs * N_NODES * 256,
            a2c2, s2 + (size_t)xs * N_NODES * 4,
            N_NODES, 256, 128);

    edge_pass2<<<dim3(E_ALL / 8, 2), 256>>>(el, eln, et, etn);

    gemm_we<<<(2 * N_NODES + 127) / 128, 256>>>(be, qe);
    combine<<<(N_NODES * OUTF + 255) / 256, 256>>>(out);
}

// round 12
// speedup vs baseline: 1.1497x; 1.0172x over previous
#include <cuda_runtime.h>
#include <math.h>

#define N_NODES 50000
#define NFEAT   64
#define NHID    64
#define E_REAL  200000
#define E_NHOP  40000
#define E_ALL   240000
#define N_REL   200
#define OUTF    128
#define ALPHA   0.2f

typedef unsigned long long ull;

// ---------------- device scratch ----------------
__device__ __align__(16) float g_P1all[(size_t)N_NODES * 512];     // [i][dir*256+role*128+h*64+j]
__device__ __align__(16) float g_R1proj[N_REL * 256];              // [r*256 + c*64 + j]
__device__ __align__(16) float g_R2proj[N_REL * OUTF];
__device__ __align__(16) float g_rowsum1T[(size_t)N_NODES * 4];    // [i*4 + dir*2 + h]
__device__ __align__(16) float g_hp1[2][(size_t)N_NODES * 128];
__device__ __align__(16) float g_xs[2][(size_t)N_NODES * OUTF];
__device__ __align__(16) float g_P2all[2][(size_t)N_NODES * 256];
__device__ float g_rowsum2[2][N_NODES];
__device__ __align__(16) float g_hp2[2][(size_t)N_NODES * OUTF];
__device__ __align__(16) float g_y[2][(size_t)N_NODES * OUTF];
__device__ float g_wsum[2];
// packed weights (row-major [n][K])
__device__ __align__(16) float g_Wp1[512 * 64];
__device__ __align__(16) float g_WpQ[256 * 64];
__device__ __align__(16) float g_Wp2[256 * 128];
__device__ __align__(16) float g_WeP[64 * 128];                    // [j][k]
// factorized attention scalars
__device__ __align__(16) float g_S1[(size_t)N_NODES * 8];          // [i*8 + dir*4 + role*2 + h]
__device__ __align__(16) float g_Sr1[N_REL * 4];
__device__ __align__(16) float g_S2[2][(size_t)N_NODES * 4];
__device__ float g_Srel2[N_REL];
// per-column dot weights
__device__ __align__(16) float g_a2cat1[512];
__device__ __align__(16) float g_a2catQ[256];
__device__ __align__(16) float g_a2cat2[256];

#define RED2(ptr, a, b) \
    asm volatile("red.global.add.v2.f32 [%0], {%1, %2};" :: "l"(ptr), "f"(a), "f"(b) : "memory")
#define RED4(ptr, a, b, c, d) \
    asm volatile("red.global.add.v4.f32 [%0], {%1, %2, %3, %4};" :: "l"(ptr), "f"(a), "f"(b), "f"(c), "f"(d) : "memory")

// ---------------- fused setup ----------------
__global__ void setup(const float* __restrict__ a_in, const float* __restrict__ a_out,
                      const float* __restrict__ a_o,
                      const float* __restrict__ a2_in, const float* __restrict__ a2_out,
                      const float* __restrict__ a2_o,
                      const float* __restrict__ rel, const float* __restrict__ W,
                      const float* __restrict__ We, float* __restrict__ out_tail) {
    int b = blockIdx.x, t = threadIdx.x;
    if (b < 512) {
        size_t tid = (size_t)b * 256 + t, stride = (size_t)512 * 256;
        float4 z = make_float4(0.f, 0.f, 0.f, 0.f);
        float4* hp1 = (float4*)&g_hp1[0][0];
        for (size_t i = tid; i < (size_t)2 * N_NODES * 32; i += stride) hp1[i] = z;
        float4* hp2 = (float4*)&g_hp2[0][0];
        for (size_t i = tid; i < (size_t)2 * N_NODES * 32; i += stride) hp2[i] = z;
        float4* rs1 = (float4*)&g_rowsum1T[0];
        for (size_t i = tid; i < (size_t)N_NODES; i += stride) rs1[i] = z;
        float4* rs2 = (float4*)&g_rowsum2[0][0];
        for (size_t i = tid; i < (size_t)N_NODES / 2; i += stride) rs2[i] = z;
        if (tid < 2) g_wsum[tid] = 0.f;
    } else if (b < 516) {
        for (int idx = (b - 512) * 256 + t; idx < 512 * 64; idx += 4 * 256) {
            int n = idx >> 6, k = idx & 63;
            int dir = n >> 8, role = (n >> 7) & 1, h = (n >> 6) & 1, j = n & 63;
            const float* A = (dir ? a_out : a_in) + (size_t)h * 64 * 192;
            g_Wp1[idx] = A[j * 192 + role * 64 + k];
        }
    } else if (b < 518) {
        for (int idx = (b - 516) * 256 + t; idx < 256 * 64; idx += 2 * 256) {
            int n = idx >> 6, k = idx & 63;
            int c = n >> 6, j = n & 63;
            const float* A = ((c >> 1) ? a_out : a_in) + (size_t)(c & 1) * 64 * 192;
            g_WpQ[idx] = A[j * 192 + 128 + k];
        }
    } else if (b < 522) {
        for (int idx = (b - 518) * 256 + t; idx < 256 * 128; idx += 4 * 256) {
            int n = idx >> 7, k = idx & 127;
            int role = n >> 7, j = n & 127;
            g_Wp2[idx] = a_o[j * 384 + role * 128 + k];
        }
    } else if (b < 524) {
        for (int idx = (b - 522) * 256 + t; idx < 64 * 128; idx += 2 * 256) {
            int j = idx >> 7, k = idx & 127;
            g_WeP[idx] = We[k * 64 + j];
        }
    } else if (b == 524) {
        for (int n = t; n < 512; n += 256) {
            int dir = n >> 8, h = (n >> 6) & 1, j = n & 63;
            g_a2cat1[n] = (dir ? a2_out : a2_in)[h * 64 + j];
        }
        for (int n = t; n < 256; n += 256) {
            int c = n >> 6, j = n & 63;
            g_a2catQ[n] = ((c >> 1) ? a2_out : a2_in)[(c & 1) * 64 + j];
        }
        if (t < 256) g_a2cat2[t] = a2_o[t & 127];
    } else {
        int r = b - 525;  // [0, 200)
        __shared__ float relrow[64];
        __shared__ float rel2row[128];
        __shared__ float red[8];
        if (t < 64) relrow[t] = rel[r * 64 + t];
        __syncthreads();
        if (t < 128) {
            float acc = 0.f;
            #pragma unroll
            for (int k = 0; k < 64; k++) acc += relrow[k] * W[k * 128 + t];
            rel2row[t] = acc;
            out_tail[(size_t)N_NODES * OUTF + r * 128 + t] = acc;
        }
        __syncthreads();
        {
            int c = t >> 6, j = t & 63;
            const float* A = ((c >> 1) ? a_out : a_in) + (size_t)(c & 1) * 64 * 192;
            float acc = 0.f;
            #pragma unroll
            for (int k = 0; k < 64; k++) acc += relrow[k] * A[j * 192 + 128 + k];
            g_R1proj[r * 256 + t] = acc;
            float part = acc * ((c >> 1) ? a2_out : a2_in)[(c & 1) * 64 + j];
            #pragma unroll
            for (int o = 16; o; o >>= 1) part += __shfl_xor_sync(0xffffffffu, part, o);
            if ((t & 31) == 0) red[t >> 5] = part;
        }
        __syncthreads();
        if (t < 4) g_Sr1[r * 4 + t] = red[2 * t] + red[2 * t + 1];
        __syncthreads();
        {
            float part = 0.f;
            if (t < 128) {
                float acc = 0.f;
                #pragma unroll 16
                for (int k = 0; k < 128; k++) acc += rel2row[k] * a_o[t * 384 + 256 + k];
                g_R2proj[r * 128 + t] = acc;
                part = acc * a2_o[t];
            }
            #pragma unroll
            for (int o = 16; o; o >>= 1) part += __shfl_xor_sync(0xffffffffu, part, o);
            if ((t & 31) == 0 && t < 128) red[t >> 5] = part;
        }
        __syncthreads();
        if (t == 0) g_Srel2[r] = red[0] + red[1] + red[2] + red[3];
    }
}

// ---------------- f32x2 GEMM (projection variant) ----------------
#define KC 16
__global__ void __launch_bounds__(256, 2)
gemm_f32x2(const float* __restrict__ X,
           const float* __restrict__ Wp,
           float* __restrict__ C,
           const float* __restrict__ a2cat,
           float* __restrict__ sOut,
           int M, int N, int K) {
    __shared__ __align__(16) float2 Xs2[KC][130];
    __shared__ __align__(16) float  As[KC][132];
    int t = threadIdx.x;
    int tx = t & 15, ty = t >> 4;
    int ib = blockIdx.x * 128;
    int jb = blockIdx.y * 128;
    ull acc[8][4];
    #pragma unroll
    for (int ii = 0; ii < 8; ii++)
        #pragma unroll
        for (int q = 0; q < 4; q++) acc[ii][q] = 0ull;

    float4 xb[2], ab[2];
    int pi0 = t & 127, pk0 = (t >> 7) * 4;
    int pk1 = pk0 + 8;
    {
        int gi = ib + pi0;
        xb[0] = make_float4(0.f, 0.f, 0.f, 0.f);
        xb[1] = make_float4(0.f, 0.f, 0.f, 0.f);
        if (gi < M) {
            xb[0] = *(const float4*)&X[(size_t)gi * K + pk0];
            xb[1] = *(const float4*)&X[(size_t)gi * K + pk1];
        }
        ab[0] = *(const float4*)&Wp[(size_t)(jb + pi0) * K + pk0];
        ab[1] = *(const float4*)&Wp[(size_t)(jb + pi0) * K + pk1];
    }

    for (int kc = 0; kc < K; kc += KC) {
        #pragma unroll
        for (int u = 0; u < 2; u++) {
            int kq = u ? pk1 : pk0;
            float4 v = xb[u];
            Xs2[kq + 0][pi0] = make_float2(v.x, v.x);
            Xs2[kq + 1][pi0] = make_float2(v.y, v.y);
            Xs2[kq + 2][pi0] = make_float2(v.z, v.z);
            Xs2[kq + 3][pi0] = make_float2(v.w, v.w);
            float4 a = ab[u];
            As[kq + 0][pi0] = a.x; As[kq + 1][pi0] = a.y;
            As[kq + 2][pi0] = a.z; As[kq + 3][pi0] = a.w;
        }
        __syncthreads();
        if (kc + KC < K) {
            int gi = ib + pi0;
            xb[0] = make_float4(0.f, 0.f, 0.f, 0.f);
            xb[1] = make_float4(0.f, 0.f, 0.f, 0.f);
            if (gi < M) {
                xb[0] = *(const float4*)&X[(size_t)gi * K + kc + KC + pk0];
                xb[1] = *(const float4*)&X[(size_t)gi * K + kc + KC + pk1];
            }
            ab[0] = *(const float4*)&Wp[(size_t)(jb + pi0) * K + kc + KC + pk0];
            ab[1] = *(const float4*)&Wp[(size_t)(jb + pi0) * K + kc + KC + pk1];
        }
        #pragma unroll
        for (int kk = 0; kk < KC; kk++) {
            ull av[4];
            #pragma unroll
            for (int q = 0; q < 4; q++)
                av[q] = *(const ull*)&As[kk][2 * (tx + 16 * q)];
            #pragma unroll
            for (int ii = 0; ii < 8; ii++) {
                ull xx = *(const ull*)&Xs2[kk][ty * 8 + ii];
                #pragma unroll
                for (int q = 0; q < 4; q++)
                    asm("fma.rn.f32x2 %0, %1, %2, %0;"
                        : "+l"(acc[ii][q]) : "l"(xx), "l"(av[q]));
            }
        }
        __syncthreads();
    }
    int nBlk = N >> 6;
    float2 w[4];
    #pragma unroll
    for (int q = 0; q < 4; q++)
        w[q] = *(const float2*)&a2cat[jb + 2 * (tx + 16 * q)];
    #pragma unroll
    for (int ii = 0; ii < 8; ii++) {
        int gi = ib + ty * 8 + ii;
        float lo[4], hi[4];
        #pragma unroll
        for (int q = 0; q < 4; q++)
            asm("mov.b64 {%0, %1}, %2;" : "=f"(lo[q]), "=f"(hi[q]) : "l"(acc[ii][q]));
        if (gi < M) {
            #pragma unroll
            for (int q = 0; q < 4; q++)
                *(float2*)&C[(size_t)gi * N + jb + 2 * (tx + 16 * q)] = make_float2(lo[q], hi[q]);
        }
        float s0 = lo[0] * w[0].x + hi[0] * w[0].y + lo[1] * w[1].x + hi[1] * w[1].y;
        float s1 = lo[2] * w[2].x + hi[2] * w[2].y + lo[3] * w[3].x + hi[3] * w[3].y;
        #pragma unroll
        for (int o = 8; o; o >>= 1) {
            s0 += __shfl_xor_sync(0xffffffffu, s0, o);
            s1 += __shfl_xor_sync(0xffffffffu, s1, o);
        }
        if (tx == 0 && gi < M) {
            size_t base = (size_t)gi * nBlk + (jb >> 6);
            sOut[base] = s0;
            sOut[base + 1] = s1;
        }
    }
}

// ---------------- gemm_q: Q projection with FUSED layer-1 real-edge pass ----------------
// No Q buffer: epilogue computes scores and scatters directly to hp1/rowsum.
// blockIdx.y = dir; N = 256, jb = dir*128; X = edge_embed; Wp = WpQ.
__global__ void __launch_bounds__(256, 2)
gemm_q(const float* __restrict__ X, const int* __restrict__ el) {
    __shared__ __align__(16) float2 Xs2[KC][130];
    __shared__ __align__(16) float  As[KC][132];
    int t = threadIdx.x;
    int tx = t & 15, ty = t >> 4;
    int dir = blockIdx.y;
    int ib = blockIdx.x * 128;
    int jb = dir * 128;
    const int M = E_REAL, K = 64;
    ull acc[8][4];
    #pragma unroll
    for (int ii = 0; ii < 8; ii++)
        #pragma unroll
        for (int q = 0; q < 4; q++) acc[ii][q] = 0ull;

    float4 xb[2], ab[2];
    int pi0 = t & 127, pk0 = (t >> 7) * 4;
    int pk1 = pk0 + 8;
    {
        int gi = ib + pi0;
        xb[0] = make_float4(0.f, 0.f, 0.f, 0.f);
        xb[1] = make_float4(0.f, 0.f, 0.f, 0.f);
        if (gi < M) {
            xb[0] = *(const float4*)&X[(size_t)gi * K + pk0];
            xb[1] = *(const float4*)&X[(size_t)gi * K + pk1];
        }
        ab[0] = *(const float4*)&g_WpQ[(size_t)(jb + pi0) * K + pk0];
        ab[1] = *(const float4*)&g_WpQ[(size_t)(jb + pi0) * K + pk1];
    }

    for (int kc = 0; kc < K; kc += KC) {
        #pragma unroll
        for (int u = 0; u < 2; u++) {
            int kq = u ? pk1 : pk0;
            float4 v = xb[u];
            Xs2[kq + 0][pi0] = make_float2(v.x, v.x);
            Xs2[kq + 1][pi0] = make_float2(v.y, v.y);
            Xs2[kq + 2][pi0] = make_float2(v.z, v.z);
            Xs2[kq + 3][pi0] = make_float2(v.w, v.w);
            float4 a = ab[u];
            As[kq + 0][pi0] = a.x; As[kq + 1][pi0] = a.y;
            As[kq + 2][pi0] = a.z; As[kq + 3][pi0] = a.w;
        }
        __syncthreads();
        if (kc + KC < K) {
            int gi = ib + pi0;
            xb[0] = make_float4(0.f, 0.f, 0.f, 0.f);
            xb[1] = make_float4(0.f, 0.f, 0.f, 0.f);
            if (gi < M) {
                xb[0] = *(const float4*)&X[(size_t)gi * K + kc + KC + pk0];
                xb[1] = *(const float4*)&X[(size_t)gi * K + kc + KC + pk1];
            }
            ab[0] = *(const float4*)&g_WpQ[(size_t)(jb + pi0) * K + kc + KC + pk0];
            ab[1] = *(const float4*)&g_WpQ[(size_t)(jb + pi0) * K + kc + KC + pk1];
        }
        #pragma unroll
        for (int kk = 0; kk < KC; kk++) {
            ull av[4];
            #pragma unroll
            for (int q = 0; q < 4; q++)
                av[q] = *(const ull*)&As[kk][2 * (tx + 16 * q)];
            #pragma unroll
            for (int ii = 0; ii < 8; ii++) {
                ull xx = *(const ull*)&Xs2[kk][ty * 8 + ii];
                #pragma unroll
                for (int q = 0; q < 4; q++)
                    asm("fma.rn.f32x2 %0, %1, %2, %0;"
                        : "+l"(acc[ii][q]) : "l"(xx), "l"(av[q]));
            }
        }
        __syncthreads();
    }
    // epilogue: fused real-edge attention scatter
    float2 w[4];
    #pragma unroll
    for (int q = 0; q < 4; q++)
        w[q] = *(const float2*)&g_a2catQ[jb + 2 * (tx + 16 * q)];
    #pragma unroll
    for (int ii = 0; ii < 8; ii++) {
        int gi = ib + ty * 8 + ii;   // edge index
        float lo[4], hi[4];
        #pragma unroll
        for (int q = 0; q < 4; q++)
            asm("mov.b64 {%0, %1}, %2;" : "=f"(lo[q]), "=f"(hi[q]) : "l"(acc[ii][q]));
        float s0 = lo[0] * w[0].x + hi[0] * w[0].y + lo[1] * w[1].x + hi[1] * w[1].y;
        float s1 = lo[2] * w[2].x + hi[2] * w[2].y + lo[3] * w[3].x + hi[3] * w[3].y;
        #pragma unroll
        for (int o = 8; o; o >>= 1) {
            s0 += __shfl_xor_sync(0xffffffffu, s0, o);
            s1 += __shfl_xor_sync(0xffffffffu, s1, o);
        }
        if (gi < M) {
            int i0 = el[gi], i1 = el[E_REAL + gi];
            int src = dir ? i1 : i0;
            int dst = dir ? i0 : i1;
            float4 sv = *(const float4*)&g_S1[(size_t)src * 8 + dir * 4];
            float4 dv = *(const float4*)&g_S1[(size_t)dst * 8 + dir * 4];
            float sc0 = sv.x + dv.z + s0;   // h=0: src role0 + dst role1
            float sc1 = sv.y + dv.w + s1;   // h=1
            float lk0 = sc0 > 0.f ? sc0 : ALPHA * sc0;
            float lk1 = sc1 > 0.f ? sc1 : ALPHA * sc1;
            float ev0 = __expf(-lk0);
            float ev1 = __expf(-lk1);
            const float* pd = &g_P1all[(size_t)dst * 512 + dir * 256 + 128];
            float* hp = &g_hp1[dir][(size_t)src * 128];
            #pragma unroll
            for (int q = 0; q < 4; q++) {
                int col = 2 * (tx + 16 * q);
                float ev = (q < 2) ? ev0 : ev1;
                float2 d = *(const float2*)&pd[col];
                RED2(&hp[col], ev * (d.x + lo[q]), ev * (d.y + hi[q]));
            }
            if (tx == 0) {
                atomicAdd(&g_rowsum1T[(size_t)src * 4 + dir * 2], ev0);
                atomicAdd(&g_rowsum1T[(size_t)src * 4 + dir * 2 + 1], ev1);
            }
        }
    }
}

// ---------------- gemm_we: norm2 fused into loader + tanh-dot epilogue ----------------
__global__ void __launch_bounds__(256, 2)
gemm_we(const float* __restrict__ be, const float* __restrict__ qe) {
    __shared__ __align__(16) float2 Xs2[KC][130];
    __shared__ __align__(16) float  As[KC][68];
    __shared__ float s_sh[2];
    int t = threadIdx.x;
    int tx = t & 7, ty = t >> 3;
    int lane = t & 31;
    int ib = blockIdx.x * 128;
    const int M = 2 * N_NODES;
    if (t < 2) s_sh[t] = 0.f;
    const float* hp2f = &g_hp2[0][0];
    const float* rs2f = &g_rowsum2[0][0];
    float* yf = &g_y[0][0];
    ull acc[4][4];
    #pragma unroll
    for (int ii = 0; ii < 4; ii++)
        #pragma unroll
        for (int q = 0; q < 4; q++) acc[ii][q] = 0ull;

    for (int kc = 0; kc < 128; kc += KC) {
        #pragma unroll
        for (int p = t; p < 512; p += 256) {
            int i = p & 127, kq = (p >> 7) * 4;
            int gi = ib + i;
            float4 v = make_float4(0.f, 0.f, 0.f, 0.f);
            if (gi < M) {
                int xs = gi >= N_NODES;
                int ii2 = xs ? gi - N_NODES : gi;
                float rs = rs2f[gi];
                if (rs > 0.f) {
                    float inv = 1.f / rs;
                    float4 hv = *(const float4*)&hp2f[(size_t)gi * 128 + kc + kq];
                    float4 pv = *(const float4*)&g_P2all[xs][(size_t)ii2 * 256 + kc + kq];
                    v.x = hv.x * inv + pv.x;
                    v.y = hv.y * inv + pv.y;
                    v.z = hv.z * inv + pv.z;
                    v.w = hv.w * inv + pv.w;
                }
                v.x = (v.x > 0.f) ? v.x : expm1f(v.x);
                v.y = (v.y > 0.f) ? v.y : expm1f(v.y);
                v.z = (v.z > 0.f) ? v.z : expm1f(v.z);
                v.w = (v.w > 0.f) ? v.w : expm1f(v.w);
                *(float4*)&yf[(size_t)gi * 128 + kc + kq] = v;
            }
            Xs2[kq + 0][i] = make_float2(v.x, v.x);
            Xs2[kq + 1][i] = make_float2(v.y, v.y);
            Xs2[kq + 2][i] = make_float2(v.z, v.z);
            Xs2[kq + 3][i] = make_float2(v.w, v.w);
        }
        {
            int j = t & 63, kq = ((t >> 6) & 3) * 4;
            float4 w = *(const float4*)&g_WeP[j * 128 + kc + kq];
            As[kq + 0][j] = w.x; As[kq + 1][j] = w.y;
            As[kq + 2][j] = w.z; As[kq + 3][j] = w.w;
        }
        __syncthreads();
        #pragma unroll
        for (int kk = 0; kk < KC; kk++) {
            ull av[4];
            #pragma unroll
            for (int q = 0; q < 4; q++)
                av[q] = *(const ull*)&As[kk][2 * (tx + 8 * q)];
            #pragma unroll
            for (int ii = 0; ii < 4; ii++) {
                ull xx = *(const ull*)&Xs2[kk][ty * 4 + ii];
                #pragma unroll
                for (int q = 0; q < 4; q++)
                    asm("fma.rn.f32x2 %0, %1, %2, %0;"
                        : "+l"(acc[ii][q]) : "l"(xx), "l"(av[q]));
            }
        }
        __syncthreads();
    }
    float2 bb[4], qq[4];
    #pragma unroll
    for (int q = 0; q < 4; q++) {
        bb[q] = *(const float2*)&be[2 * (tx + 8 * q)];
        qq[q] = *(const float2*)&qe[2 * (tx + 8 * q)];
    }
    #pragma unroll
    for (int ii = 0; ii < 4; ii++) {
        int gi = ib + ty * 4 + ii;
        float lo[4], hi[4];
        #pragma unroll
        for (int q = 0; q < 4; q++)
            asm("mov.b64 {%0, %1}, %2;" : "=f"(lo[q]), "=f"(hi[q]) : "l"(acc[ii][q]));
        float s = 0.f;
        #pragma unroll
        for (int q = 0; q < 4; q++)
            s += tanhf(lo[q] + bb[q].x) * qq[q].x + tanhf(hi[q] + bb[q].y) * qq[q].y;
        #pragma unroll
        for (int o = 4; o; o >>= 1) s += __shfl_xor_sync(0xffffffffu, s, o);
        if ((lane & 7) == 0 && gi < M)
            atomicAdd(&s_sh[gi >= N_NODES], s);
    }
    __syncthreads();
    if (t < 2) atomicAdd(&g_wsum[t], s_sh[t]);
}

// ---------------- layer-1 nhop edge pass (real edges handled in gemm_q) ----------------
__global__ void edge_pass1n(const int* __restrict__ eln, const int* __restrict__ etn) {
    int dir = blockIdx.y;
    int e = blockIdx.x * 8 + (threadIdx.x >> 5);   // [0, E_NHOP)
    int lane = threadIdx.x & 31;
    int h = lane >> 4;
    int jj = 4 * (lane & 15);
    int i0 = eln[e], i1 = eln[E_NHOP + e];
    int t0 = etn[2 * e], t1 = etn[2 * e + 1];
    float4 qa = *(const float4*)&g_R1proj[t0 * 256 + dir * 128 + h * 64 + jj];
    float4 qb = *(const float4*)&g_R1proj[t1 * 256 + dir * 128 + h * 64 + jj];
    float4 q;
    q.x = qa.x + qb.x; q.y = qa.y + qb.y; q.z = qa.z + qb.z; q.w = qa.w + qb.w;
    float sq = g_Sr1[t0 * 4 + dir * 2 + h] + g_Sr1[t1 * 4 + dir * 2 + h];
    int src = dir ? i1 : i0;
    int dst = dir ? i0 : i1;
    float score = g_S1[(size_t)src * 8 + dir * 4 + h]
                + g_S1[(size_t)dst * 8 + dir * 4 + 2 + h] + sq;
    float lk = score > 0.f ? score : ALPHA * score;
    float ev = __expf(-lk);
    float4 d = *(const float4*)&g_P1all[(size_t)dst * 512 + dir * 256 + 128 + h * 64 + jj];
    float* hp = &g_hp1[dir][(size_t)src * 128 + h * 64 + jj];
    RED4(hp, ev * (d.x + q.x), ev * (d.y + q.y), ev * (d.z + q.z), ev * (d.w + q.w));
    if ((lane & 15) == 0) atomicAdd(&g_rowsum1T[(size_t)src * 4 + dir * 2 + h], ev);
}

// ---------------- normalize (+ fold p_src) + elu -> x_s ----------------
__global__ void norm1() {
    int dir = blockIdx.y;
    int idx = blockIdx.x * 256 + threadIdx.x;
    if (idx >= N_NODES * 128) return;
    int i = idx >> 7, kk = idx & 127;
    float rs = g_rowsum1T[(size_t)i * 4 + dir * 2 + (kk >> 6)];
    float v = g_hp1[dir][idx];
    v = (rs > 0.f) ? v / rs + g_P1all[(size_t)i * 512 + dir * 256 + kk] : 0.f;
    v = (v > 0.f) ? v : expm1f(v);
    g_xs[dir][idx] = v;
}

// ---------------- layer-2 edge pass ----------------
__global__ void edge_pass2(const int* __restrict__ el, const int* __restrict__ eln,
                           const int* __restrict__ et, const int* __restrict__ etn) {
    int dir = blockIdx.y;
    int e = blockIdx.x * 8 + (threadIdx.x >> 5);
    if (e >= E_ALL) return;
    int lane = threadIdx.x & 31;
    int i0, i1;
    float q0, q1, q2, q3, sq;
    if (e < E_REAL) {
        i0 = el[e]; i1 = el[E_REAL + e];
        int ty = et[e];
        float4 qv = *(const float4*)&g_R2proj[ty * 128 + 4 * lane];
        q0 = qv.x; q1 = qv.y; q2 = qv.z; q3 = qv.w;
        sq = g_Srel2[ty];
    } else {
        int en = e - E_REAL;
        i0 = eln[en]; i1 = eln[E_NHOP + en];
        int t0 = etn[2 * en], t1 = etn[2 * en + 1];
        float4 qa = *(const float4*)&g_R2proj[t0 * 128 + 4 * lane];
        float4 qb = *(const float4*)&g_R2proj[t1 * 128 + 4 * lane];
        q0 = qa.x + qb.x; q1 = qa.y + qb.y; q2 = qa.z + qb.z; q3 = qa.w + qb.w;
        sq = g_Srel2[t0] + g_Srel2[t1];
    }
    int seg = dir ? i1 : i0;
    int nbr = dir ? i0 : i1;
    float4 sA = *(const float4*)&g_S2[dir][(size_t)seg * 4];
    float4 sB = *(const float4*)&g_S2[dir][(size_t)nbr * 4];
    float score = sA.x + sA.y + sB.z + sB.w + sq;
    float lk = score > 0.f ? score : ALPHA * score;
    float ev = __expf(-lk);
    float4 dv = *(const float4*)&g_P2all[dir][(size_t)nbr * 256 + 128 + 4 * lane];
    float* hp = &g_hp2[dir][(size_t)seg * 128 + 4 * lane];
    RED4(hp, ev * (dv.x + q0), ev * (dv.y + q1), ev * (dv.z + q2), ev * (dv.w + q3));
    if (lane == 0) atomicAdd(&g_rowsum2[dir][seg], ev);
}

// ---------------- beta + combine ----------------
__global__ void combine(float* __restrict__ out) {
    float m0 = g_wsum[0] / (float)N_NODES;
    float m1 = g_wsum[1] / (float)N_NODES;
    float mx = fmaxf(m0, m1);
    float e0 = expf(m0 - mx), e1 = expf(m1 - mx);
    float b0 = e0 / (e0 + e1), b1 = e1 / (e0 + e1);
    size_t i = (size_t)blockIdx.x * 256 + threadIdx.x;
    if (i >= (size_t)N_NODES * OUTF) return;
    out[i] = b0 * g_y[0][i] + b1 * g_y[1][i];
}

// ---------------- launch ----------------
extern "C" void kernel_launch(void* const* d_in, const int* in_sizes, int n_in,
                              void* d_out, int out_size) {
    const float* ent   = (const float*)d_in[0];
    const float* rel   = (const float*)d_in[1];
    const int*   el    = (const int*)d_in[2];
    const int*   et    = (const int*)d_in[3];
    const float* eemb  = (const float*)d_in[4];
    const int*   eln   = (const int*)d_in[5];
    const int*   etn   = (const int*)d_in[6];
    const float* a_in  = (const float*)d_in[7];
    const float* a2_in = (const float*)d_in[8];
    const float* a_out = (const float*)d_in[9];
    const float* a2_out= (const float*)d_in[10];
    const float* a_o   = (const float*)d_in[11];
    const float* a2_o  = (const float*)d_in[12];
    const float* W     = (const float*)d_in[13];
    const float* We    = (const float*)d_in[14];
    const float* be    = (const float*)d_in[15];
    const float* qe    = (const float*)d_in[16];
    float* out = (float*)d_out;

    float *p1 = 0, *xsb = 0, *p2 = 0, *wp1 = 0, *wp2 = 0;
    float *a2c1 = 0, *a2c2 = 0, *s1 = 0, *s2 = 0;
    cudaGetSymbolAddress((void**)&p1, g_P1all);
    cudaGetSymbolAddress((void**)&xsb, g_xs);
    cudaGetSymbolAddress((void**)&p2, g_P2all);
    cudaGetSymbolAddress((void**)&wp1, g_Wp1);
    cudaGetSymbolAddress((void**)&wp2, g_Wp2);
    cudaGetSymbolAddress((void**)&a2c1, g_a2cat1);
    cudaGetSymbolAddress((void**)&a2c2, g_a2cat2);
    cudaGetSymbolAddress((void**)&s1, g_S1);
    cudaGetSymbolAddress((void**)&s2, g_S2);

    setup<<<725, 256>>>(a_in, a_out, a_o, a2_in, a2_out, a2_o, rel, W, We, out);

    // layer-1 node projections (P1 + S1)
    gemm_f32x2<<<dim3((N_NODES + 127) / 128, 4), 256>>>(ent, wp1, p1, a2c1, s1,
                                                        N_NODES, 512, 64);
    // Q projection with fused real-edge pass (needs P1all + S1 ready)
    gemm_q<<<dim3((E_REAL + 127) / 128, 2), 256>>>(eemb, el);
    // nhop edges
    edge_pass1n<<<dim3(E_NHOP / 8, 2), 256>>>(eln, etn);
    norm1<<<dim3((N_NODES * 128 + 255) / 256, 2), 256>>>();

    // layer-2 projections (both xs merged: M = 100000)
    gemm_f32x2<<<dim3((2 * N_NODES + 127) / 128, 2), 256>>>(
        xsb, wp2, p2, a2c2, s2, 2 * N_NODES, 256, 128);

    edge_pass2<<<dim3(E_ALL / 8, 2), 256>>>(el, eln, et, etn);

    gemm_we<<<(2 * N_NODES + 127) / 128, 256>>>(be, qe);
    combine<<<(N_NODES * OUTF + 255) / 256, 256>>>(out);
}

// round 13
// speedup vs baseline: 1.1709x; 1.0184x over previous
#include <cuda_runtime.h>
#include <math.h>

#define N_NODES 50000
#define NFEAT   64
#define NHID    64
#define E_REAL  200000
#define E_NHOP  40000
#define E_ALL   240000
#define N_REL   200
#define OUTF    128
#define ALPHA   0.2f

typedef unsigned long long ull;

// ---------------- device scratch ----------------
__device__ __align__(16) float g_P1all[(size_t)N_NODES * 512];     // [i][dir*256+role*128+h*64+j]
__device__ __align__(16) float g_R1proj[N_REL * 256];              // [r*256 + c*64 + j]
__device__ __align__(16) float g_R2proj[N_REL * OUTF];
__device__ __align__(16) float g_rowsum1T[(size_t)N_NODES * 4];    // [i*4 + dir*2 + h]
__device__ __align__(16) float g_hp1[2][(size_t)N_NODES * 128];
__device__ __align__(16) float g_P2all[2][(size_t)N_NODES * 256];
__device__ float g_rowsum2[2][N_NODES];
__device__ __align__(16) float g_hp2[2][(size_t)N_NODES * OUTF];
__device__ __align__(16) float g_y[2][(size_t)N_NODES * OUTF];
__device__ float g_wsum[2];
// packed weights (row-major [n][K])
__device__ __align__(16) float g_Wp1[512 * 64];
__device__ __align__(16) float g_WpQ[256 * 64];
__device__ __align__(16) float g_Wp2[256 * 128];
__device__ __align__(16) float g_WeP[64 * 128];                    // [j][k]
// factorized attention scalars
__device__ __align__(16) float g_S1[(size_t)N_NODES * 8];          // [i*8 + dir*4 + role*2 + h]
__device__ __align__(16) float g_Sr1[N_REL * 4];
__device__ __align__(16) float g_S2[2][(size_t)N_NODES * 4];
__device__ float g_Srel2[N_REL];
// per-column dot weights
__device__ __align__(16) float g_a2cat1[512];
__device__ __align__(16) float g_a2catQ[256];
__device__ __align__(16) float g_a2cat2[256];

#define RED2(ptr, a, b) \
    asm volatile("red.global.add.v2.f32 [%0], {%1, %2};" :: "l"(ptr), "f"(a), "f"(b) : "memory")
#define RED4(ptr, a, b, c, d) \
    asm volatile("red.global.add.v4.f32 [%0], {%1, %2, %3, %4};" :: "l"(ptr), "f"(a), "f"(b), "f"(c), "f"(d) : "memory")

// ---------------- fused setup ----------------
__global__ void setup(const float* __restrict__ a_in, const float* __restrict__ a_out,
                      const float* __restrict__ a_o,
                      const float* __restrict__ a2_in, const float* __restrict__ a2_out,
                      const float* __restrict__ a2_o,
                      const float* __restrict__ rel, const float* __restrict__ W,
                      const float* __restrict__ We, float* __restrict__ out_tail) {
    int b = blockIdx.x, t = threadIdx.x;
    if (b < 512) {
        size_t tid = (size_t)b * 256 + t, stride = (size_t)512 * 256;
        float4 z = make_float4(0.f, 0.f, 0.f, 0.f);
        float4* hp1 = (float4*)&g_hp1[0][0];
        for (size_t i = tid; i < (size_t)2 * N_NODES * 32; i += stride) hp1[i] = z;
        float4* hp2 = (float4*)&g_hp2[0][0];
        for (size_t i = tid; i < (size_t)2 * N_NODES * 32; i += stride) hp2[i] = z;
        float4* rs1 = (float4*)&g_rowsum1T[0];
        for (size_t i = tid; i < (size_t)N_NODES; i += stride) rs1[i] = z;
        float4* rs2 = (float4*)&g_rowsum2[0][0];
        for (size_t i = tid; i < (size_t)N_NODES / 2; i += stride) rs2[i] = z;
        if (tid < 2) g_wsum[tid] = 0.f;
    } else if (b < 516) {
        for (int idx = (b - 512) * 256 + t; idx < 512 * 64; idx += 4 * 256) {
            int n = idx >> 6, k = idx & 63;
            int dir = n >> 8, role = (n >> 7) & 1, h = (n >> 6) & 1, j = n & 63;
            const float* A = (dir ? a_out : a_in) + (size_t)h * 64 * 192;
            g_Wp1[idx] = A[j * 192 + role * 64 + k];
        }
    } else if (b < 518) {
        for (int idx = (b - 516) * 256 + t; idx < 256 * 64; idx += 2 * 256) {
            int n = idx >> 6, k = idx & 63;
            int c = n >> 6, j = n & 63;
            const float* A = ((c >> 1) ? a_out : a_in) + (size_t)(c & 1) * 64 * 192;
            g_WpQ[idx] = A[j * 192 + 128 + k];
        }
    } else if (b < 522) {
        for (int idx = (b - 518) * 256 + t; idx < 256 * 128; idx += 4 * 256) {
            int n = idx >> 7, k = idx & 127;
            int role = n >> 7, j = n & 127;
            g_Wp2[idx] = a_o[j * 384 + role * 128 + k];
        }
    } else if (b < 524) {
        for (int idx = (b - 522) * 256 + t; idx < 64 * 128; idx += 2 * 256) {
            int j = idx >> 7, k = idx & 127;
            g_WeP[idx] = We[k * 64 + j];
        }
    } else if (b == 524) {
        for (int n = t; n < 512; n += 256) {
            int dir = n >> 8, h = (n >> 6) & 1, j = n & 63;
            g_a2cat1[n] = (dir ? a2_out : a2_in)[h * 64 + j];
        }
        for (int n = t; n < 256; n += 256) {
            int c = n >> 6, j = n & 63;
            g_a2catQ[n] = ((c >> 1) ? a2_out : a2_in)[(c & 1) * 64 + j];
        }
        if (t < 256) g_a2cat2[t] = a2_o[t & 127];
    } else {
        int r = b - 525;  // [0, 200)
        __shared__ float relrow[64];
        __shared__ float rel2row[128];
        __shared__ float red[8];
        if (t < 64) relrow[t] = rel[r * 64 + t];
        __syncthreads();
        if (t < 128) {
            float acc = 0.f;
            #pragma unroll
            for (int k = 0; k < 64; k++) acc += relrow[k] * W[k * 128 + t];
            rel2row[t] = acc;
            out_tail[(size_t)N_NODES * OUTF + r * 128 + t] = acc;
        }
        __syncthreads();
        {
            int c = t >> 6, j = t & 63;
            const float* A = ((c >> 1) ? a_out : a_in) + (size_t)(c & 1) * 64 * 192;
            float acc = 0.f;
            #pragma unroll
            for (int k = 0; k < 64; k++) acc += relrow[k] * A[j * 192 + 128 + k];
            g_R1proj[r * 256 + t] = acc;
            float part = acc * ((c >> 1) ? a2_out : a2_in)[(c & 1) * 64 + j];
            #pragma unroll
            for (int o = 16; o; o >>= 1) part += __shfl_xor_sync(0xffffffffu, part, o);
            if ((t & 31) == 0) red[t >> 5] = part;
        }
        __syncthreads();
        if (t < 4) g_Sr1[r * 4 + t] = red[2 * t] + red[2 * t + 1];
        __syncthreads();
        {
            float part = 0.f;
            if (t < 128) {
                float acc = 0.f;
                #pragma unroll 16
                for (int k = 0; k < 128; k++) acc += rel2row[k] * a_o[t * 384 + 256 + k];
                g_R2proj[r * 128 + t] = acc;
                part = acc * a2_o[t];
            }
            #pragma unroll
            for (int o = 16; o; o >>= 1) part += __shfl_xor_sync(0xffffffffu, part, o);
            if ((t & 31) == 0 && t < 128) red[t >> 5] = part;
        }
        __syncthreads();
        if (t == 0) g_Srel2[r] = red[0] + red[1] + red[2] + red[3];
    }
}

// ---------------- f32x2 GEMM (projection variant, register prefetch) ----------------
#define KC 16
__global__ void __launch_bounds__(256, 2)
gemm_f32x2(const float* __restrict__ X,
           const float* __restrict__ Wp,
           float* __restrict__ C,
           const float* __restrict__ a2cat,
           float* __restrict__ sOut,
           int M, int N, int K) {
    __shared__ __align__(16) float2 Xs2[KC][130];
    __shared__ __align__(16) float  As[KC][132];
    int t = threadIdx.x;
    int tx = t & 15, ty = t >> 4;
    int ib = blockIdx.x * 128;
    int jb = blockIdx.y * 128;
    ull acc[8][4];
    #pragma unroll
    for (int ii = 0; ii < 8; ii++)
        #pragma unroll
        for (int q = 0; q < 4; q++) acc[ii][q] = 0ull;

    float4 xb[2], ab[2];
    int pi0 = t & 127, pk0 = (t >> 7) * 4;
    int pk1 = pk0 + 8;
    {
        int gi = ib + pi0;
        xb[0] = make_float4(0.f, 0.f, 0.f, 0.f);
        xb[1] = make_float4(0.f, 0.f, 0.f, 0.f);
        if (gi < M) {
            xb[0] = *(const float4*)&X[(size_t)gi * K + pk0];
            xb[1] = *(const float4*)&X[(size_t)gi * K + pk1];
        }
        ab[0] = *(const float4*)&Wp[(size_t)(jb + pi0) * K + pk0];
        ab[1] = *(const float4*)&Wp[(size_t)(jb + pi0) * K + pk1];
    }

    for (int kc = 0; kc < K; kc += KC) {
        #pragma unroll
        for (int u = 0; u < 2; u++) {
            int kq = u ? pk1 : pk0;
            float4 v = xb[u];
            Xs2[kq + 0][pi0] = make_float2(v.x, v.x);
            Xs2[kq + 1][pi0] = make_float2(v.y, v.y);
            Xs2[kq + 2][pi0] = make_float2(v.z, v.z);
            Xs2[kq + 3][pi0] = make_float2(v.w, v.w);
            float4 a = ab[u];
            As[kq + 0][pi0] = a.x; As[kq + 1][pi0] = a.y;
            As[kq + 2][pi0] = a.z; As[kq + 3][pi0] = a.w;
        }
        __syncthreads();
        if (kc + KC < K) {
            int gi = ib + pi0;
            xb[0] = make_float4(0.f, 0.f, 0.f, 0.f);
            xb[1] = make_float4(0.f, 0.f, 0.f, 0.f);
            if (gi < M) {
                xb[0] = *(const float4*)&X[(size_t)gi * K + kc + KC + pk0];
                xb[1] = *(const float4*)&X[(size_t)gi * K + kc + KC + pk1];
            }
            ab[0] = *(const float4*)&Wp[(size_t)(jb + pi0) * K + kc + KC + pk0];
            ab[1] = *(const float4*)&Wp[(size_t)(jb + pi0) * K + kc + KC + pk1];
        }
        #pragma unroll
        for (int kk = 0; kk < KC; kk++) {
            ull av[4];
            #pragma unroll
            for (int q = 0; q < 4; q++)
                av[q] = *(const ull*)&As[kk][2 * (tx + 16 * q)];
            #pragma unroll
            for (int ii = 0; ii < 8; ii++) {
                ull xx = *(const ull*)&Xs2[kk][ty * 8 + ii];
                #pragma unroll
                for (int q = 0; q < 4; q++)
                    asm("fma.rn.f32x2 %0, %1, %2, %0;"
                        : "+l"(acc[ii][q]) : "l"(xx), "l"(av[q]));
            }
        }
        __syncthreads();
    }
    int nBlk = N >> 6;
    float2 w[4];
    #pragma unroll
    for (int q = 0; q < 4; q++)
        w[q] = *(const float2*)&a2cat[jb + 2 * (tx + 16 * q)];
    #pragma unroll
    for (int ii = 0; ii < 8; ii++) {
        int gi = ib + ty * 8 + ii;
        float lo[4], hi[4];
        #pragma unroll
        for (int q = 0; q < 4; q++)
            asm("mov.b64 {%0, %1}, %2;" : "=f"(lo[q]), "=f"(hi[q]) : "l"(acc[ii][q]));
        if (gi < M) {
            #pragma unroll
            for (int q = 0; q < 4; q++)
                *(float2*)&C[(size_t)gi * N + jb + 2 * (tx + 16 * q)] = make_float2(lo[q], hi[q]);
        }
        float s0 = lo[0] * w[0].x + hi[0] * w[0].y + lo[1] * w[1].x + hi[1] * w[1].y;
        float s1 = lo[2] * w[2].x + hi[2] * w[2].y + lo[3] * w[3].x + hi[3] * w[3].y;
        #pragma unroll
        for (int o = 8; o; o >>= 1) {
            s0 += __shfl_xor_sync(0xffffffffu, s0, o);
            s1 += __shfl_xor_sync(0xffffffffu, s1, o);
        }
        if (tx == 0 && gi < M) {
            size_t base = (size_t)gi * nBlk + (jb >> 6);
            sOut[base] = s0;
            sOut[base + 1] = s1;
        }
    }
}

// ---------------- gemm_x2: layer-2 projection with FUSED norm1 in the X loader ----------------
// X row gi in [0, 2*N_NODES): dir = gi / N_NODES, i = gi % N_NODES.
// x = elu(hp1/rs + p_src) computed on the fly; g_xs never materialized.
__global__ void __launch_bounds__(256, 2)
gemm_x2(float* __restrict__ C, const float* __restrict__ a2cat,
        float* __restrict__ sOut) {
    __shared__ __align__(16) float2 Xs2[KC][130];
    __shared__ __align__(16) float  As[KC][132];
    int t = threadIdx.x;
    int tx = t & 15, ty = t >> 4;
    int ib = blockIdx.x * 128;
    int jb = blockIdx.y * 128;
    const int M = 2 * N_NODES, N = 256, K = 128;
    ull acc[8][4];
    #pragma unroll
    for (int ii = 0; ii < 8; ii++)
        #pragma unroll
        for (int q = 0; q < 4; q++) acc[ii][q] = 0ull;

    for (int kc = 0; kc < K; kc += KC) {
        // fused norm1 loader
        #pragma unroll
        for (int p = t; p < 512; p += 256) {
            int i = p & 127, kq = (p >> 7) * 4;
            int gi = ib + i;
            float4 v = make_float4(0.f, 0.f, 0.f, 0.f);
            if (gi < M) {
                int dir = gi >= N_NODES;
                int i2 = dir ? gi - N_NODES : gi;
                int kk = kc + kq;
                float rs = g_rowsum1T[(size_t)i2 * 4 + dir * 2 + (kk >> 6)];
                if (rs > 0.f) {
                    float inv = 1.f / rs;
                    float4 hv = *(const float4*)&g_hp1[dir][(size_t)i2 * 128 + kk];
                    float4 pv = *(const float4*)&g_P1all[(size_t)i2 * 512 + dir * 256 + kk];
                    v.x = hv.x * inv + pv.x;
                    v.y = hv.y * inv + pv.y;
                    v.z = hv.z * inv + pv.z;
                    v.w = hv.w * inv + pv.w;
                }
                v.x = (v.x > 0.f) ? v.x : expm1f(v.x);
                v.y = (v.y > 0.f) ? v.y : expm1f(v.y);
                v.z = (v.z > 0.f) ? v.z : expm1f(v.z);
                v.w = (v.w > 0.f) ? v.w : expm1f(v.w);
            }
            Xs2[kq + 0][i] = make_float2(v.x, v.x);
            Xs2[kq + 1][i] = make_float2(v.y, v.y);
            Xs2[kq + 2][i] = make_float2(v.z, v.z);
            Xs2[kq + 3][i] = make_float2(v.w, v.w);
        }
        #pragma unroll
        for (int p = t; p < 512; p += 256) {
            int j = p & 127, kq = (p >> 7) * 4;
            float4 v = *(const float4*)&g_Wp2[(size_t)(jb + j) * K + kc + kq];
            As[kq + 0][j] = v.x; As[kq + 1][j] = v.y;
            As[kq + 2][j] = v.z; As[kq + 3][j] = v.w;
        }
        __syncthreads();
        #pragma unroll
        for (int kk = 0; kk < KC; kk++) {
            ull av[4];
            #pragma unroll
            for (int q = 0; q < 4; q++)
                av[q] = *(const ull*)&As[kk][2 * (tx + 16 * q)];
            #pragma unroll
            for (int ii = 0; ii < 8; ii++) {
                ull xx = *(const ull*)&Xs2[kk][ty * 8 + ii];
                #pragma unroll
                for (int q = 0; q < 4; q++)
                    asm("fma.rn.f32x2 %0, %1, %2, %0;"
                        : "+l"(acc[ii][q]) : "l"(xx), "l"(av[q]));
            }
        }
        __syncthreads();
    }
    int nBlk = N >> 6;
    float2 w[4];
    #pragma unroll
    for (int q = 0; q < 4; q++)
        w[q] = *(const float2*)&a2cat[jb + 2 * (tx + 16 * q)];
    #pragma unroll
    for (int ii = 0; ii < 8; ii++) {
        int gi = ib + ty * 8 + ii;
        float lo[4], hi[4];
        #pragma unroll
        for (int q = 0; q < 4; q++)
            asm("mov.b64 {%0, %1}, %2;" : "=f"(lo[q]), "=f"(hi[q]) : "l"(acc[ii][q]));
        if (gi < M) {
            #pragma unroll
            for (int q = 0; q < 4; q++)
                *(float2*)&C[(size_t)gi * N + jb + 2 * (tx + 16 * q)] = make_float2(lo[q], hi[q]);
        }
        float s0 = lo[0] * w[0].x + hi[0] * w[0].y + lo[1] * w[1].x + hi[1] * w[1].y;
        float s1 = lo[2] * w[2].x + hi[2] * w[2].y + lo[3] * w[3].x + hi[3] * w[3].y;
        #pragma unroll
        for (int o = 8; o; o >>= 1) {
            s0 += __shfl_xor_sync(0xffffffffu, s0, o);
            s1 += __shfl_xor_sync(0xffffffffu, s1, o);
        }
        if (tx == 0 && gi < M) {
            size_t base = (size_t)gi * nBlk + (jb >> 6);
            sOut[base] = s0;
            sOut[base + 1] = s1;
        }
    }
}

// ---------------- gemm_q: Q projection with FUSED layer-1 real-edge pass ----------------
__global__ void __launch_bounds__(256, 2)
gemm_q(const float* __restrict__ X, const int* __restrict__ el) {
    __shared__ __align__(16) float2 Xs2[KC][130];
    __shared__ __align__(16) float  As[KC][132];
    int t = threadIdx.x;
    int tx = t & 15, ty = t >> 4;
    int dir = blockIdx.y;
    int ib = blockIdx.x * 128;
    int jb = dir * 128;
    const int M = E_REAL, K = 64;
    ull acc[8][4];
    #pragma unroll
    for (int ii = 0; ii < 8; ii++)
        #pragma unroll
        for (int q = 0; q < 4; q++) acc[ii][q] = 0ull;

    float4 xb[2], ab[2];
    int pi0 = t & 127, pk0 = (t >> 7) * 4;
    int pk1 = pk0 + 8;
    {
        int gi = ib + pi0;
        xb[0] = make_float4(0.f, 0.f, 0.f, 0.f);
        xb[1] = make_float4(0.f, 0.f, 0.f, 0.f);
        if (gi < M) {
            xb[0] = *(const float4*)&X[(size_t)gi * K + pk0];
            xb[1] = *(const float4*)&X[(size_t)gi * K + pk1];
        }
        ab[0] = *(const float4*)&g_WpQ[(size_t)(jb + pi0) * K + pk0];
        ab[1] = *(const float4*)&g_WpQ[(size_t)(jb + pi0) * K + pk1];
    }

    for (int kc = 0; kc < K; kc += KC) {
        #pragma unroll
        for (int u = 0; u < 2; u++) {
            int kq = u ? pk1 : pk0;
            float4 v = xb[u];
            Xs2[kq + 0][pi0] = make_float2(v.x, v.x);
            Xs2[kq + 1][pi0] = make_float2(v.y, v.y);
            Xs2[kq + 2][pi0] = make_float2(v.z, v.z);
            Xs2[kq + 3][pi0] = make_float2(v.w, v.w);
            float4 a = ab[u];
            As[kq + 0][pi0] = a.x; As[kq + 1][pi0] = a.y;
            As[kq + 2][pi0] = a.z; As[kq + 3][pi0] = a.w;
        }
        __syncthreads();
        if (kc + KC < K) {
            int gi = ib + pi0;
            xb[0] = make_float4(0.f, 0.f, 0.f, 0.f);
            xb[1] = make_float4(0.f, 0.f, 0.f, 0.f);
            if (gi < M) {
                xb[0] = *(const float4*)&X[(size_t)gi * K + kc + KC + pk0];
                xb[1] = *(const float4*)&X[(size_t)gi * K + kc + KC + pk1];
            }
            ab[0] = *(const float4*)&g_WpQ[(size_t)(jb + pi0) * K + kc + KC + pk0];
            ab[1] = *(const float4*)&g_WpQ[(size_t)(jb + pi0) * K + kc + KC + pk1];
        }
        #pragma unroll
        for (int kk = 0; kk < KC; kk++) {
            ull av[4];
            #pragma unroll
            for (int q = 0; q < 4; q++)
                av[q] = *(const ull*)&As[kk][2 * (tx + 16 * q)];
            #pragma unroll
            for (int ii = 0; ii < 8; ii++) {
                ull xx = *(const ull*)&Xs2[kk][ty * 8 + ii];
                #pragma unroll
                for (int q = 0; q < 4; q++)
                    asm("fma.rn.f32x2 %0, %1, %2, %0;"
                        : "+l"(acc[ii][q]) : "l"(xx), "l"(av[q]));
            }
        }
        __syncthreads();
    }
    float2 w[4];
    #pragma unroll
    for (int q = 0; q < 4; q++)
        w[q] = *(const float2*)&g_a2catQ[jb + 2 * (tx + 16 * q)];
    #pragma unroll
    for (int ii = 0; ii < 8; ii++) {
        int gi = ib + ty * 8 + ii;   // edge index
        float lo[4], hi[4];
        #pragma unroll
        for (int q = 0; q < 4; q++)
            asm("mov.b64 {%0, %1}, %2;" : "=f"(lo[q]), "=f"(hi[q]) : "l"(acc[ii][q]));
        float s0 = lo[0] * w[0].x + hi[0] * w[0].y + lo[1] * w[1].x + hi[1] * w[1].y;
        float s1 = lo[2] * w[2].x + hi[2] * w[2].y + lo[3] * w[3].x + hi[3] * w[3].y;
        #pragma unroll
        for (int o = 8; o; o >>= 1) {
            s0 += __shfl_xor_sync(0xffffffffu, s0, o);
            s1 += __shfl_xor_sync(0xffffffffu, s1, o);
        }
        if (gi < M) {
            int i0 = el[gi], i1 = el[E_REAL + gi];
            int src = dir ? i1 : i0;
            int dst = dir ? i0 : i1;
            float4 sv = *(const float4*)&g_S1[(size_t)src * 8 + dir * 4];
            float4 dv = *(const float4*)&g_S1[(size_t)dst * 8 + dir * 4];
            float sc0 = sv.x + dv.z + s0;
            float sc1 = sv.y + dv.w + s1;
            float lk0 = sc0 > 0.f ? sc0 : ALPHA * sc0;
            float lk1 = sc1 > 0.f ? sc1 : ALPHA * sc1;
            float ev0 = __expf(-lk0);
            float ev1 = __expf(-lk1);
            const float* pd = &g_P1all[(size_t)dst * 512 + dir * 256 + 128];
            float* hp = &g_hp1[dir][(size_t)src * 128];
            #pragma unroll
            for (int q = 0; q < 4; q++) {
                int col = 2 * (tx + 16 * q);
                float ev = (q < 2) ? ev0 : ev1;
                float2 d = *(const float2*)&pd[col];
                RED2(&hp[col], ev * (d.x + lo[q]), ev * (d.y + hi[q]));
            }
            if (tx == 0) {
                atomicAdd(&g_rowsum1T[(size_t)src * 4 + dir * 2], ev0);
                atomicAdd(&g_rowsum1T[(size_t)src * 4 + dir * 2 + 1], ev1);
            }
        }
    }
}

// ---------------- gemm_we: norm2 fused into loader + tanh-dot epilogue ----------------
__global__ void __launch_bounds__(256, 2)
gemm_we(const float* __restrict__ be, const float* __restrict__ qe) {
    __shared__ __align__(16) float2 Xs2[KC][130];
    __shared__ __align__(16) float  As[KC][68];
    __shared__ float s_sh[2];
    int t = threadIdx.x;
    int tx = t & 7, ty = t >> 3;
    int lane = t & 31;
    int ib = blockIdx.x * 128;
    const int M = 2 * N_NODES;
    if (t < 2) s_sh[t] = 0.f;
    const float* hp2f = &g_hp2[0][0];
    const float* rs2f = &g_rowsum2[0][0];
    float* yf = &g_y[0][0];
    ull acc[4][4];
    #pragma unroll
    for (int ii = 0; ii < 4; ii++)
        #pragma unroll
        for (int q = 0; q < 4; q++) acc[ii][q] = 0ull;

    for (int kc = 0; kc < 128; kc += KC) {
        #pragma unroll
        for (int p = t; p < 512; p += 256) {
            int i = p & 127, kq = (p >> 7) * 4;
            int gi = ib + i;
            float4 v = make_float4(0.f, 0.f, 0.f, 0.f);
            if (gi < M) {
                int xs = gi >= N_NODES;
                int ii2 = xs ? gi - N_NODES : gi;
                float rs = rs2f[gi];
                if (rs > 0.f) {
                    float inv = 1.f / rs;
                    float4 hv = *(const float4*)&hp2f[(size_t)gi * 128 + kc + kq];
                    float4 pv = *(const float4*)&g_P2all[xs][(size_t)ii2 * 256 + kc + kq];
                    v.x = hv.x * inv + pv.x;
                    v.y = hv.y * inv + pv.y;
                    v.z = hv.z * inv + pv.z;
                    v.w = hv.w * inv + pv.w;
                }
                v.x = (v.x > 0.f) ? v.x : expm1f(v.x);
                v.y = (v.y > 0.f) ? v.y : expm1f(v.y);
                v.z = (v.z > 0.f) ? v.z : expm1f(v.z);
                v.w = (v.w > 0.f) ? v.w : expm1f(v.w);
                *(float4*)&yf[(size_t)gi * 128 + kc + kq] = v;
            }
            Xs2[kq + 0][i] = make_float2(v.x, v.x);
            Xs2[kq + 1][i] = make_float2(v.y, v.y);
            Xs2[kq + 2][i] = make_float2(v.z, v.z);
            Xs2[kq + 3][i] = make_float2(v.w, v.w);
        }
        {
            int j = t & 63, kq = ((t >> 6) & 3) * 4;
            float4 w = *(const float4*)&g_WeP[j * 128 + kc + kq];
            As[kq + 0][j] = w.x; As[kq + 1][j] = w.y;
            As[kq + 2][j] = w.z; As[kq + 3][j] = w.w;
        }
        __syncthreads();
        #pragma unroll
        for (int kk = 0; kk < KC; kk++) {
            ull av[4];
            #pragma unroll
            for (int q = 0; q < 4; q++)
                av[q] = *(const ull*)&As[kk][2 * (tx + 8 * q)];
            #pragma unroll
            for (int ii = 0; ii < 4; ii++) {
                ull xx = *(const ull*)&Xs2[kk][ty * 4 + ii];
                #pragma unroll
                for (int q = 0; q < 4; q++)
                    asm("fma.rn.f32x2 %0, %1, %2, %0;"
                        : "+l"(acc[ii][q]) : "l"(xx), "l"(av[q]));
            }
        }
        __syncthreads();
    }
    float2 bb[4], qq[4];
    #pragma unroll
    for (int q = 0; q < 4; q++) {
        bb[q] = *(const float2*)&be[2 * (tx + 8 * q)];
        qq[q] = *(const float2*)&qe[2 * (tx + 8 * q)];
    }
    #pragma unroll
    for (int ii = 0; ii < 4; ii++) {
        int gi = ib + ty * 4 + ii;
        float lo[4], hi[4];
        #pragma unroll
        for (int q = 0; q < 4; q++)
            asm("mov.b64 {%0, %1}, %2;" : "=f"(lo[q]), "=f"(hi[q]) : "l"(acc[ii][q]));
        float s = 0.f;
        #pragma unroll
        for (int q = 0; q < 4; q++)
            s += tanhf(lo[q] + bb[q].x) * qq[q].x + tanhf(hi[q] + bb[q].y) * qq[q].y;
        #pragma unroll
        for (int o = 4; o; o >>= 1) s += __shfl_xor_sync(0xffffffffu, s, o);
        if ((lane & 7) == 0 && gi < M)
            atomicAdd(&s_sh[gi >= N_NODES], s);
    }
    __syncthreads();
    if (t < 2) atomicAdd(&g_wsum[t], s_sh[t]);
}

// ---------------- layer-1 nhop edge pass ----------------
__global__ void edge_pass1n(const int* __restrict__ eln, const int* __restrict__ etn) {
    int dir = blockIdx.y;
    int e = blockIdx.x * 8 + (threadIdx.x >> 5);
    int lane = threadIdx.x & 31;
    int h = lane >> 4;
    int jj = 4 * (lane & 15);
    int i0 = eln[e], i1 = eln[E_NHOP + e];
    int t0 = etn[2 * e], t1 = etn[2 * e + 1];
    float4 qa = *(const float4*)&g_R1proj[t0 * 256 + dir * 128 + h * 64 + jj];
    float4 qb = *(const float4*)&g_R1proj[t1 * 256 + dir * 128 + h * 64 + jj];
    float4 q;
    q.x = qa.x + qb.x; q.y = qa.y + qb.y; q.z = qa.z + qb.z; q.w = qa.w + qb.w;
    float sq = g_Sr1[t0 * 4 + dir * 2 + h] + g_Sr1[t1 * 4 + dir * 2 + h];
    int src = dir ? i1 : i0;
    int dst = dir ? i0 : i1;
    float score = g_S1[(size_t)src * 8 + dir * 4 + h]
                + g_S1[(size_t)dst * 8 + dir * 4 + 2 + h] + sq;
    float lk = score > 0.f ? score : ALPHA * score;
    float ev = __expf(-lk);
    float4 d = *(const float4*)&g_P1all[(size_t)dst * 512 + dir * 256 + 128 + h * 64 + jj];
    float* hp = &g_hp1[dir][(size_t)src * 128 + h * 64 + jj];
    RED4(hp, ev * (d.x + q.x), ev * (d.y + q.y), ev * (d.z + q.z), ev * (d.w + q.w));
    if ((lane & 15) == 0) atomicAdd(&g_rowsum1T[(size_t)src * 4 + dir * 2 + h], ev);
}

// ---------------- layer-2 edge pass ----------------
__global__ void edge_pass2(const int* __restrict__ el, const int* __restrict__ eln,
                           const int* __restrict__ et, const int* __restrict__ etn) {
    int dir = blockIdx.y;
    int e = blockIdx.x * 8 + (threadIdx.x >> 5);
    if (e >= E_ALL) return;
    int lane = threadIdx.x & 31;
    int i0, i1;
    float q0, q1, q2, q3, sq;
    if (e < E_REAL) {
        i0 = el[e]; i1 = el[E_REAL + e];
        int ty = et[e];
        float4 qv = *(const float4*)&g_R2proj[ty * 128 + 4 * lane];
        q0 = qv.x; q1 = qv.y; q2 = qv.z; q3 = qv.w;
        sq = g_Srel2[ty];
    } else {
        int en = e - E_REAL;
        i0 = eln[en]; i1 = eln[E_NHOP + en];
        int t0 = etn[2 * en], t1 = etn[2 * en + 1];
        float4 qa = *(const float4*)&g_R2proj[t0 * 128 + 4 * lane];
        float4 qb = *(const float4*)&g_R2proj[t1 * 128 + 4 * lane];
        q0 = qa.x + qb.x; q1 = qa.y + qb.y; q2 = qa.z + qb.z; q3 = qa.w + qb.w;
        sq = g_Srel2[t0] + g_Srel2[t1];
    }
    int seg = dir ? i1 : i0;
    int nbr = dir ? i0 : i1;
    float4 sA = *(const float4*)&g_S2[dir][(size_t)seg * 4];
    float4 sB = *(const float4*)&g_S2[dir][(size_t)nbr * 4];
    float score = sA.x + sA.y + sB.z + sB.w + sq;
    float lk = score > 0.f ? score : ALPHA * score;
    float ev = __expf(-lk);
    float4 dv = *(const float4*)&g_P2all[dir][(size_t)nbr * 256 + 128 + 4 * lane];
    float* hp = &g_hp2[dir][(size_t)seg * 128 + 4 * lane];
    RED4(hp, ev * (dv.x + q0), ev * (dv.y + q1), ev * (dv.z + q2), ev * (dv.w + q3));
    if (lane == 0) atomicAdd(&g_rowsum2[dir][seg], ev);
}

// ---------------- beta + combine ----------------
__global__ void combine(float* __restrict__ out) {
    float m0 = g_wsum[0] / (float)N_NODES;
    float m1 = g_wsum[1] / (float)N_NODES;
    float mx = fmaxf(m0, m1);
    float e0 = expf(m0 - mx), e1 = expf(m1 - mx);
    float b0 = e0 / (e0 + e1), b1 = e1 / (e0 + e1);
    size_t i = (size_t)blockIdx.x * 256 + threadIdx.x;
    if (i >= (size_t)N_NODES * OUTF) return;
    out[i] = b0 * g_y[0][i] + b1 * g_y[1][i];
}

// ---------------- launch ----------------
extern "C" void kernel_launch(void* const* d_in, const int* in_sizes, int n_in,
                              void* d_out, int out_size) {
    const float* ent   = (const float*)d_in[0];
    const float* rel   = (const float*)d_in[1];
    const int*   el    = (const int*)d_in[2];
    const int*   et    = (const int*)d_in[3];
    const float* eemb  = (const float*)d_in[4];
    const int*   eln   = (const int*)d_in[5];
    const int*   etn   = (const int*)d_in[6];
    const float* a_in  = (const float*)d_in[7];
    const float* a2_in = (const float*)d_in[8];
    const float* a_out = (const float*)d_in[9];
    const float* a2_out= (const float*)d_in[10];
    const float* a_o   = (const float*)d_in[11];
    const float* a2_o  = (const float*)d_in[12];
    const float* W     = (const float*)d_in[13];
    const float* We    = (const float*)d_in[14];
    const float* be    = (const float*)d_in[15];
    const float* qe    = (const float*)d_in[16];
    float* out = (float*)d_out;

    float *p1 = 0, *p2 = 0, *wp1 = 0;
    float *a2c1 = 0, *a2c2 = 0, *s1 = 0, *s2 = 0;
    cudaGetSymbolAddress((void**)&p1, g_P1all);
    cudaGetSymbolAddress((void**)&p2, g_P2all);
    cudaGetSymbolAddress((void**)&wp1, g_Wp1);
    cudaGetSymbolAddress((void**)&a2c1, g_a2cat1);
    cudaGetSymbolAddress((void**)&a2c2, g_a2cat2);
    cudaGetSymbolAddress((void**)&s1, g_S1);
    cudaGetSymbolAddress((void**)&s2, g_S2);

    setup<<<725, 256>>>(a_in, a_out, a_o, a2_in, a2_out, a2_o, rel, W, We, out);

    // layer-1 node projections (P1 + S1)
    gemm_f32x2<<<dim3((N_NODES + 127) / 128, 4), 256>>>(ent, wp1, p1, a2c1, s1,
                                                        N_NODES, 512, 64);
    // Q projection with fused real-edge pass
    gemm_q<<<dim3((E_REAL + 127) / 128, 2), 256>>>(eemb, el);
    // nhop edges
    edge_pass1n<<<dim3(E_NHOP / 8, 2), 256>>>(eln, etn);

    // layer-2 projections with fused norm1 (xs never materialized)
    gemm_x2<<<dim3((2 * N_NODES + 127) / 128, 2), 256>>>(p2, a2c2, s2);

    edge_pass2<<<dim3(E_ALL / 8, 2), 256>>>(el, eln, et, etn);

    gemm_we<<<(2 * N_NODES + 127) / 128, 256>>>(be, qe);
    combine<<<(N_NODES * OUTF + 255) / 256, 256>>>(out);
}

// round 14
// speedup vs baseline: 1.1713x; 1.0004x over previous
#include <cuda_runtime.h>
#include <math.h>

#define N_NODES 50000
#define NFEAT   64
#define NHID    64
#define E_REAL  200000
#define E_NHOP  40000
#define E_ALL   240000
#define N_REL   200
#define OUTF    128
#define ALPHA   0.2f
#define QBLK    1563   // (E_REAL+127)/128

typedef unsigned long long ull;

// ---------------- device scratch ----------------
__device__ __align__(16) float g_P1all[(size_t)N_NODES * 512];     // [i][dir*256+role*128+h*64+j]
__device__ __align__(16) float g_R1proj[N_REL * 256];              // [r*256 + c*64 + j]
__device__ __align__(16) float g_R2proj[N_REL * OUTF];
__device__ __align__(16) float g_rowsum1T[(size_t)N_NODES * 4];    // [i*4 + dir*2 + h]
__device__ __align__(16) float g_hp1[2][(size_t)N_NODES * 128];
__device__ __align__(16) float g_P2all[2][(size_t)N_NODES * 256];
__device__ float g_rowsum2[2][N_NODES];
__device__ __align__(16) float g_hp2[2][(size_t)N_NODES * OUTF];
__device__ __align__(16) float g_y[2][(size_t)N_NODES * OUTF];
__device__ float g_wsum[2];
// packed weights (row-major [n][K])
__device__ __align__(16) float g_Wp1[512 * 64];
__device__ __align__(16) float g_WpQ[256 * 64];
__device__ __align__(16) float g_Wp2[256 * 128];
__device__ __align__(16) float g_WeP[64 * 128];                    // [j][k]
// factorized attention scalars
__device__ __align__(16) float g_S1[(size_t)N_NODES * 8];          // [i*8 + dir*4 + role*2 + h]
__device__ __align__(16) float g_Sr1[N_REL * 4];
__device__ __align__(16) float g_S2[2][(size_t)N_NODES * 4];
__device__ float g_Srel2[N_REL];
// per-column dot weights
__device__ __align__(16) float g_a2cat1[512];
__device__ __align__(16) float g_a2catQ[256];
__device__ __align__(16) float g_a2cat2[256];

#define RED2(ptr, a, b) \
    asm volatile("red.global.add.v2.f32 [%0], {%1, %2};" :: "l"(ptr), "f"(a), "f"(b) : "memory")
#define RED4(ptr, a, b, c, d) \
    asm volatile("red.global.add.v4.f32 [%0], {%1, %2, %3, %4};" :: "l"(ptr), "f"(a), "f"(b), "f"(c), "f"(d) : "memory")

// ---------------- setupA: weight packing (13 blocks, main stream) ----------------
__global__ void setupA(const float* __restrict__ a_in, const float* __restrict__ a_out,
                       const float* __restrict__ a_o,
                       const float* __restrict__ a2_in, const float* __restrict__ a2_out,
                       const float* __restrict__ a2_o, const float* __restrict__ We) {
    int b = blockIdx.x, t = threadIdx.x;
    if (b < 4) {
        for (int idx = b * 256 + t; idx < 512 * 64; idx += 4 * 256) {
            int n = idx >> 6, k = idx & 63;
            int dir = n >> 8, role = (n >> 7) & 1, h = (n >> 6) & 1, j = n & 63;
            const float* A = (dir ? a_out : a_in) + (size_t)h * 64 * 192;
            g_Wp1[idx] = A[j * 192 + role * 64 + k];
        }
    } else if (b < 6) {
        for (int idx = (b - 4) * 256 + t; idx < 256 * 64; idx += 2 * 256) {
            int n = idx >> 6, k = idx & 63;
            int c = n >> 6, j = n & 63;
            const float* A = ((c >> 1) ? a_out : a_in) + (size_t)(c & 1) * 64 * 192;
            g_WpQ[idx] = A[j * 192 + 128 + k];
        }
    } else if (b < 10) {
        for (int idx = (b - 6) * 256 + t; idx < 256 * 128; idx += 4 * 256) {
            int n = idx >> 7, k = idx & 127;
            int role = n >> 7, j = n & 127;
            g_Wp2[idx] = a_o[j * 384 + role * 128 + k];
        }
    } else if (b < 12) {
        for (int idx = (b - 10) * 256 + t; idx < 64 * 128; idx += 2 * 256) {
            int j = idx >> 7, k = idx & 127;
            g_WeP[idx] = We[k * 64 + j];
        }
    } else {
        for (int n = t; n < 512; n += 256) {
            int dir = n >> 8, h = (n >> 6) & 1, j = n & 63;
            g_a2cat1[n] = (dir ? a2_out : a2_in)[h * 64 + j];
        }
        for (int n = t; n < 256; n += 256) {
            int c = n >> 6, j = n & 63;
            g_a2catQ[n] = ((c >> 1) ? a2_out : a2_in)[(c & 1) * 64 + j];
        }
        if (t < 256) g_a2cat2[t] = a2_o[t & 127];
    }
}

// ---------------- setupB: zero accumulators + relation tables (parallel stream) ------
__global__ void setupB(const float* __restrict__ a_in, const float* __restrict__ a_out,
                       const float* __restrict__ a_o,
                       const float* __restrict__ a2_in, const float* __restrict__ a2_out,
                       const float* __restrict__ a2_o,
                       const float* __restrict__ rel, const float* __restrict__ W,
                       float* __restrict__ out_tail) {
    int b = blockIdx.x, t = threadIdx.x;
    if (b < 512) {
        size_t tid = (size_t)b * 256 + t, stride = (size_t)512 * 256;
        float4 z = make_float4(0.f, 0.f, 0.f, 0.f);
        float4* hp1 = (float4*)&g_hp1[0][0];
        for (size_t i = tid; i < (size_t)2 * N_NODES * 32; i += stride) hp1[i] = z;
        float4* hp2 = (float4*)&g_hp2[0][0];
        for (size_t i = tid; i < (size_t)2 * N_NODES * 32; i += stride) hp2[i] = z;
        float4* rs1 = (float4*)&g_rowsum1T[0];
        for (size_t i = tid; i < (size_t)N_NODES; i += stride) rs1[i] = z;
        float4* rs2 = (float4*)&g_rowsum2[0][0];
        for (size_t i = tid; i < (size_t)N_NODES / 2; i += stride) rs2[i] = z;
        if (tid < 2) g_wsum[tid] = 0.f;
    } else {
        int r = b - 512;  // [0, 200)
        __shared__ float relrow[64];
        __shared__ float rel2row[128];
        __shared__ float red[8];
        if (t < 64) relrow[t] = rel[r * 64 + t];
        __syncthreads();
        if (t < 128) {
            float acc = 0.f;
            #pragma unroll
            for (int k = 0; k < 64; k++) acc += relrow[k] * W[k * 128 + t];
            rel2row[t] = acc;
            out_tail[(size_t)N_NODES * OUTF + r * 128 + t] = acc;
        }
        __syncthreads();
        {
            int c = t >> 6, j = t & 63;
            const float* A = ((c >> 1) ? a_out : a_in) + (size_t)(c & 1) * 64 * 192;
            float acc = 0.f;
            #pragma unroll
            for (int k = 0; k < 64; k++) acc += relrow[k] * A[j * 192 + 128 + k];
            g_R1proj[r * 256 + t] = acc;
            float part = acc * ((c >> 1) ? a2_out : a2_in)[(c & 1) * 64 + j];
            #pragma unroll
            for (int o = 16; o; o >>= 1) part += __shfl_xor_sync(0xffffffffu, part, o);
            if ((t & 31) == 0) red[t >> 5] = part;
        }
        __syncthreads();
        if (t < 4) g_Sr1[r * 4 + t] = red[2 * t] + red[2 * t + 1];
        __syncthreads();
        {
            float part = 0.f;
            if (t < 128) {
                float acc = 0.f;
                #pragma unroll 16
                for (int k = 0; k < 128; k++) acc += rel2row[k] * a_o[t * 384 + 256 + k];
                g_R2proj[r * 128 + t] = acc;
                part = acc * a2_o[t];
            }
            #pragma unroll
            for (int o = 16; o; o >>= 1) part += __shfl_xor_sync(0xffffffffu, part, o);
            if ((t & 31) == 0 && t < 128) red[t >> 5] = part;
        }
        __syncthreads();
        if (t == 0) g_Srel2[r] = red[0] + red[1] + red[2] + red[3];
    }
}

// ---------------- f32x2 GEMM (projection variant, register prefetch) ----------------
#define KC 16
__global__ void __launch_bounds__(256, 2)
gemm_f32x2(const float* __restrict__ X,
           const float* __restrict__ Wp,
           float* __restrict__ C,
           const float* __restrict__ a2cat,
           float* __restrict__ sOut,
           int M, int N, int K) {
    __shared__ __align__(16) float2 Xs2[KC][130];
    __shared__ __align__(16) float  As[KC][132];
    int t = threadIdx.x;
    int tx = t & 15, ty = t >> 4;
    int ib = blockIdx.x * 128;
    int jb = blockIdx.y * 128;
    ull acc[8][4];
    #pragma unroll
    for (int ii = 0; ii < 8; ii++)
        #pragma unroll
        for (int q = 0; q < 4; q++) acc[ii][q] = 0ull;

    float4 xb[2], ab[2];
    int pi0 = t & 127, pk0 = (t >> 7) * 4;
    int pk1 = pk0 + 8;
    {
        int gi = ib + pi0;
        xb[0] = make_float4(0.f, 0.f, 0.f, 0.f);
        xb[1] = make_float4(0.f, 0.f, 0.f, 0.f);
        if (gi < M) {
            xb[0] = *(const float4*)&X[(size_t)gi * K + pk0];
            xb[1] = *(const float4*)&X[(size_t)gi * K + pk1];
        }
        ab[0] = *(const float4*)&Wp[(size_t)(jb + pi0) * K + pk0];
        ab[1] = *(const float4*)&Wp[(size_t)(jb + pi0) * K + pk1];
    }

    for (int kc = 0; kc < K; kc += KC) {
        #pragma unroll
        for (int u = 0; u < 2; u++) {
            int kq = u ? pk1 : pk0;
            float4 v = xb[u];
            Xs2[kq + 0][pi0] = make_float2(v.x, v.x);
            Xs2[kq + 1][pi0] = make_float2(v.y, v.y);
            Xs2[kq + 2][pi0] = make_float2(v.z, v.z);
            Xs2[kq + 3][pi0] = make_float2(v.w, v.w);
            float4 a = ab[u];
            As[kq + 0][pi0] = a.x; As[kq + 1][pi0] = a.y;
            As[kq + 2][pi0] = a.z; As[kq + 3][pi0] = a.w;
        }
        __syncthreads();
        if (kc + KC < K) {
            int gi = ib + pi0;
            xb[0] = make_float4(0.f, 0.f, 0.f, 0.f);
            xb[1] = make_float4(0.f, 0.f, 0.f, 0.f);
            if (gi < M) {
                xb[0] = *(const float4*)&X[(size_t)gi * K + kc + KC + pk0];
                xb[1] = *(const float4*)&X[(size_t)gi * K + kc + KC + pk1];
            }
            ab[0] = *(const float4*)&Wp[(size_t)(jb + pi0) * K + kc + KC + pk0];
            ab[1] = *(const float4*)&Wp[(size_t)(jb + pi0) * K + kc + KC + pk1];
        }
        #pragma unroll
        for (int kk = 0; kk < KC; kk++) {
            ull av[4];
            #pragma unroll
            for (int q = 0; q < 4; q++)
                av[q] = *(const ull*)&As[kk][2 * (tx + 16 * q)];
            #pragma unroll
            for (int ii = 0; ii < 8; ii++) {
                ull xx = *(const ull*)&Xs2[kk][ty * 8 + ii];
                #pragma unroll
                for (int q = 0; q < 4; q++)
                    asm("fma.rn.f32x2 %0, %1, %2, %0;"
                        : "+l"(acc[ii][q]) : "l"(xx), "l"(av[q]));
            }
        }
        __syncthreads();
    }
    int nBlk = N >> 6;
    float2 w[4];
    #pragma unroll
    for (int q = 0; q < 4; q++)
        w[q] = *(const float2*)&a2cat[jb + 2 * (tx + 16 * q)];
    #pragma unroll
    for (int ii = 0; ii < 8; ii++) {
        int gi = ib + ty * 8 + ii;
        float lo[4], hi[4];
        #pragma unroll
        for (int q = 0; q < 4; q++)
            asm("mov.b64 {%0, %1}, %2;" : "=f"(lo[q]), "=f"(hi[q]) : "l"(acc[ii][q]));
        if (gi < M) {
            #pragma unroll
            for (int q = 0; q < 4; q++)
                *(float2*)&C[(size_t)gi * N + jb + 2 * (tx + 16 * q)] = make_float2(lo[q], hi[q]);
        }
        float s0 = lo[0] * w[0].x + hi[0] * w[0].y + lo[1] * w[1].x + hi[1] * w[1].y;
        float s1 = lo[2] * w[2].x + hi[2] * w[2].y + lo[3] * w[3].x + hi[3] * w[3].y;
        #pragma unroll
        for (int o = 8; o; o >>= 1) {
            s0 += __shfl_xor_sync(0xffffffffu, s0, o);
            s1 += __shfl_xor_sync(0xffffffffu, s1, o);
        }
        if (tx == 0 && gi < M) {
            size_t base = (size_t)gi * nBlk + (jb >> 6);
            sOut[base] = s0;
            sOut[base + 1] = s1;
        }
    }
}

// ---------------- gemm_x2: layer-2 projection with FUSED norm1 in the X loader ------
__global__ void __launch_bounds__(256, 2)
gemm_x2(float* __restrict__ C, const float* __restrict__ a2cat,
        float* __restrict__ sOut) {
    __shared__ __align__(16) float2 Xs2[KC][130];
    __shared__ __align__(16) float  As[KC][132];
    int t = threadIdx.x;
    int tx = t & 15, ty = t >> 4;
    int ib = blockIdx.x * 128;
    int jb = blockIdx.y * 128;
    const int M = 2 * N_NODES, N = 256, K = 128;
    ull acc[8][4];
    #pragma unroll
    for (int ii = 0; ii < 8; ii++)
        #pragma unroll
        for (int q = 0; q < 4; q++) acc[ii][q] = 0ull;

    for (int kc = 0; kc < K; kc += KC) {
        #pragma unroll
        for (int p = t; p < 512; p += 256) {
            int i = p & 127, kq = (p >> 7) * 4;
            int gi = ib + i;
            float4 v = make_float4(0.f, 0.f, 0.f, 0.f);
            if (gi < M) {
                int dir = gi >= N_NODES;
                int i2 = dir ? gi - N_NODES : gi;
                int kk = kc + kq;
                float rs = g_rowsum1T[(size_t)i2 * 4 + dir * 2 + (kk >> 6)];
                if (rs > 0.f) {
                    float inv = 1.f / rs;
                    float4 hv = *(const float4*)&g_hp1[dir][(size_t)i2 * 128 + kk];
                    float4 pv = *(const float4*)&g_P1all[(size_t)i2 * 512 + dir * 256 + kk];
                    v.x = hv.x * inv + pv.x;
                    v.y = hv.y * inv + pv.y;
                    v.z = hv.z * inv + pv.z;
                    v.w = hv.w * inv + pv.w;
                }
                v.x = (v.x > 0.f) ? v.x : expm1f(v.x);
                v.y = (v.y > 0.f) ? v.y : expm1f(v.y);
                v.z = (v.z > 0.f) ? v.z : expm1f(v.z);
                v.w = (v.w > 0.f) ? v.w : expm1f(v.w);
            }
            Xs2[kq + 0][i] = make_float2(v.x, v.x);
            Xs2[kq + 1][i] = make_float2(v.y, v.y);
            Xs2[kq + 2][i] = make_float2(v.z, v.z);
            Xs2[kq + 3][i] = make_float2(v.w, v.w);
        }
        #pragma unroll
        for (int p = t; p < 512; p += 256) {
            int j = p & 127, kq = (p >> 7) * 4;
            float4 v = *(const float4*)&g_Wp2[(size_t)(jb + j) * K + kc + kq];
            As[kq + 0][j] = v.x; As[kq + 1][j] = v.y;
            As[kq + 2][j] = v.z; As[kq + 3][j] = v.w;
        }
        __syncthreads();
        #pragma unroll
        for (int kk = 0; kk < KC; kk++) {
            ull av[4];
            #pragma unroll
            for (int q = 0; q < 4; q++)
                av[q] = *(const ull*)&As[kk][2 * (tx + 16 * q)];
            #pragma unroll
            for (int ii = 0; ii < 8; ii++) {
                ull xx = *(const ull*)&Xs2[kk][ty * 8 + ii];
                #pragma unroll
                for (int q = 0; q < 4; q++)
                    asm("fma.rn.f32x2 %0, %1, %2, %0;"
                        : "+l"(acc[ii][q]) : "l"(xx), "l"(av[q]));
            }
        }
        __syncthreads();
    }
    int nBlk = N >> 6;
    float2 w[4];
    #pragma unroll
    for (int q = 0; q < 4; q++)
        w[q] = *(const float2*)&a2cat[jb + 2 * (tx + 16 * q)];
    #pragma unroll
    for (int ii = 0; ii < 8; ii++) {
        int gi = ib + ty * 8 + ii;
        float lo[4], hi[4];
        #pragma unroll
        for (int q = 0; q < 4; q++)
            asm("mov.b64 {%0, %1}, %2;" : "=f"(lo[q]), "=f"(hi[q]) : "l"(acc[ii][q]));
        if (gi < M) {
            #pragma unroll
            for (int q = 0; q < 4; q++)
                *(float2*)&C[(size_t)gi * N + jb + 2 * (tx + 16 * q)] = make_float2(lo[q], hi[q]);
        }
        float s0 = lo[0] * w[0].x + hi[0] * w[0].y + lo[1] * w[1].x + hi[1] * w[1].y;
        float s1 = lo[2] * w[2].x + hi[2] * w[2].y + lo[3] * w[3].x + hi[3] * w[3].y;
        #pragma unroll
        for (int o = 8; o; o >>= 1) {
            s0 += __shfl_xor_sync(0xffffffffu, s0, o);
            s1 += __shfl_xor_sync(0xffffffffu, s1, o);
        }
        if (tx == 0 && gi < M) {
            size_t base = (size_t)gi * nBlk + (jb >> 6);
            sOut[base] = s0;
            sOut[base + 1] = s1;
        }
    }
}

// ---------------- gemm_q: Q projection + fused real-edge pass + nhop tail blocks ----
__global__ void __launch_bounds__(256, 2)
gemm_q(const float* __restrict__ X, const int* __restrict__ el,
       const int* __restrict__ eln, const int* __restrict__ etn) {
    __shared__ __align__(16) float2 Xs2[KC][130];
    __shared__ __align__(16) float  As[KC][132];
    int t = threadIdx.x;
    int dir = blockIdx.y;

    if (blockIdx.x >= QBLK) {
        // ---- nhop edge pass (former edge_pass1n) ----
        int e = (blockIdx.x - QBLK) * 8 + (t >> 5);   // [0, E_NHOP)
        int lane = t & 31;
        int h = lane >> 4;
        int jj = 4 * (lane & 15);
        int i0 = eln[e], i1 = eln[E_NHOP + e];
        int t0 = etn[2 * e], t1 = etn[2 * e + 1];
        float4 qa = *(const float4*)&g_R1proj[t0 * 256 + dir * 128 + h * 64 + jj];
        float4 qb = *(const float4*)&g_R1proj[t1 * 256 + dir * 128 + h * 64 + jj];
        float4 q;
        q.x = qa.x + qb.x; q.y = qa.y + qb.y; q.z = qa.z + qb.z; q.w = qa.w + qb.w;
        float sq = g_Sr1[t0 * 4 + dir * 2 + h] + g_Sr1[t1 * 4 + dir * 2 + h];
        int src = dir ? i1 : i0;
        int dst = dir ? i0 : i1;
        float score = g_S1[(size_t)src * 8 + dir * 4 + h]
                    + g_S1[(size_t)dst * 8 + dir * 4 + 2 + h] + sq;
        float lk = score > 0.f ? score : ALPHA * score;
        float ev = __expf(-lk);
        float4 d = *(const float4*)&g_P1all[(size_t)dst * 512 + dir * 256 + 128 + h * 64 + jj];
        float* hp = &g_hp1[dir][(size_t)src * 128 + h * 64 + jj];
        RED4(hp, ev * (d.x + q.x), ev * (d.y + q.y), ev * (d.z + q.z), ev * (d.w + q.w));
        if ((lane & 15) == 0) atomicAdd(&g_rowsum1T[(size_t)src * 4 + dir * 2 + h], ev);
        return;
    }

    int tx = t & 15, ty = t >> 4;
    int ib = blockIdx.x * 128;
    int jb = dir * 128;
    const int M = E_REAL, K = 64;
    ull acc[8][4];
    #pragma unroll
    for (int ii = 0; ii < 8; ii++)
        #pragma unroll
        for (int q = 0; q < 4; q++) acc[ii][q] = 0ull;

    float4 xb[2], ab[2];
    int pi0 = t & 127, pk0 = (t >> 7) * 4;
    int pk1 = pk0 + 8;
    {
        int gi = ib + pi0;
        xb[0] = make_float4(0.f, 0.f, 0.f, 0.f);
        xb[1] = make_float4(0.f, 0.f, 0.f, 0.f);
        if (gi < M) {
            xb[0] = *(const float4*)&X[(size_t)gi * K + pk0];
            xb[1] = *(const float4*)&X[(size_t)gi * K + pk1];
        }
        ab[0] = *(const float4*)&g_WpQ[(size_t)(jb + pi0) * K + pk0];
        ab[1] = *(const float4*)&g_WpQ[(size_t)(jb + pi0) * K + pk1];
    }

    for (int kc = 0; kc < K; kc += KC) {
        #pragma unroll
        for (int u = 0; u < 2; u++) {
            int kq = u ? pk1 : pk0;
            float4 v = xb[u];
            Xs2[kq + 0][pi0] = make_float2(v.x, v.x);
            Xs2[kq + 1][pi0] = make_float2(v.y, v.y);
            Xs2[kq + 2][pi0] = make_float2(v.z, v.z);
            Xs2[kq + 3][pi0] = make_float2(v.w, v.w);
            float4 a = ab[u];
            As[kq + 0][pi0] = a.x; As[kq + 1][pi0] = a.y;
            As[kq + 2][pi0] = a.z; As[kq + 3][pi0] = a.w;
        }
        __syncthreads();
        if (kc + KC < K) {
            int gi = ib + pi0;
            xb[0] = make_float4(0.f, 0.f, 0.f, 0.f);
            xb[1] = make_float4(0.f, 0.f, 0.f, 0.f);
            if (gi < M) {
                xb[0] = *(const float4*)&X[(size_t)gi * K + kc + KC + pk0];
                xb[1] = *(const float4*)&X[(size_t)gi * K + kc + KC + pk1];
            }
            ab[0] = *(const float4*)&g_WpQ[(size_t)(jb + pi0) * K + kc + KC + pk0];
            ab[1] = *(const float4*)&g_WpQ[(size_t)(jb + pi0) * K + kc + KC + pk1];
        }
        #pragma unroll
        for (int kk = 0; kk < KC; kk++) {
            ull av[4];
            #pragma unroll
            for (int q = 0; q < 4; q++)
                av[q] = *(const ull*)&As[kk][2 * (tx + 16 * q)];
            #pragma unroll
            for (int ii = 0; ii < 8; ii++) {
                ull xx = *(const ull*)&Xs2[kk][ty * 8 + ii];
                #pragma unroll
                for (int q = 0; q < 4; q++)
                    asm("fma.rn.f32x2 %0, %1, %2, %0;"
                        : "+l"(acc[ii][q]) : "l"(xx), "l"(av[q]));
            }
        }
        __syncthreads();
    }
    float2 w[4];
    #pragma unroll
    for (int q = 0; q < 4; q++)
        w[q] = *(const float2*)&g_a2catQ[jb + 2 * (tx + 16 * q)];
    #pragma unroll
    for (int ii = 0; ii < 8; ii++) {
        int gi = ib + ty * 8 + ii;   // edge index
        float lo[4], hi[4];
        #pragma unroll
        for (int q = 0; q < 4; q++)
            asm("mov.b64 {%0, %1}, %2;" : "=f"(lo[q]), "=f"(hi[q]) : "l"(acc[ii][q]));
        float s0 = lo[0] * w[0].x + hi[0] * w[0].y + lo[1] * w[1].x + hi[1] * w[1].y;
        float s1 = lo[2] * w[2].x + hi[2] * w[2].y + lo[3] * w[3].x + hi[3] * w[3].y;
        #pragma unroll
        for (int o = 8; o; o >>= 1) {
            s0 += __shfl_xor_sync(0xffffffffu, s0, o);
            s1 += __shfl_xor_sync(0xffffffffu, s1, o);
        }
        if (gi < M) {
            int i0 = el[gi], i1 = el[E_REAL + gi];
            int src = dir ? i1 : i0;
            int dst = dir ? i0 : i1;
            float4 sv = *(const float4*)&g_S1[(size_t)src * 8 + dir * 4];
            float4 dv = *(const float4*)&g_S1[(size_t)dst * 8 + dir * 4];
            float sc0 = sv.x + dv.z + s0;
            float sc1 = sv.y + dv.w + s1;
            float lk0 = sc0 > 0.f ? sc0 : ALPHA * sc0;
            float lk1 = sc1 > 0.f ? sc1 : ALPHA * sc1;
            float ev0 = __expf(-lk0);
            float ev1 = __expf(-lk1);
            const float* pd = &g_P1all[(size_t)dst * 512 + dir * 256 + 128];
            float* hp = &g_hp1[dir][(size_t)src * 128];
            #pragma unroll
            for (int q = 0; q < 4; q++) {
                int col = 2 * (tx + 16 * q);
                float ev = (q < 2) ? ev0 : ev1;
                float2 d = *(const float2*)&pd[col];
                RED2(&hp[col], ev * (d.x + lo[q]), ev * (d.y + hi[q]));
            }
            if (tx == 0) {
                atomicAdd(&g_rowsum1T[(size_t)src * 4 + dir * 2], ev0);
                atomicAdd(&g_rowsum1T[(size_t)src * 4 + dir * 2 + 1], ev1);
            }
        }
    }
}

// ---------------- gemm_we: norm2 fused into loader + tanh-dot epilogue ----------------
__global__ void __launch_bounds__(256, 2)
gemm_we(const float* __restrict__ be, const float* __restrict__ qe) {
    __shared__ __align__(16) float2 Xs2[KC][130];
    __shared__ __align__(16) float  As[KC][68];
    __shared__ float s_sh[2];
    int t = threadIdx.x;
    int tx = t & 7, ty = t >> 3;
    int lane = t & 31;
    int ib = blockIdx.x * 128;
    const int M = 2 * N_NODES;
    if (t < 2) s_sh[t] = 0.f;
    const float* hp2f = &g_hp2[0][0];
    const float* rs2f = &g_rowsum2[0][0];
    float* yf = &g_y[0][0];
    ull acc[4][4];
    #pragma unroll
    for (int ii = 0; ii < 4; ii++)
        #pragma unroll
        for (int q = 0; q < 4; q++) acc[ii][q] = 0ull;

    for (int kc = 0; kc < 128; kc += KC) {
        #pragma unroll
        for (int p = t; p < 512; p += 256) {
            int i = p & 127, kq = (p >> 7) * 4;
            int gi = ib + i;
            float4 v = make_float4(0.f, 0.f, 0.f, 0.f);
            if (gi < M) {
                int xs = gi >= N_NODES;
                int ii2 = xs ? gi - N_NODES : gi;
                float rs = rs2f[gi];
                if (rs > 0.f) {
                    float inv = 1.f / rs;
                    float4 hv = *(const float4*)&hp2f[(size_t)gi * 128 + kc + kq];
                    float4 pv = *(const float4*)&g_P2all[xs][(size_t)ii2 * 256 + kc + kq];
                    v.x = hv.x * inv + pv.x;
                    v.y = hv.y * inv + pv.y;
                    v.z = hv.z * inv + pv.z;
                    v.w = hv.w * inv + pv.w;
                }
                v.x = (v.x > 0.f) ? v.x : expm1f(v.x);
                v.y = (v.y > 0.f) ? v.y : expm1f(v.y);
                v.z = (v.z > 0.f) ? v.z : expm1f(v.z);
                v.w = (v.w > 0.f) ? v.w : expm1f(v.w);
                *(float4*)&yf[(size_t)gi * 128 + kc + kq] = v;
            }
            Xs2[kq + 0][i] = make_float2(v.x, v.x);
            Xs2[kq + 1][i] = make_float2(v.y, v.y);
            Xs2[kq + 2][i] = make_float2(v.z, v.z);
            Xs2[kq + 3][i] = make_float2(v.w, v.w);
        }
        {
            int j = t & 63, kq = ((t >> 6) & 3) * 4;
            float4 w = *(const float4*)&g_WeP[j * 128 + kc + kq];
            As[kq + 0][j] = w.x; As[kq + 1][j] = w.y;
            As[kq + 2][j] = w.z; As[kq + 3][j] = w.w;
        }
        __syncthreads();
        #pragma unroll
        for (int kk = 0; kk < KC; kk++) {
            ull av[4];
            #pragma unroll
            for (int q = 0; q < 4; q++)
                av[q] = *(const ull*)&As[kk][2 * (tx + 8 * q)];
            #pragma unroll
            for (int ii = 0; ii < 4; ii++) {
                ull xx = *(const ull*)&Xs2[kk][ty * 4 + ii];
                #pragma unroll
                for (int q = 0; q < 4; q++)
                    asm("fma.rn.f32x2 %0, %1, %2, %0;"
                        : "+l"(acc[ii][q]) : "l"(xx), "l"(av[q]));
            }
        }
        __syncthreads();
    }
    float2 bb[4], qq[4];
    #pragma unroll
    for (int q = 0; q < 4; q++) {
        bb[q] = *(const float2*)&be[2 * (tx + 8 * q)];
        qq[q] = *(const float2*)&qe[2 * (tx + 8 * q)];
    }
    #pragma unroll
    for (int ii = 0; ii < 4; ii++) {
        int gi = ib + ty * 4 + ii;
        float lo[4], hi[4];
        #pragma unroll
        for (int q = 0; q < 4; q++)
            asm("mov.b64 {%0, %1}, %2;" : "=f"(lo[q]), "=f"(hi[q]) : "l"(acc[ii][q]));
        float s = 0.f;
        #pragma unroll
        for (int q = 0; q < 4; q++)
            s += tanhf(lo[q] + bb[q].x) * qq[q].x + tanhf(hi[q] + bb[q].y) * qq[q].y;
        #pragma unroll
        for (int o = 4; o; o >>= 1) s += __shfl_xor_sync(0xffffffffu, s, o);
        if ((lane & 7) == 0 && gi < M)
            atomicAdd(&s_sh[gi >= N_NODES], s);
    }
    __syncthreads();
    if (t < 2) atomicAdd(&g_wsum[t], s_sh[t]);
}

// ---------------- layer-2 edge pass ----------------
__global__ void edge_pass2(const int* __restrict__ el, const int* __restrict__ eln,
                           const int* __restrict__ et, const int* __restrict__ etn) {
    int dir = blockIdx.y;
    int e = blockIdx.x * 8 + (threadIdx.x >> 5);
    if (e >= E_ALL) return;
    int lane = threadIdx.x & 31;
    int i0, i1;
    float q0, q1, q2, q3, sq;
    if (e < E_REAL) {
        i0 = el[e]; i1 = el[E_REAL + e];
        int ty = et[e];
        float4 qv = *(const float4*)&g_R2proj[ty * 128 + 4 * lane];
        q0 = qv.x; q1 = qv.y; q2 = qv.z; q3 = qv.w;
        sq = g_Srel2[ty];
    } else {
        int en = e - E_REAL;
        i0 = eln[en]; i1 = eln[E_NHOP + en];
        int t0 = etn[2 * en], t1 = etn[2 * en + 1];
        float4 qa = *(const float4*)&g_R2proj[t0 * 128 + 4 * lane];
        float4 qb = *(const float4*)&g_R2proj[t1 * 128 + 4 * lane];
        q0 = qa.x + qb.x; q1 = qa.y + qb.y; q2 = qa.z + qb.z; q3 = qa.w + qb.w;
        sq = g_Srel2[t0] + g_Srel2[t1];
    }
    int seg = dir ? i1 : i0;
    int nbr = dir ? i0 : i1;
    float4 sA = *(const float4*)&g_S2[dir][(size_t)seg * 4];
    float4 sB = *(const float4*)&g_S2[dir][(size_t)nbr * 4];
    float score = sA.x + sA.y + sB.z + sB.w + sq;
    float lk = score > 0.f ? score : ALPHA * score;
    float ev = __expf(-lk);
    float4 dv = *(const float4*)&g_P2all[dir][(size_t)nbr * 256 + 128 + 4 * lane];
    float* hp = &g_hp2[dir][(size_t)seg * 128 + 4 * lane];
    RED4(hp, ev * (dv.x + q0), ev * (dv.y + q1), ev * (dv.z + q2), ev * (dv.w + q3));
    if (lane == 0) atomicAdd(&g_rowsum2[dir][seg], ev);
}

// ---------------- beta + combine ----------------
__global__ void combine(float* __restrict__ out) {
    float m0 = g_wsum[0] / (float)N_NODES;
    float m1 = g_wsum[1] / (float)N_NODES;
    float mx = fmaxf(m0, m1);
    float e0 = expf(m0 - mx), e1 = expf(m1 - mx);
    float b0 = e0 / (e0 + e1), b1 = e1 / (e0 + e1);
    size_t i = (size_t)blockIdx.x * 256 + threadIdx.x;
    if (i >= (size_t)N_NODES * OUTF) return;
    out[i] = b0 * g_y[0][i] + b1 * g_y[1][i];
}

// ---------------- launch ----------------
extern "C" void kernel_launch(void* const* d_in, const int* in_sizes, int n_in,
                              void* d_out, int out_size) {
    const float* ent   = (const float*)d_in[0];
    const float* rel   = (const float*)d_in[1];
    const int*   el    = (const int*)d_in[2];
    const int*   et    = (const int*)d_in[3];
    const float* eemb  = (const float*)d_in[4];
    const int*   eln   = (const int*)d_in[5];
    const int*   etn   = (const int*)d_in[6];
    const float* a_in  = (const float*)d_in[7];
    const float* a2_in = (const float*)d_in[8];
    const float* a_out = (const float*)d_in[9];
    const float* a2_out= (const float*)d_in[10];
    const float* a_o   = (const float*)d_in[11];
    const float* a2_o  = (const float*)d_in[12];
    const float* W     = (const float*)d_in[13];
    const float* We    = (const float*)d_in[14];
    const float* be    = (const float*)d_in[15];
    const float* qe    = (const float*)d_in[16];
    float* out = (float*)d_out;

    float *p1 = 0, *p2 = 0, *wp1 = 0;
    float *a2c1 = 0, *a2c2 = 0, *s1 = 0, *s2 = 0;
    cudaGetSymbolAddress((void**)&p1, g_P1all);
    cudaGetSymbolAddress((void**)&p2, g_P2all);
    cudaGetSymbolAddress((void**)&wp1, g_Wp1);
    cudaGetSymbolAddress((void**)&a2c1, g_a2cat1);
    cudaGetSymbolAddress((void**)&a2c2, g_a2cat2);
    cudaGetSymbolAddress((void**)&s1, g_S1);
    cudaGetSymbolAddress((void**)&s2, g_S2);

    // fork-join: setupB (zero + relation tables) runs concurrently with
    // setupA -> P1 GEMM on the main stream. Streams/events are created per
    // call; kernel_launch only runs for correctness + capture, so the few
    // leaked handles are harmless (no device memory involved).
    cudaStream_t sB;
    cudaStreamCreateWithFlags(&sB, cudaStreamNonBlocking);
    cudaEvent_t evFork, evJoin;
    cudaEventCreateWithFlags(&evFork, cudaEventDisableTiming);
    cudaEventCreateWithFlags(&evJoin, cudaEventDisableTiming);

    cudaEventRecord(evFork, 0);
    cudaStreamWaitEvent(sB, evFork, 0);
    setupB<<<712, 256, 0, sB>>>(a_in, a_out, a_o, a2_in, a2_out, a2_o, rel, W, out);
    cudaEventRecord(evJoin, sB);

    setupA<<<13, 256>>>(a_in, a_out, a_o, a2_in, a2_out, a2_o, We);
    // layer-1 node projections (P1 + S1) — independent of setupB
    gemm_f32x2<<<dim3((N_NODES + 127) / 128, 4), 256>>>(ent, wp1, p1, a2c1, s1,
                                                        N_NODES, 512, 64);
    cudaStreamWaitEvent(0, evJoin, 0);

    // Q projection with fused real-edge pass + nhop tail blocks
    gemm_q<<<dim3(QBLK + E_NHOP / 8, 2), 256>>>(eemb, el, eln, etn);

    // layer-2 projections with fused norm1
    gemm_x2<<<dim3((2 * N_NODES + 127) / 128, 2), 256>>>(p2, a2c2, s2);

    edge_pass2<<<dim3(E_ALL / 8, 2), 256>>>(el, eln, et, etn);

    gemm_we<<<(2 * N_NODES + 127) / 128, 256>>>(be, qe);
    combine<<<(N_NODES * OUTF + 255) / 256, 256>>>(out);

    cudaStreamDestroy(sB);  // async-safe: pending work completes before teardown
    cudaEventDestroy(evFork);
    cudaEventDestroy(evJoin);
}

// round 15
// speedup vs baseline: 1.1924x; 1.0179x over previous
#include <cuda_runtime.h>
#include <math.h>

#define N_NODES 50000
#define NFEAT   64
#define NHID    64
#define E_REAL  200000
#define E_NHOP  40000
#define E_ALL   240000
#define N_REL   200
#define OUTF    128
#define ALPHA   0.2f
#define QBLK64  3125   // (E_REAL+63)/64

typedef unsigned long long ull;

// ---------------- device scratch ----------------
__device__ __align__(16) float g_P1all[(size_t)N_NODES * 512];     // [i][dir*256+role*128+h*64+j]
__device__ __align__(16) float g_R1proj[N_REL * 256];              // [r*256 + c*64 + j]
__device__ __align__(16) float g_R2proj[N_REL * OUTF];
__device__ __align__(16) float g_rowsum1T[(size_t)N_NODES * 4];    // [i*4 + dir*2 + h]
__device__ __align__(16) float g_hp1[2][(size_t)N_NODES * 128];
__device__ __align__(16) float g_P2all[2][(size_t)N_NODES * 256];
__device__ float g_rowsum2[2][N_NODES];
__device__ __align__(16) float g_hp2[2][(size_t)N_NODES * OUTF];
__device__ __align__(16) float g_y[2][(size_t)N_NODES * OUTF];
__device__ float g_wsum[2];
// packed weights (row-major [n][K])
__device__ __align__(16) float g_Wp1[512 * 64];
__device__ __align__(16) float g_WpQ[256 * 64];
__device__ __align__(16) float g_Wp2[256 * 128];
__device__ __align__(16) float g_WeP[64 * 128];                    // [j][k]
// factorized attention scalars
__device__ __align__(16) float g_S1[(size_t)N_NODES * 8];          // [i*8 + dir*4 + role*2 + h]
__device__ __align__(16) float g_Sr1[N_REL * 4];
__device__ __align__(16) float g_S2[2][(size_t)N_NODES * 4];
__device__ float g_Srel2[N_REL];
// per-column dot weights
__device__ __align__(16) float g_a2cat1[512];
__device__ __align__(16) float g_a2catQ[256];
__device__ __align__(16) float g_a2cat2[256];

#define RED2(ptr, a, b) \
    asm volatile("red.global.add.v2.f32 [%0], {%1, %2};" :: "l"(ptr), "f"(a), "f"(b) : "memory")
#define RED4(ptr, a, b, c, d) \
    asm volatile("red.global.add.v4.f32 [%0], {%1, %2, %3, %4};" :: "l"(ptr), "f"(a), "f"(b), "f"(c), "f"(d) : "memory")

// ---------------- setupA: weight packing (13 blocks, main stream) ----------------
__global__ void setupA(const float* __restrict__ a_in, const float* __restrict__ a_out,
                       const float* __restrict__ a_o,
                       const float* __restrict__ a2_in, const float* __restrict__ a2_out,
                       const float* __restrict__ a2_o, const float* __restrict__ We) {
    int b = blockIdx.x, t = threadIdx.x;
    if (b < 4) {
        for (int idx = b * 256 + t; idx < 512 * 64; idx += 4 * 256) {
            int n = idx >> 6, k = idx & 63;
            int dir = n >> 8, role = (n >> 7) & 1, h = (n >> 6) & 1, j = n & 63;
            const float* A = (dir ? a_out : a_in) + (size_t)h * 64 * 192;
            g_Wp1[idx] = A[j * 192 + role * 64 + k];
        }
    } else if (b < 6) {
        for (int idx = (b - 4) * 256 + t; idx < 256 * 64; idx += 2 * 256) {
            int n = idx >> 6, k = idx & 63;
            int c = n >> 6, j = n & 63;
            const float* A = ((c >> 1) ? a_out : a_in) + (size_t)(c & 1) * 64 * 192;
            g_WpQ[idx] = A[j * 192 + 128 + k];
        }
    } else if (b < 10) {
        for (int idx = (b - 6) * 256 + t; idx < 256 * 128; idx += 4 * 256) {
            int n = idx >> 7, k = idx & 127;
            int role = n >> 7, j = n & 127;
            g_Wp2[idx] = a_o[j * 384 + role * 128 + k];
        }
    } else if (b < 12) {
        for (int idx = (b - 10) * 256 + t; idx < 64 * 128; idx += 2 * 256) {
            int j = idx >> 7, k = idx & 127;
            g_WeP[idx] = We[k * 64 + j];
        }
    } else {
        for (int n = t; n < 512; n += 256) {
            int dir = n >> 8, h = (n >> 6) & 1, j = n & 63;
            g_a2cat1[n] = (dir ? a2_out : a2_in)[h * 64 + j];
        }
        for (int n = t; n < 256; n += 256) {
            int c = n >> 6, j = n & 63;
            g_a2catQ[n] = ((c >> 1) ? a2_out : a2_in)[(c & 1) * 64 + j];
        }
        if (t < 256) g_a2cat2[t] = a2_o[t & 127];
    }
}

// ---------------- setupB: zero accumulators + relation tables (parallel stream) ------
__global__ void setupB(const float* __restrict__ a_in, const float* __restrict__ a_out,
                       const float* __restrict__ a_o,
                       const float* __restrict__ a2_in, const float* __restrict__ a2_out,
                       const float* __restrict__ a2_o,
                       const float* __restrict__ rel, const float* __restrict__ W,
                       float* __restrict__ out_tail) {
    int b = blockIdx.x, t = threadIdx.x;
    if (b < 512) {
        size_t tid = (size_t)b * 256 + t, stride = (size_t)512 * 256;
        float4 z = make_float4(0.f, 0.f, 0.f, 0.f);
        float4* hp1 = (float4*)&g_hp1[0][0];
        for (size_t i = tid; i < (size_t)2 * N_NODES * 32; i += stride) hp1[i] = z;
        float4* hp2 = (float4*)&g_hp2[0][0];
        for (size_t i = tid; i < (size_t)2 * N_NODES * 32; i += stride) hp2[i] = z;
        float4* rs1 = (float4*)&g_rowsum1T[0];
        for (size_t i = tid; i < (size_t)N_NODES; i += stride) rs1[i] = z;
        float4* rs2 = (float4*)&g_rowsum2[0][0];
        for (size_t i = tid; i < (size_t)N_NODES / 2; i += stride) rs2[i] = z;
        if (tid < 2) g_wsum[tid] = 0.f;
    } else {
        int r = b - 512;  // [0, 200)
        __shared__ float relrow[64];
        __shared__ float rel2row[128];
        __shared__ float red[8];
        if (t < 64) relrow[t] = rel[r * 64 + t];
        __syncthreads();
        if (t < 128) {
            float acc = 0.f;
            #pragma unroll
            for (int k = 0; k < 64; k++) acc += relrow[k] * W[k * 128 + t];
            rel2row[t] = acc;
            out_tail[(size_t)N_NODES * OUTF + r * 128 + t] = acc;
        }
        __syncthreads();
        {
            int c = t >> 6, j = t & 63;
            const float* A = ((c >> 1) ? a_out : a_in) + (size_t)(c & 1) * 64 * 192;
            float acc = 0.f;
            #pragma unroll
            for (int k = 0; k < 64; k++) acc += relrow[k] * A[j * 192 + 128 + k];
            g_R1proj[r * 256 + t] = acc;
            float part = acc * ((c >> 1) ? a2_out : a2_in)[(c & 1) * 64 + j];
            #pragma unroll
            for (int o = 16; o; o >>= 1) part += __shfl_xor_sync(0xffffffffu, part, o);
            if ((t & 31) == 0) red[t >> 5] = part;
        }
        __syncthreads();
        if (t < 4) g_Sr1[r * 4 + t] = red[2 * t] + red[2 * t + 1];
        __syncthreads();
        {
            float part = 0.f;
            if (t < 128) {
                float acc = 0.f;
                #pragma unroll 16
                for (int k = 0; k < 128; k++) acc += rel2row[k] * a_o[t * 384 + 256 + k];
                g_R2proj[r * 128 + t] = acc;
                part = acc * a2_o[t];
            }
            #pragma unroll
            for (int o = 16; o; o >>= 1) part += __shfl_xor_sync(0xffffffffu, part, o);
            if ((t & 31) == 0 && t < 128) red[t >> 5] = part;
        }
        __syncthreads();
        if (t == 0) g_Srel2[r] = red[0] + red[1] + red[2] + red[3];
    }
}

// ---------------- f32x2 GEMM (projection variant, register prefetch) ----------------
#define KC 16
__global__ void __launch_bounds__(256, 2)
gemm_f32x2(const float* __restrict__ X,
           const float* __restrict__ Wp,
           float* __restrict__ C,
           const float* __restrict__ a2cat,
           float* __restrict__ sOut,
           int M, int N, int K) {
    __shared__ __align__(16) float2 Xs2[KC][130];
    __shared__ __align__(16) float  As[KC][132];
    int t = threadIdx.x;
    int tx = t & 15, ty = t >> 4;
    int ib = blockIdx.x * 128;
    int jb = blockIdx.y * 128;
    ull acc[8][4];
    #pragma unroll
    for (int ii = 0; ii < 8; ii++)
        #pragma unroll
        for (int q = 0; q < 4; q++) acc[ii][q] = 0ull;

    float4 xb[2], ab[2];
    int pi0 = t & 127, pk0 = (t >> 7) * 4;
    int pk1 = pk0 + 8;
    {
        int gi = ib + pi0;
        xb[0] = make_float4(0.f, 0.f, 0.f, 0.f);
        xb[1] = make_float4(0.f, 0.f, 0.f, 0.f);
        if (gi < M) {
            xb[0] = *(const float4*)&X[(size_t)gi * K + pk0];
            xb[1] = *(const float4*)&X[(size_t)gi * K + pk1];
        }
        ab[0] = *(const float4*)&Wp[(size_t)(jb + pi0) * K + pk0];
        ab[1] = *(const float4*)&Wp[(size_t)(jb + pi0) * K + pk1];
    }

    for (int kc = 0; kc < K; kc += KC) {
        #pragma unroll
        for (int u = 0; u < 2; u++) {
            int kq = u ? pk1 : pk0;
            float4 v = xb[u];
            Xs2[kq + 0][pi0] = make_float2(v.x, v.x);
            Xs2[kq + 1][pi0] = make_float2(v.y, v.y);
            Xs2[kq + 2][pi0] = make_float2(v.z, v.z);
            Xs2[kq + 3][pi0] = make_float2(v.w, v.w);
            float4 a = ab[u];
            As[kq + 0][pi0] = a.x; As[kq + 1][pi0] = a.y;
            As[kq + 2][pi0] = a.z; As[kq + 3][pi0] = a.w;
        }
        __syncthreads();
        if (kc + KC < K) {
            int gi = ib + pi0;
            xb[0] = make_float4(0.f, 0.f, 0.f, 0.f);
            xb[1] = make_float4(0.f, 0.f, 0.f, 0.f);
            if (gi < M) {
                xb[0] = *(const float4*)&X[(size_t)gi * K + kc + KC + pk0];
                xb[1] = *(const float4*)&X[(size_t)gi * K + kc + KC + pk1];
            }
            ab[0] = *(const float4*)&Wp[(size_t)(jb + pi0) * K + kc + KC + pk0];
            ab[1] = *(const float4*)&Wp[(size_t)(jb + pi0) * K + kc + KC + pk1];
        }
        #pragma unroll
        for (int kk = 0; kk < KC; kk++) {
            ull av[4];
            #pragma unroll
            for (int q = 0; q < 4; q++)
                av[q] = *(const ull*)&As[kk][2 * (tx + 16 * q)];
            #pragma unroll
            for (int ii = 0; ii < 8; ii++) {
                ull xx = *(const ull*)&Xs2[kk][ty * 8 + ii];
                #pragma unroll
                for (int q = 0; q < 4; q++)
                    asm("fma.rn.f32x2 %0, %1, %2, %0;"
                        : "+l"(acc[ii][q]) : "l"(xx), "l"(av[q]));
            }
        }
        __syncthreads();
    }
    int nBlk = N >> 6;
    float2 w[4];
    #pragma unroll
    for (int q = 0; q < 4; q++)
        w[q] = *(const float2*)&a2cat[jb + 2 * (tx + 16 * q)];
    #pragma unroll
    for (int ii = 0; ii < 8; ii++) {
        int gi = ib + ty * 8 + ii;
        float lo[4], hi[4];
        #pragma unroll
        for (int q = 0; q < 4; q++)
            asm("mov.b64 {%0, %1}, %2;" : "=f"(lo[q]), "=f"(hi[q]) : "l"(acc[ii][q]));
        if (gi < M) {
            #pragma unroll
            for (int q = 0; q < 4; q++)
                *(float2*)&C[(size_t)gi * N + jb + 2 * (tx + 16 * q)] = make_float2(lo[q], hi[q]);
        }
        float s0 = lo[0] * w[0].x + hi[0] * w[0].y + lo[1] * w[1].x + hi[1] * w[1].y;
        float s1 = lo[2] * w[2].x + hi[2] * w[2].y + lo[3] * w[3].x + hi[3] * w[3].y;
        #pragma unroll
        for (int o = 8; o; o >>= 1) {
            s0 += __shfl_xor_sync(0xffffffffu, s0, o);
            s1 += __shfl_xor_sync(0xffffffffu, s1, o);
        }
        if (tx == 0 && gi < M) {
            size_t base = (size_t)gi * nBlk + (jb >> 6);
            sOut[base] = s0;
            sOut[base + 1] = s1;
        }
    }
}

// ---------------- gemm_x2: layer-2 projection with FUSED norm1 in the X loader ------
__global__ void __launch_bounds__(256, 2)
gemm_x2(float* __restrict__ C, const float* __restrict__ a2cat,
        float* __restrict__ sOut) {
    __shared__ __align__(16) float2 Xs2[KC][130];
    __shared__ __align__(16) float  As[KC][132];
    int t = threadIdx.x;
    int tx = t & 15, ty = t >> 4;
    int ib = blockIdx.x * 128;
    int jb = blockIdx.y * 128;
    const int M = 2 * N_NODES, N = 256, K = 128;
    ull acc[8][4];
    #pragma unroll
    for (int ii = 0; ii < 8; ii++)
        #pragma unroll
        for (int q = 0; q < 4; q++) acc[ii][q] = 0ull;

    for (int kc = 0; kc < K; kc += KC) {
        #pragma unroll
        for (int p = t; p < 512; p += 256) {
            int i = p & 127, kq = (p >> 7) * 4;
            int gi = ib + i;
            float4 v = make_float4(0.f, 0.f, 0.f, 0.f);
            if (gi < M) {
                int dir = gi >= N_NODES;
                int i2 = dir ? gi - N_NODES : gi;
                int kk = kc + kq;
                float rs = g_rowsum1T[(size_t)i2 * 4 + dir * 2 + (kk >> 6)];
                if (rs > 0.f) {
                    float inv = 1.f / rs;
                    float4 hv = *(const float4*)&g_hp1[dir][(size_t)i2 * 128 + kk];
                    float4 pv = *(const float4*)&g_P1all[(size_t)i2 * 512 + dir * 256 + kk];
                    v.x = hv.x * inv + pv.x;
                    v.y = hv.y * inv + pv.y;
                    v.z = hv.z * inv + pv.z;
                    v.w = hv.w * inv + pv.w;
                }
                v.x = (v.x > 0.f) ? v.x : expm1f(v.x);
                v.y = (v.y > 0.f) ? v.y : expm1f(v.y);
                v.z = (v.z > 0.f) ? v.z : expm1f(v.z);
                v.w = (v.w > 0.f) ? v.w : expm1f(v.w);
            }
            Xs2[kq + 0][i] = make_float2(v.x, v.x);
            Xs2[kq + 1][i] = make_float2(v.y, v.y);
            Xs2[kq + 2][i] = make_float2(v.z, v.z);
            Xs2[kq + 3][i] = make_float2(v.w, v.w);
        }
        #pragma unroll
        for (int p = t; p < 512; p += 256) {
            int j = p & 127, kq = (p >> 7) * 4;
            float4 v = *(const float4*)&g_Wp2[(size_t)(jb + j) * K + kc + kq];
            As[kq + 0][j] = v.x; As[kq + 1][j] = v.y;
            As[kq + 2][j] = v.z; As[kq + 3][j] = v.w;
        }
        __syncthreads();
        #pragma unroll
        for (int kk = 0; kk < KC; kk++) {
            ull av[4];
            #pragma unroll
            for (int q = 0; q < 4; q++)
                av[q] = *(const ull*)&As[kk][2 * (tx + 16 * q)];
            #pragma unroll
            for (int ii = 0; ii < 8; ii++) {
                ull xx = *(const ull*)&Xs2[kk][ty * 8 + ii];
                #pragma unroll
                for (int q = 0; q < 4; q++)
                    asm("fma.rn.f32x2 %0, %1, %2, %0;"
                        : "+l"(acc[ii][q]) : "l"(xx), "l"(av[q]));
            }
        }
        __syncthreads();
    }
    int nBlk = N >> 6;
    float2 w[4];
    #pragma unroll
    for (int q = 0; q < 4; q++)
        w[q] = *(const float2*)&a2cat[jb + 2 * (tx + 16 * q)];
    #pragma unroll
    for (int ii = 0; ii < 8; ii++) {
        int gi = ib + ty * 8 + ii;
        float lo[4], hi[4];
        #pragma unroll
        for (int q = 0; q < 4; q++)
            asm("mov.b64 {%0, %1}, %2;" : "=f"(lo[q]), "=f"(hi[q]) : "l"(acc[ii][q]));
        if (gi < M) {
            #pragma unroll
            for (int q = 0; q < 4; q++)
                *(float2*)&C[(size_t)gi * N + jb + 2 * (tx + 16 * q)] = make_float2(lo[q], hi[q]);
        }
        float s0 = lo[0] * w[0].x + hi[0] * w[0].y + lo[1] * w[1].x + hi[1] * w[1].y;
        float s1 = lo[2] * w[2].x + hi[2] * w[2].y + lo[3] * w[3].x + hi[3] * w[3].y;
        #pragma unroll
        for (int o = 8; o; o >>= 1) {
            s0 += __shfl_xor_sync(0xffffffffu, s0, o);
            s1 += __shfl_xor_sync(0xffffffffu, s1, o);
        }
        if (tx == 0 && gi < M) {
            size_t base = (size_t)gi * nBlk + (jb >> 6);
            sOut[base] = s0;
            sOut[base + 1] = s1;
        }
    }
}

// ---------------- gemm_q: 64-edge tiles, 3 CTAs/SM, fused real-edge pass + nhop tail ----
__global__ void __launch_bounds__(256, 3)
gemm_q(const float* __restrict__ X, const int* __restrict__ el,
       const int* __restrict__ eln, const int* __restrict__ etn) {
    __shared__ __align__(16) float2 Xs2[KC][66];
    __shared__ __align__(16) float  As[KC][132];
    int t = threadIdx.x;
    int dir = blockIdx.y;

    if (blockIdx.x >= QBLK64) {
        // ---- nhop edge pass ----
        int e = (blockIdx.x - QBLK64) * 8 + (t >> 5);   // [0, E_NHOP)
        int lane = t & 31;
        int h = lane >> 4;
        int jj = 4 * (lane & 15);
        int i0 = eln[e], i1 = eln[E_NHOP + e];
        int t0 = etn[2 * e], t1 = etn[2 * e + 1];
        float4 qa = *(const float4*)&g_R1proj[t0 * 256 + dir * 128 + h * 64 + jj];
        float4 qb = *(const float4*)&g_R1proj[t1 * 256 + dir * 128 + h * 64 + jj];
        float4 q;
        q.x = qa.x + qb.x; q.y = qa.y + qb.y; q.z = qa.z + qb.z; q.w = qa.w + qb.w;
        float sq = g_Sr1[t0 * 4 + dir * 2 + h] + g_Sr1[t1 * 4 + dir * 2 + h];
        int src = dir ? i1 : i0;
        int dst = dir ? i0 : i1;
        float score = g_S1[(size_t)src * 8 + dir * 4 + h]
                    + g_S1[(size_t)dst * 8 + dir * 4 + 2 + h] + sq;
        float lk = score > 0.f ? score : ALPHA * score;
        float ev = __expf(-lk);
        float4 d = *(const float4*)&g_P1all[(size_t)dst * 512 + dir * 256 + 128 + h * 64 + jj];
        float* hp = &g_hp1[dir][(size_t)src * 128 + h * 64 + jj];
        RED4(hp, ev * (d.x + q.x), ev * (d.y + q.y), ev * (d.z + q.z), ev * (d.w + q.w));
        if ((lane & 15) == 0) atomicAdd(&g_rowsum1T[(size_t)src * 4 + dir * 2 + h], ev);
        return;
    }

    int tx = t & 15, ty = t >> 4;   // ty 0..15, 4 rows each -> 64 rows
    int ib = blockIdx.x * 64;
    int jb = dir * 128;
    const int M = E_REAL, K = 64;
    ull acc[4][4];
    #pragma unroll
    for (int ii = 0; ii < 4; ii++)
        #pragma unroll
        for (int q = 0; q < 4; q++) acc[ii][q] = 0ull;

    for (int kc = 0; kc < K; kc += KC) {
        // X tile: 64 rows x 16 k = 256 float4 over 256 threads
        {
            int i = t & 63, kq = (t >> 6) * 4;
            int gi = ib + i;
            float4 v = make_float4(0.f, 0.f, 0.f, 0.f);
            if (gi < M) v = *(const float4*)&X[(size_t)gi * K + kc + kq];
            Xs2[kq + 0][i] = make_float2(v.x, v.x);
            Xs2[kq + 1][i] = make_float2(v.y, v.y);
            Xs2[kq + 2][i] = make_float2(v.z, v.z);
            Xs2[kq + 3][i] = make_float2(v.w, v.w);
        }
        // A tile: 128 j x 16 k = 512 float4 over 256 threads x2
        #pragma unroll
        for (int p = t; p < 512; p += 256) {
            int j = p & 127, kq = (p >> 7) * 4;
            float4 v = *(const float4*)&g_WpQ[(size_t)(jb + j) * K + kc + kq];
            As[kq + 0][j] = v.x; As[kq + 1][j] = v.y;
            As[kq + 2][j] = v.z; As[kq + 3][j] = v.w;
        }
        __syncthreads();
        #pragma unroll
        for (int kk = 0; kk < KC; kk++) {
            ull av[4];
            #pragma unroll
            for (int q = 0; q < 4; q++)
                av[q] = *(const ull*)&As[kk][2 * (tx + 16 * q)];
            #pragma unroll
            for (int ii = 0; ii < 4; ii++) {
                ull xx = *(const ull*)&Xs2[kk][ty * 4 + ii];
                #pragma unroll
                for (int q = 0; q < 4; q++)
                    asm("fma.rn.f32x2 %0, %1, %2, %0;"
                        : "+l"(acc[ii][q]) : "l"(xx), "l"(av[q]));
            }
        }
        __syncthreads();
    }
    // epilogue: fused real-edge attention scatter (4 rows/thread)
    float2 w[4];
    #pragma unroll
    for (int q = 0; q < 4; q++)
        w[q] = *(const float2*)&g_a2catQ[jb + 2 * (tx + 16 * q)];
    #pragma unroll
    for (int ii = 0; ii < 4; ii++) {
        int gi = ib + ty * 4 + ii;   // edge index
        float lo[4], hi[4];
        #pragma unroll
        for (int q = 0; q < 4; q++)
            asm("mov.b64 {%0, %1}, %2;" : "=f"(lo[q]), "=f"(hi[q]) : "l"(acc[ii][q]));
        float s0 = lo[0] * w[0].x + hi[0] * w[0].y + lo[1] * w[1].x + hi[1] * w[1].y;
        float s1 = lo[2] * w[2].x + hi[2] * w[2].y + lo[3] * w[3].x + hi[3] * w[3].y;
        #pragma unroll
        for (int o = 8; o; o >>= 1) {
            s0 += __shfl_xor_sync(0xffffffffu, s0, o);
            s1 += __shfl_xor_sync(0xffffffffu, s1, o);
        }
        if (gi < M) {
            int i0 = el[gi], i1 = el[E_REAL + gi];
            int src = dir ? i1 : i0;
            int dst = dir ? i0 : i1;
            float4 sv = *(const float4*)&g_S1[(size_t)src * 8 + dir * 4];
            float4 dv = *(const float4*)&g_S1[(size_t)dst * 8 + dir * 4];
            float sc0 = sv.x + dv.z + s0;
            float sc1 = sv.y + dv.w + s1;
            float lk0 = sc0 > 0.f ? sc0 : ALPHA * sc0;
            float lk1 = sc1 > 0.f ? sc1 : ALPHA * sc1;
            float ev0 = __expf(-lk0);
            float ev1 = __expf(-lk1);
            const float* pd = &g_P1all[(size_t)dst * 512 + dir * 256 + 128];
            float* hp = &g_hp1[dir][(size_t)src * 128];
            #pragma unroll
            for (int q = 0; q < 4; q++) {
                int col = 2 * (tx + 16 * q);
                float ev = (q < 2) ? ev0 : ev1;
                float2 d = *(const float2*)&pd[col];
                RED2(&hp[col], ev * (d.x + lo[q]), ev * (d.y + hi[q]));
            }
            if (tx == 0) {
                atomicAdd(&g_rowsum1T[(size_t)src * 4 + dir * 2], ev0);
                atomicAdd(&g_rowsum1T[(size_t)src * 4 + dir * 2 + 1], ev1);
            }
        }
    }
}

// ---------------- gemm_we: norm2 fused into loader + tanh-dot epilogue ----------------
__global__ void __launch_bounds__(256, 2)
gemm_we(const float* __restrict__ be, const float* __restrict__ qe) {
    __shared__ __align__(16) float2 Xs2[KC][130];
    __shared__ __align__(16) float  As[KC][68];
    __shared__ float s_sh[2];
    int t = threadIdx.x;
    int tx = t & 7, ty = t >> 3;
    int lane = t & 31;
    int ib = blockIdx.x * 128;
    const int M = 2 * N_NODES;
    if (t < 2) s_sh[t] = 0.f;
    const float* hp2f = &g_hp2[0][0];
    const float* rs2f = &g_rowsum2[0][0];
    float* yf = &g_y[0][0];
    ull acc[4][4];
    #pragma unroll
    for (int ii = 0; ii < 4; ii++)
        #pragma unroll
        for (int q = 0; q < 4; q++) acc[ii][q] = 0ull;

    for (int kc = 0; kc < 128; kc += KC) {
        #pragma unroll
        for (int p = t; p < 512; p += 256) {
            int i = p & 127, kq = (p >> 7) * 4;
            int gi = ib + i;
            float4 v = make_float4(0.f, 0.f, 0.f, 0.f);
            if (gi < M) {
                int xs = gi >= N_NODES;
                int ii2 = xs ? gi - N_NODES : gi;
                float rs = rs2f[gi];
                if (rs > 0.f) {
                    float inv = 1.f / rs;
                    float4 hv = *(const float4*)&hp2f[(size_t)gi * 128 + kc + kq];
                    float4 pv = *(const float4*)&g_P2all[xs][(size_t)ii2 * 256 + kc + kq];
                    v.x = hv.x * inv + pv.x;
                    v.y = hv.y * inv + pv.y;
                    v.z = hv.z * inv + pv.z;
                    v.w = hv.w * inv + pv.w;
                }
                v.x = (v.x > 0.f) ? v.x : expm1f(v.x);
                v.y = (v.y > 0.f) ? v.y : expm1f(v.y);
                v.z = (v.z > 0.f) ? v.z : expm1f(v.z);
                v.w = (v.w > 0.f) ? v.w : expm1f(v.w);
                *(float4*)&yf[(size_t)gi * 128 + kc + kq] = v;
            }
            Xs2[kq + 0][i] = make_float2(v.x, v.x);
            Xs2[kq + 1][i] = make_float2(v.y, v.y);
            Xs2[kq + 2][i] = make_float2(v.z, v.z);
            Xs2[kq + 3][i] = make_float2(v.w, v.w);
        }
        {
            int j = t & 63, kq = ((t >> 6) & 3) * 4;
            float4 w = *(const float4*)&g_WeP[j * 128 + kc + kq];
            As[kq + 0][j] = w.x; As[kq + 1][j] = w.y;
            As[kq + 2][j] = w.z; As[kq + 3][j] = w.w;
        }
        __syncthreads();
        #pragma unroll
        for (int kk = 0; kk < KC; kk++) {
            ull av[4];
            #pragma unroll
            for (int q = 0; q < 4; q++)
                av[q] = *(const ull*)&As[kk][2 * (tx + 8 * q)];
            #pragma unroll
            for (int ii = 0; ii < 4; ii++) {
                ull xx = *(const ull*)&Xs2[kk][ty * 4 + ii];
                #pragma unroll
                for (int q = 0; q < 4; q++)
                    asm("fma.rn.f32x2 %0, %1, %2, %0;"
                        : "+l"(acc[ii][q]) : "l"(xx), "l"(av[q]));
            }
        }
        __syncthreads();
    }
    float2 bb[4], qq[4];
    #pragma unroll
    for (int q = 0; q < 4; q++) {
        bb[q] = *(const float2*)&be[2 * (tx + 8 * q)];
        qq[q] = *(const float2*)&qe[2 * (tx + 8 * q)];
    }
    #pragma unroll
    for (int ii = 0; ii < 4; ii++) {
        int gi = ib + ty * 4 + ii;
        float lo[4], hi[4];
        #pragma unroll
        for (int q = 0; q < 4; q++)
            asm("mov.b64 {%0, %1}, %2;" : "=f"(lo[q]), "=f"(hi[q]) : "l"(acc[ii][q]));
        float s = 0.f;
        #pragma unroll
        for (int q = 0; q < 4; q++)
            s += tanhf(lo[q] + bb[q].x) * qq[q].x + tanhf(hi[q] + bb[q].y) * qq[q].y;
        #pragma unroll
        for (int o = 4; o; o >>= 1) s += __shfl_xor_sync(0xffffffffu, s, o);
        if ((lane & 7) == 0 && gi < M)
            atomicAdd(&s_sh[gi >= N_NODES], s);
    }
    __syncthreads();
    if (t < 2) atomicAdd(&g_wsum[t], s_sh[t]);
}

// ---------------- layer-2 edge pass ----------------
__global__ void edge_pass2(const int* __restrict__ el, const int* __restrict__ eln,
                           const int* __restrict__ et, const int* __restrict__ etn) {
    int dir = blockIdx.y;
    int e = blockIdx.x * 8 + (threadIdx.x >> 5);
    if (e >= E_ALL) return;
    int lane = threadIdx.x & 31;
    int i0, i1;
    float q0, q1, q2, q3, sq;
    if (e < E_REAL) {
        i0 = el[e]; i1 = el[E_REAL + e];
        int ty = et[e];
        float4 qv = *(const float4*)&g_R2proj[ty * 128 + 4 * lane];
        q0 = qv.x; q1 = qv.y; q2 = qv.z; q3 = qv.w;
        sq = g_Srel2[ty];
    } else {
        int en = e - E_REAL;
        i0 = eln[en]; i1 = eln[E_NHOP + en];
        int t0 = etn[2 * en], t1 = etn[2 * en + 1];
        float4 qa = *(const float4*)&g_R2proj[t0 * 128 + 4 * lane];
        float4 qb = *(const float4*)&g_R2proj[t1 * 128 + 4 * lane];
        q0 = qa.x + qb.x; q1 = qa.y + qb.y; q2 = qa.z + qb.z; q3 = qa.w + qb.w;
        sq = g_Srel2[t0] + g_Srel2[t1];
    }
    int seg = dir ? i1 : i0;
    int nbr = dir ? i0 : i1;
    float4 sA = *(const float4*)&g_S2[dir][(size_t)seg * 4];
    float4 sB = *(const float4*)&g_S2[dir][(size_t)nbr * 4];
    float score = sA.x + sA.y + sB.z + sB.w + sq;
    float lk = score > 0.f ? score : ALPHA * score;
    float ev = __expf(-lk);
    float4 dv = *(const float4*)&g_P2all[dir][(size_t)nbr * 256 + 128 + 4 * lane];
    float* hp = &g_hp2[dir][(size_t)seg * 128 + 4 * lane];
    RED4(hp, ev * (dv.x + q0), ev * (dv.y + q1), ev * (dv.z + q2), ev * (dv.w + q3));
    if (lane == 0) atomicAdd(&g_rowsum2[dir][seg], ev);
}

// ---------------- beta + combine ----------------
__global__ void combine(float* __restrict__ out) {
    float m0 = g_wsum[0] / (float)N_NODES;
    float m1 = g_wsum[1] / (float)N_NODES;
    float mx = fmaxf(m0, m1);
    float e0 = expf(m0 - mx), e1 = expf(m1 - mx);
    float b0 = e0 / (e0 + e1), b1 = e1 / (e0 + e1);
    size_t i = (size_t)blockIdx.x * 256 + threadIdx.x;
    if (i >= (size_t)N_NODES * OUTF) return;
    out[i] = b0 * g_y[0][i] + b1 * g_y[1][i];
}

// ---------------- launch ----------------
extern "C" void kernel_launch(void* const* d_in, const int* in_sizes, int n_in,
                              void* d_out, int out_size) {
    const float* ent   = (const float*)d_in[0];
    const float* rel   = (const float*)d_in[1];
    const int*   el    = (const int*)d_in[2];
    const int*   et    = (const int*)d_in[3];
    const float* eemb  = (const float*)d_in[4];
    const int*   eln   = (const int*)d_in[5];
    const int*   etn   = (const int*)d_in[6];
    const float* a_in  = (const float*)d_in[7];
    const float* a2_in = (const float*)d_in[8];
    const float* a_out = (const float*)d_in[9];
    const float* a2_out= (const float*)d_in[10];
    const float* a_o   = (const float*)d_in[11];
    const float* a2_o  = (const float*)d_in[12];
    const float* W     = (const float*)d_in[13];
    const float* We    = (const float*)d_in[14];
    const float* be    = (const float*)d_in[15];
    const float* qe    = (const float*)d_in[16];
    float* out = (float*)d_out;

    float *p1 = 0, *p2 = 0, *wp1 = 0;
    float *a2c1 = 0, *a2c2 = 0, *s1 = 0, *s2 = 0;
    cudaGetSymbolAddress((void**)&p1, g_P1all);
    cudaGetSymbolAddress((void**)&p2, g_P2all);
    cudaGetSymbolAddress((void**)&wp1, g_Wp1);
    cudaGetSymbolAddress((void**)&a2c1, g_a2cat1);
    cudaGetSymbolAddress((void**)&a2c2, g_a2cat2);
    cudaGetSymbolAddress((void**)&s1, g_S1);
    cudaGetSymbolAddress((void**)&s2, g_S2);

    cudaStream_t sB;
    cudaStreamCreateWithFlags(&sB, cudaStreamNonBlocking);
    cudaEvent_t evFork, evJoin;
    cudaEventCreateWithFlags(&evFork, cudaEventDisableTiming);
    cudaEventCreateWithFlags(&evJoin, cudaEventDisableTiming);

    cudaEventRecord(evFork, 0);
    cudaStreamWaitEvent(sB, evFork, 0);
    setupB<<<712, 256, 0, sB>>>(a_in, a_out, a_o, a2_in, a2_out, a2_o, rel, W, out);
    cudaEventRecord(evJoin, sB);

    setupA<<<13, 256>>>(a_in, a_out, a_o, a2_in, a2_out, a2_o, We);
    gemm_f32x2<<<dim3((N_NODES + 127) / 128, 4), 256>>>(ent, wp1, p1, a2c1, s1,
                                                        N_NODES, 512, 64);
    cudaStreamWaitEvent(0, evJoin, 0);

    gemm_q<<<dim3(QBLK64 + E_NHOP / 8, 2), 256>>>(eemb, el, eln, etn);

    gemm_x2<<<dim3((2 * N_NODES + 127) / 128, 2), 256>>>(p2, a2c2, s2);

    edge_pass2<<<dim3(E_ALL / 8, 2), 256>>>(el, eln, et, etn);

    gemm_we<<<(2 * N_NODES + 127) / 128, 256>>>(be, qe);
    combine<<<(N_NODES * OUTF + 255) / 256, 256>>>(out);

    cudaStreamDestroy(sB);
    cudaEventDestroy(evFork);
    cudaEventDestroy(evJoin);
}

// round 16
// speedup vs baseline: 1.2345x; 1.0354x over previous
#include <cuda_runtime.h>
#include <math.h>

#define N_NODES 50000
#define NFEAT   64
#define NHID    64
#define E_REAL  200000
#define E_NHOP  40000
#define E_ALL   240000
#define N_REL   200
#define OUTF    128
#define ALPHA   0.2f
#define QBLK64  3125   // (E_REAL+63)/64

typedef unsigned long long ull;

// ---------------- device scratch ----------------
__device__ __align__(16) float g_P1all[(size_t)N_NODES * 512];     // [i][dir*256+role*128+h*64+j]
__device__ __align__(16) float g_R1proj[N_REL * 256];              // [r*256 + c*64 + j]
__device__ __align__(16) float g_R2proj[N_REL * OUTF];
__device__ __align__(16) float g_rowsum1T[(size_t)N_NODES * 4];    // [i*4 + dir*2 + h]
__device__ __align__(16) float g_hp1[2][(size_t)N_NODES * 128];
__device__ __align__(16) float g_P2all[2][(size_t)N_NODES * 256];
__device__ float g_rowsum2[2][N_NODES];
__device__ __align__(16) float g_hp2[2][(size_t)N_NODES * OUTF];
__device__ __align__(16) float g_y[2][(size_t)N_NODES * OUTF];
__device__ float g_wsum[2];
// packed weights (row-major [n][K])
__device__ __align__(16) float g_Wp1[512 * 64];
__device__ __align__(16) float g_WpQ[256 * 64];
__device__ __align__(16) float g_Wp2[256 * 128];
__device__ __align__(16) float g_WeP[64 * 128];                    // [j][k]
// factorized attention scalars
__device__ __align__(16) float g_S1[(size_t)N_NODES * 8];          // [i*8 + dir*4 + role*2 + h]
__device__ __align__(16) float g_Sr1[N_REL * 4];
__device__ __align__(16) float g_S2[2][(size_t)N_NODES * 4];
__device__ float g_Srel2[N_REL];
// per-column dot weights
__device__ __align__(16) float g_a2cat1[512];
__device__ __align__(16) float g_a2catQ[256];
__device__ __align__(16) float g_a2cat2[256];

#define RED4(ptr, a, b, c, d) \
    asm volatile("red.global.add.v4.f32 [%0], {%1, %2, %3, %4};" :: "l"(ptr), "f"(a), "f"(b), "f"(c), "f"(d) : "memory")

// ---------------- setupA: weight packing (13 blocks, main stream) ----------------
__global__ void setupA(const float* __restrict__ a_in, const float* __restrict__ a_out,
                       const float* __restrict__ a_o,
                       const float* __restrict__ a2_in, const float* __restrict__ a2_out,
                       const float* __restrict__ a2_o, const float* __restrict__ We) {
    int b = blockIdx.x, t = threadIdx.x;
    if (b < 4) {
        for (int idx = b * 256 + t; idx < 512 * 64; idx += 4 * 256) {
            int n = idx >> 6, k = idx & 63;
            int dir = n >> 8, role = (n >> 7) & 1, h = (n >> 6) & 1, j = n & 63;
            const float* A = (dir ? a_out : a_in) + (size_t)h * 64 * 192;
            g_Wp1[idx] = A[j * 192 + role * 64 + k];
        }
    } else if (b < 6) {
        for (int idx = (b - 4) * 256 + t; idx < 256 * 64; idx += 2 * 256) {
            int n = idx >> 6, k = idx & 63;
            int c = n >> 6, j = n & 63;
            const float* A = ((c >> 1) ? a_out : a_in) + (size_t)(c & 1) * 64 * 192;
            g_WpQ[idx] = A[j * 192 + 128 + k];
        }
    } else if (b < 10) {
        for (int idx = (b - 6) * 256 + t; idx < 256 * 128; idx += 4 * 256) {
            int n = idx >> 7, k = idx & 127;
            int role = n >> 7, j = n & 127;
            g_Wp2[idx] = a_o[j * 384 + role * 128 + k];
        }
    } else if (b < 12) {
        for (int idx = (b - 10) * 256 + t; idx < 64 * 128; idx += 2 * 256) {
            int j = idx >> 7, k = idx & 127;
            g_WeP[idx] = We[k * 64 + j];
        }
    } else {
        for (int n = t; n < 512; n += 256) {
            int dir = n >> 8, h = (n >> 6) & 1, j = n & 63;
            g_a2cat1[n] = (dir ? a2_out : a2_in)[h * 64 + j];
        }
        for (int n = t; n < 256; n += 256) {
            int c = n >> 6, j = n & 63;
            g_a2catQ[n] = ((c >> 1) ? a2_out : a2_in)[(c & 1) * 64 + j];
        }
        if (t < 256) g_a2cat2[t] = a2_o[t & 127];
    }
}

// ---------------- setupB: zero accumulators + relation tables (parallel stream) ------
__global__ void setupB(const float* __restrict__ a_in, const float* __restrict__ a_out,
                       const float* __restrict__ a_o,
                       const float* __restrict__ a2_in, const float* __restrict__ a2_out,
                       const float* __restrict__ a2_o,
                       const float* __restrict__ rel, const float* __restrict__ W,
                       float* __restrict__ out_tail) {
    int b = blockIdx.x, t = threadIdx.x;
    if (b < 512) {
        size_t tid = (size_t)b * 256 + t, stride = (size_t)512 * 256;
        float4 z = make_float4(0.f, 0.f, 0.f, 0.f);
        float4* hp1 = (float4*)&g_hp1[0][0];
        for (size_t i = tid; i < (size_t)2 * N_NODES * 32; i += stride) hp1[i] = z;
        float4* hp2 = (float4*)&g_hp2[0][0];
        for (size_t i = tid; i < (size_t)2 * N_NODES * 32; i += stride) hp2[i] = z;
        float4* rs1 = (float4*)&g_rowsum1T[0];
        for (size_t i = tid; i < (size_t)N_NODES; i += stride) rs1[i] = z;
        float4* rs2 = (float4*)&g_rowsum2[0][0];
        for (size_t i = tid; i < (size_t)N_NODES / 2; i += stride) rs2[i] = z;
        if (tid < 2) g_wsum[tid] = 0.f;
    } else {
        int r = b - 512;  // [0, 200)
        __shared__ float relrow[64];
        __shared__ float rel2row[128];
        __shared__ float red[8];
        if (t < 64) relrow[t] = rel[r * 64 + t];
        __syncthreads();
        if (t < 128) {
            float acc = 0.f;
            #pragma unroll
            for (int k = 0; k < 64; k++) acc += relrow[k] * W[k * 128 + t];
            rel2row[t] = acc;
            out_tail[(size_t)N_NODES * OUTF + r * 128 + t] = acc;
        }
        __syncthreads();
        {
            int c = t >> 6, j = t & 63;
            const float* A = ((c >> 1) ? a_out : a_in) + (size_t)(c & 1) * 64 * 192;
            float acc = 0.f;
            #pragma unroll
            for (int k = 0; k < 64; k++) acc += relrow[k] * A[j * 192 + 128 + k];
            g_R1proj[r * 256 + t] = acc;
            float part = acc * ((c >> 1) ? a2_out : a2_in)[(c & 1) * 64 + j];
            #pragma unroll
            for (int o = 16; o; o >>= 1) part += __shfl_xor_sync(0xffffffffu, part, o);
            if ((t & 31) == 0) red[t >> 5] = part;
        }
        __syncthreads();
        if (t < 4) g_Sr1[r * 4 + t] = red[2 * t] + red[2 * t + 1];
        __syncthreads();
        {
            float part = 0.f;
            if (t < 128) {
                float acc = 0.f;
                #pragma unroll 16
                for (int k = 0; k < 128; k++) acc += rel2row[k] * a_o[t * 384 + 256 + k];
                g_R2proj[r * 128 + t] = acc;
                part = acc * a2_o[t];
            }
            #pragma unroll
            for (int o = 16; o; o >>= 1) part += __shfl_xor_sync(0xffffffffu, part, o);
            if ((t & 31) == 0 && t < 128) red[t >> 5] = part;
        }
        __syncthreads();
        if (t == 0) g_Srel2[r] = red[0] + red[1] + red[2] + red[3];
    }
}

// ---------------- f32x2 GEMM (projection variant, register prefetch) ----------------
#define KC 16
__global__ void __launch_bounds__(256, 2)
gemm_f32x2(const float* __restrict__ X,
           const float* __restrict__ Wp,
           float* __restrict__ C,
           const float* __restrict__ a2cat,
           float* __restrict__ sOut,
           int M, int N, int K) {
    __shared__ __align__(16) float2 Xs2[KC][130];
    __shared__ __align__(16) float  As[KC][132];
    int t = threadIdx.x;
    int tx = t & 15, ty = t >> 4;
    int ib = blockIdx.x * 128;
    int jb = blockIdx.y * 128;
    ull acc[8][4];
    #pragma unroll
    for (int ii = 0; ii < 8; ii++)
        #pragma unroll
        for (int q = 0; q < 4; q++) acc[ii][q] = 0ull;

    float4 xb[2], ab[2];
    int pi0 = t & 127, pk0 = (t >> 7) * 4;
    int pk1 = pk0 + 8;
    {
        int gi = ib + pi0;
        xb[0] = make_float4(0.f, 0.f, 0.f, 0.f);
        xb[1] = make_float4(0.f, 0.f, 0.f, 0.f);
        if (gi < M) {
            xb[0] = *(const float4*)&X[(size_t)gi * K + pk0];
            xb[1] = *(const float4*)&X[(size_t)gi * K + pk1];
        }
        ab[0] = *(const float4*)&Wp[(size_t)(jb + pi0) * K + pk0];
        ab[1] = *(const float4*)&Wp[(size_t)(jb + pi0) * K + pk1];
    }

    for (int kc = 0; kc < K; kc += KC) {
        #pragma unroll
        for (int u = 0; u < 2; u++) {
            int kq = u ? pk1 : pk0;
            float4 v = xb[u];
            Xs2[kq + 0][pi0] = make_float2(v.x, v.x);
            Xs2[kq + 1][pi0] = make_float2(v.y, v.y);
            Xs2[kq + 2][pi0] = make_float2(v.z, v.z);
            Xs2[kq + 3][pi0] = make_float2(v.w, v.w);
            float4 a = ab[u];
            As[kq + 0][pi0] = a.x; As[kq + 1][pi0] = a.y;
            As[kq + 2][pi0] = a.z; As[kq + 3][pi0] = a.w;
        }
        __syncthreads();
        if (kc + KC < K) {
            int gi = ib + pi0;
            xb[0] = make_float4(0.f, 0.f, 0.f, 0.f);
            xb[1] = make_float4(0.f, 0.f, 0.f, 0.f);
            if (gi < M) {
                xb[0] = *(const float4*)&X[(size_t)gi * K + kc + KC + pk0];
                xb[1] = *(const float4*)&X[(size_t)gi * K + kc + KC + pk1];
            }
            ab[0] = *(const float4*)&Wp[(size_t)(jb + pi0) * K + kc + KC + pk0];
            ab[1] = *(const float4*)&Wp[(size_t)(jb + pi0) * K + kc + KC + pk1];
        }
        #pragma unroll
        for (int kk = 0; kk < KC; kk++) {
            ull av[4];
            #pragma unroll
            for (int q = 0; q < 4; q++)
                av[q] = *(const ull*)&As[kk][2 * (tx + 16 * q)];
            #pragma unroll
            for (int ii = 0; ii < 8; ii++) {
                ull xx = *(const ull*)&Xs2[kk][ty * 8 + ii];
                #pragma unroll
                for (int q = 0; q < 4; q++)
                    asm("fma.rn.f32x2 %0, %1, %2, %0;"
                        : "+l"(acc[ii][q]) : "l"(xx), "l"(av[q]));
            }
        }
        __syncthreads();
    }
    int nBlk = N >> 6;
    float2 w[4];
    #pragma unroll
    for (int q = 0; q < 4; q++)
        w[q] = *(const float2*)&a2cat[jb + 2 * (tx + 16 * q)];
    #pragma unroll
    for (int ii = 0; ii < 8; ii++) {
        int gi = ib + ty * 8 + ii;
        float lo[4], hi[4];
        #pragma unroll
        for (int q = 0; q < 4; q++)
            asm("mov.b64 {%0, %1}, %2;" : "=f"(lo[q]), "=f"(hi[q]) : "l"(acc[ii][q]));
        if (gi < M) {
            #pragma unroll
            for (int q = 0; q < 4; q++)
                *(float2*)&C[(size_t)gi * N + jb + 2 * (tx + 16 * q)] = make_float2(lo[q], hi[q]);
        }
        float s0 = lo[0] * w[0].x + hi[0] * w[0].y + lo[1] * w[1].x + hi[1] * w[1].y;
        float s1 = lo[2] * w[2].x + hi[2] * w[2].y + lo[3] * w[3].x + hi[3] * w[3].y;
        #pragma unroll
        for (int o = 8; o; o >>= 1) {
            s0 += __shfl_xor_sync(0xffffffffu, s0, o);
            s1 += __shfl_xor_sync(0xffffffffu, s1, o);
        }
        if (tx == 0 && gi < M) {
            size_t base = (size_t)gi * nBlk + (jb >> 6);
            sOut[base] = s0;
            sOut[base + 1] = s1;
        }
    }
}

// ---------------- gemm_x2: layer-2 projection with FUSED norm1 in the X loader ------
__global__ void __launch_bounds__(256, 2)
gemm_x2(float* __restrict__ C, const float* __restrict__ a2cat,
        float* __restrict__ sOut) {
    __shared__ __align__(16) float2 Xs2[KC][130];
    __shared__ __align__(16) float  As[KC][132];
    int t = threadIdx.x;
    int tx = t & 15, ty = t >> 4;
    int ib = blockIdx.x * 128;
    int jb = blockIdx.y * 128;
    const int M = 2 * N_NODES, N = 256, K = 128;
    ull acc[8][4];
    #pragma unroll
    for (int ii = 0; ii < 8; ii++)
        #pragma unroll
        for (int q = 0; q < 4; q++) acc[ii][q] = 0ull;

    for (int kc = 0; kc < K; kc += KC) {
        #pragma unroll
        for (int p = t; p < 512; p += 256) {
            int i = p & 127, kq = (p >> 7) * 4;
            int gi = ib + i;
            float4 v = make_float4(0.f, 0.f, 0.f, 0.f);
            if (gi < M) {
                int dir = gi >= N_NODES;
                int i2 = dir ? gi - N_NODES : gi;
                int kk = kc + kq;
                float rs = g_rowsum1T[(size_t)i2 * 4 + dir * 2 + (kk >> 6)];
                if (rs > 0.f) {
                    float inv = 1.f / rs;
                    float4 hv = *(const float4*)&g_hp1[dir][(size_t)i2 * 128 + kk];
                    float4 pv = *(const float4*)&g_P1all[(size_t)i2 * 512 + dir * 256 + kk];
                    v.x = hv.x * inv + pv.x;
                    v.y = hv.y * inv + pv.y;
                    v.z = hv.z * inv + pv.z;
                    v.w = hv.w * inv + pv.w;
                }
                v.x = (v.x > 0.f) ? v.x : expm1f(v.x);
                v.y = (v.y > 0.f) ? v.y : expm1f(v.y);
                v.z = (v.z > 0.f) ? v.z : expm1f(v.z);
                v.w = (v.w > 0.f) ? v.w : expm1f(v.w);
            }
            Xs2[kq + 0][i] = make_float2(v.x, v.x);
            Xs2[kq + 1][i] = make_float2(v.y, v.y);
            Xs2[kq + 2][i] = make_float2(v.z, v.z);
            Xs2[kq + 3][i] = make_float2(v.w, v.w);
        }
        #pragma unroll
        for (int p = t; p < 512; p += 256) {
            int j = p & 127, kq = (p >> 7) * 4;
            float4 v = *(const float4*)&g_Wp2[(size_t)(jb + j) * K + kc + kq];
            As[kq + 0][j] = v.x; As[kq + 1][j] = v.y;
            As[kq + 2][j] = v.z; As[kq + 3][j] = v.w;
        }
        __syncthreads();
        #pragma unroll
        for (int kk = 0; kk < KC; kk++) {
            ull av[4];
            #pragma unroll
            for (int q = 0; q < 4; q++)
                av[q] = *(const ull*)&As[kk][2 * (tx + 16 * q)];
            #pragma unroll
            for (int ii = 0; ii < 8; ii++) {
                ull xx = *(const ull*)&Xs2[kk][ty * 8 + ii];
                #pragma unroll
                for (int q = 0; q < 4; q++)
                    asm("fma.rn.f32x2 %0, %1, %2, %0;"
                        : "+l"(acc[ii][q]) : "l"(xx), "l"(av[q]));
            }
        }
        __syncthreads();
    }
    int nBlk = N >> 6;
    float2 w[4];
    #pragma unroll
    for (int q = 0; q < 4; q++)
        w[q] = *(const float2*)&a2cat[jb + 2 * (tx + 16 * q)];
    #pragma unroll
    for (int ii = 0; ii < 8; ii++) {
        int gi = ib + ty * 8 + ii;
        float lo[4], hi[4];
        #pragma unroll
        for (int q = 0; q < 4; q++)
            asm("mov.b64 {%0, %1}, %2;" : "=f"(lo[q]), "=f"(hi[q]) : "l"(acc[ii][q]));
        if (gi < M) {
            #pragma unroll
            for (int q = 0; q < 4; q++)
                *(float2*)&C[(size_t)gi * N + jb + 2 * (tx + 16 * q)] = make_float2(lo[q], hi[q]);
        }
        float s0 = lo[0] * w[0].x + hi[0] * w[0].y + lo[1] * w[1].x + hi[1] * w[1].y;
        float s1 = lo[2] * w[2].x + hi[2] * w[2].y + lo[3] * w[3].x + hi[3] * w[3].y;
        #pragma unroll
        for (int o = 8; o; o >>= 1) {
            s0 += __shfl_xor_sync(0xffffffffu, s0, o);
            s1 += __shfl_xor_sync(0xffffffffu, s1, o);
        }
        if (tx == 0 && gi < M) {
            size_t base = (size_t)gi * nBlk + (jb >> 6);
            sOut[base] = s0;
            sOut[base + 1] = s1;
        }
    }
}

// ---------------- gemm_q: contiguous-4 columns (LDS.128/RED4/LDG.128), 3 CTAs/SM ----
__global__ void __launch_bounds__(256, 3)
gemm_q(const float* __restrict__ X, const int* __restrict__ el,
       const int* __restrict__ eln, const int* __restrict__ etn) {
    __shared__ __align__(16) float2 Xs2[KC][66];
    __shared__ __align__(16) float  As[KC][132];
    int t = threadIdx.x;
    int dir = blockIdx.y;

    if (blockIdx.x >= QBLK64) {
        // ---- nhop edge pass ----
        int e = (blockIdx.x - QBLK64) * 8 + (t >> 5);   // [0, E_NHOP)
        int lane = t & 31;
        int h = lane >> 4;
        int jj = 4 * (lane & 15);
        int i0 = eln[e], i1 = eln[E_NHOP + e];
        int t0 = etn[2 * e], t1 = etn[2 * e + 1];
        float4 qa = *(const float4*)&g_R1proj[t0 * 256 + dir * 128 + h * 64 + jj];
        float4 qb = *(const float4*)&g_R1proj[t1 * 256 + dir * 128 + h * 64 + jj];
        float4 q;
        q.x = qa.x + qb.x; q.y = qa.y + qb.y; q.z = qa.z + qb.z; q.w = qa.w + qb.w;
        float sq = g_Sr1[t0 * 4 + dir * 2 + h] + g_Sr1[t1 * 4 + dir * 2 + h];
        int src = dir ? i1 : i0;
        int dst = dir ? i0 : i1;
        float score = g_S1[(size_t)src * 8 + dir * 4 + h]
                    + g_S1[(size_t)dst * 8 + dir * 4 + 2 + h] + sq;
        float lk = score > 0.f ? score : ALPHA * score;
        float ev = __expf(-lk);
        float4 d = *(const float4*)&g_P1all[(size_t)dst * 512 + dir * 256 + 128 + h * 64 + jj];
        float* hp = &g_hp1[dir][(size_t)src * 128 + h * 64 + jj];
        RED4(hp, ev * (d.x + q.x), ev * (d.y + q.y), ev * (d.z + q.z), ev * (d.w + q.w));
        if ((lane & 15) == 0) atomicAdd(&g_rowsum1T[(size_t)src * 4 + dir * 2 + h], ev);
        return;
    }

    int tx = t & 15, ty = t >> 4;   // ty 0..15, 4 rows each -> 64 rows
    int ib = blockIdx.x * 64;
    int jb = dir * 128;
    const int M = E_REAL, K = 64;
    // acc[ii][0..1]: cols 4tx..4tx+3 (h0); acc[ii][2..3]: cols 4tx+64..+67 (h1)
    ull acc[4][4];
    #pragma unroll
    for (int ii = 0; ii < 4; ii++)
        #pragma unroll
        for (int q = 0; q < 4; q++) acc[ii][q] = 0ull;

    for (int kc = 0; kc < K; kc += KC) {
        {
            int i = t & 63, kq = (t >> 6) * 4;
            int gi = ib + i;
            float4 v = make_float4(0.f, 0.f, 0.f, 0.f);
            if (gi < M) v = *(const float4*)&X[(size_t)gi * K + kc + kq];
            Xs2[kq + 0][i] = make_float2(v.x, v.x);
            Xs2[kq + 1][i] = make_float2(v.y, v.y);
            Xs2[kq + 2][i] = make_float2(v.z, v.z);
            Xs2[kq + 3][i] = make_float2(v.w, v.w);
        }
        #pragma unroll
        for (int p = t; p < 512; p += 256) {
            int j = p & 127, kq = (p >> 7) * 4;
            float4 v = *(const float4*)&g_WpQ[(size_t)(jb + j) * K + kc + kq];
            As[kq + 0][j] = v.x; As[kq + 1][j] = v.y;
            As[kq + 2][j] = v.z; As[kq + 3][j] = v.w;
        }
        __syncthreads();
        #pragma unroll
        for (int kk = 0; kk < KC; kk++) {
            ulonglong2 a01 = *(const ulonglong2*)&As[kk][4 * tx];
            ulonglong2 a23 = *(const ulonglong2*)&As[kk][4 * tx + 64];
            #pragma unroll
            for (int ii = 0; ii < 4; ii++) {
                ull xx = *(const ull*)&Xs2[kk][ty * 4 + ii];
                asm("fma.rn.f32x2 %0, %1, %2, %0;" : "+l"(acc[ii][0]) : "l"(xx), "l"(a01.x));
                asm("fma.rn.f32x2 %0, %1, %2, %0;" : "+l"(acc[ii][1]) : "l"(xx), "l"(a01.y));
                asm("fma.rn.f32x2 %0, %1, %2, %0;" : "+l"(acc[ii][2]) : "l"(xx), "l"(a23.x));
                asm("fma.rn.f32x2 %0, %1, %2, %0;" : "+l"(acc[ii][3]) : "l"(xx), "l"(a23.y));
            }
        }
        __syncthreads();
    }
    // epilogue: fused real-edge attention scatter (contiguous-4, RED4)
    float4 w0 = *(const float4*)&g_a2catQ[jb + 4 * tx];         // h0 cols
    float4 w1 = *(const float4*)&g_a2catQ[jb + 4 * tx + 64];    // h1 cols
    #pragma unroll
    for (int ii = 0; ii < 4; ii++) {
        int gi = ib + ty * 4 + ii;   // edge index
        float f[8];
        #pragma unroll
        for (int q = 0; q < 4; q++)
            asm("mov.b64 {%0, %1}, %2;" : "=f"(f[2 * q]), "=f"(f[2 * q + 1]) : "l"(acc[ii][q]));
        float s0 = f[0] * w0.x + f[1] * w0.y + f[2] * w0.z + f[3] * w0.w;
        float s1 = f[4] * w1.x + f[5] * w1.y + f[6] * w1.z + f[7] * w1.w;
        #pragma unroll
        for (int o = 8; o; o >>= 1) {
            s0 += __shfl_xor_sync(0xffffffffu, s0, o);
            s1 += __shfl_xor_sync(0xffffffffu, s1, o);
        }
        if (gi < M) {
            int i0 = el[gi], i1 = el[E_REAL + gi];
            int src = dir ? i1 : i0;
            int dst = dir ? i0 : i1;
            float4 sv = *(const float4*)&g_S1[(size_t)src * 8 + dir * 4];
            float4 dv = *(const float4*)&g_S1[(size_t)dst * 8 + dir * 4];
            float sc0 = sv.x + dv.z + s0;
            float sc1 = sv.y + dv.w + s1;
            float lk0 = sc0 > 0.f ? sc0 : ALPHA * sc0;
            float lk1 = sc1 > 0.f ? sc1 : ALPHA * sc1;
            float ev0 = __expf(-lk0);
            float ev1 = __expf(-lk1);
            const float* pd = &g_P1all[(size_t)dst * 512 + dir * 256 + 128];
            float* hp = &g_hp1[dir][(size_t)src * 128];
            float4 d0 = *(const float4*)&pd[4 * tx];
            float4 d1 = *(const float4*)&pd[4 * tx + 64];
            RED4(&hp[4 * tx],
                 ev0 * (d0.x + f[0]), ev0 * (d0.y + f[1]),
                 ev0 * (d0.z + f[2]), ev0 * (d0.w + f[3]));
            RED4(&hp[4 * tx + 64],
                 ev1 * (d1.x + f[4]), ev1 * (d1.y + f[5]),
                 ev1 * (d1.z + f[6]), ev1 * (d1.w + f[7]));
            if (tx == 0) {
                atomicAdd(&g_rowsum1T[(size_t)src * 4 + dir * 2], ev0);
                atomicAdd(&g_rowsum1T[(size_t)src * 4 + dir * 2 + 1], ev1);
            }
        }
    }
}

// ---------------- gemm_we: norm2 fused into loader + tanh-dot epilogue ----------------
__global__ void __launch_bounds__(256, 2)
gemm_we(const float* __restrict__ be, const float* __restrict__ qe) {
    __shared__ __align__(16) float2 Xs2[KC][130];
    __shared__ __align__(16) float  As[KC][68];
    __shared__ float s_sh[2];
    int t = threadIdx.x;
    int tx = t & 7, ty = t >> 3;
    int lane = t & 31;
    int ib = blockIdx.x * 128;
    const int M = 2 * N_NODES;
    if (t < 2) s_sh[t] = 0.f;
    const float* hp2f = &g_hp2[0][0];
    const float* rs2f = &g_rowsum2[0][0];
    float* yf = &g_y[0][0];
    ull acc[4][4];
    #pragma unroll
    for (int ii = 0; ii < 4; ii++)
        #pragma unroll
        for (int q = 0; q < 4; q++) acc[ii][q] = 0ull;

    for (int kc = 0; kc < 128; kc += KC) {
        #pragma unroll
        for (int p = t; p < 512; p += 256) {
            int i = p & 127, kq = (p >> 7) * 4;
            int gi = ib + i;
            float4 v = make_float4(0.f, 0.f, 0.f, 0.f);
            if (gi < M) {
                int xs = gi >= N_NODES;
                int ii2 = xs ? gi - N_NODES : gi;
                float rs = rs2f[gi];
                if (rs > 0.f) {
                    float inv = 1.f / rs;
                    float4 hv = *(const float4*)&hp2f[(size_t)gi * 128 + kc + kq];
                    float4 pv = *(const float4*)&g_P2all[xs][(size_t)ii2 * 256 + kc + kq];
                    v.x = hv.x * inv + pv.x;
                    v.y = hv.y * inv + pv.y;
                    v.z = hv.z * inv + pv.z;
                    v.w = hv.w * inv + pv.w;
                }
                v.x = (v.x > 0.f) ? v.x : expm1f(v.x);
                v.y = (v.y > 0.f) ? v.y : expm1f(v.y);
                v.z = (v.z > 0.f) ? v.z : expm1f(v.z);
                v.w = (v.w > 0.f) ? v.w : expm1f(v.w);
                *(float4*)&yf[(size_t)gi * 128 + kc + kq] = v;
            }
            Xs2[kq + 0][i] = make_float2(v.x, v.x);
            Xs2[kq + 1][i] = make_float2(v.y, v.y);
            Xs2[kq + 2][i] = make_float2(v.z, v.z);
            Xs2[kq + 3][i] = make_float2(v.w, v.w);
        }
        {
            int j = t & 63, kq = ((t >> 6) & 3) * 4;
            float4 w = *(const float4*)&g_WeP[j * 128 + kc + kq];
            As[kq + 0][j] = w.x; As[kq + 1][j] = w.y;
            As[kq + 2][j] = w.z; As[kq + 3][j] = w.w;
        }
        __syncthreads();
        #pragma unroll
        for (int kk = 0; kk < KC; kk++) {
            ull av[4];
            #pragma unroll
            for (int q = 0; q < 4; q++)
                av[q] = *(const ull*)&As[kk][2 * (tx + 8 * q)];
            #pragma unroll
            for (int ii = 0; ii < 4; ii++) {
                ull xx = *(const ull*)&Xs2[kk][ty * 4 + ii];
                #pragma unroll
                for (int q = 0; q < 4; q++)
                    asm("fma.rn.f32x2 %0, %1, %2, %0;"
                        : "+l"(acc[ii][q]) : "l"(xx), "l"(av[q]));
            }
        }
        __syncthreads();
    }
    float2 bb[4], qq[4];
    #pragma unroll
    for (int q = 0; q < 4; q++) {
        bb[q] = *(const float2*)&be[2 * (tx + 8 * q)];
        qq[q] = *(const float2*)&qe[2 * (tx + 8 * q)];
    }
    #pragma unroll
    for (int ii = 0; ii < 4; ii++) {
        int gi = ib + ty * 4 + ii;
        float lo[4], hi[4];
        #pragma unroll
        for (int q = 0; q < 4; q++)
            asm("mov.b64 {%0, %1}, %2;" : "=f"(lo[q]), "=f"(hi[q]) : "l"(acc[ii][q]));
        float s = 0.f;
        #pragma unroll
        for (int q = 0; q < 4; q++)
            s += tanhf(lo[q] + bb[q].x) * qq[q].x + tanhf(hi[q] + bb[q].y) * qq[q].y;
        #pragma unroll
        for (int o = 4; o; o >>= 1) s += __shfl_xor_sync(0xffffffffu, s, o);
        if ((lane & 7) == 0 && gi < M)
            atomicAdd(&s_sh[gi >= N_NODES], s);
    }
    __syncthreads();
    if (t < 2) atomicAdd(&g_wsum[t], s_sh[t]);
}

// ---------------- layer-2 edge pass ----------------
__global__ void edge_pass2(const int* __restrict__ el, const int* __restrict__ eln,
                           const int* __restrict__ et, const int* __restrict__ etn) {
    int dir = blockIdx.y;
    int e = blockIdx.x * 8 + (threadIdx.x >> 5);
    if (e >= E_ALL) return;
    int lane = threadIdx.x & 31;
    int i0, i1;
    float q0, q1, q2, q3, sq;
    if (e < E_REAL) {
        i0 = el[e]; i1 = el[E_REAL + e];
        int ty = et[e];
        float4 qv = *(const float4*)&g_R2proj[ty * 128 + 4 * lane];
        q0 = qv.x; q1 = qv.y; q2 = qv.z; q3 = qv.w;
        sq = g_Srel2[ty];
    } else {
        int en = e - E_REAL;
        i0 = eln[en]; i1 = eln[E_NHOP + en];
        int t0 = etn[2 * en], t1 = etn[2 * en + 1];
        float4 qa = *(const float4*)&g_R2proj[t0 * 128 + 4 * lane];
        float4 qb = *(const float4*)&g_R2proj[t1 * 128 + 4 * lane];
        q0 = qa.x + qb.x; q1 = qa.y + qb.y; q2 = qa.z + qb.z; q3 = qa.w + qb.w;
        sq = g_Srel2[t0] + g_Srel2[t1];
    }
    int seg = dir ? i1 : i0;
    int nbr = dir ? i0 : i1;
    float4 sA = *(const float4*)&g_S2[dir][(size_t)seg * 4];
    float4 sB = *(const float4*)&g_S2[dir][(size_t)nbr * 4];
    float score = sA.x + sA.y + sB.z + sB.w + sq;
    float lk = score > 0.f ? score : ALPHA * score;
    float ev = __expf(-lk);
    float4 dv = *(const float4*)&g_P2all[dir][(size_t)nbr * 256 + 128 + 4 * lane];
    float* hp = &g_hp2[dir][(size_t)seg * 128 + 4 * lane];
    RED4(hp, ev * (dv.x + q0), ev * (dv.y + q1), ev * (dv.z + q2), ev * (dv.w + q3));
    if (lane == 0) atomicAdd(&g_rowsum2[dir][seg], ev);
}

// ---------------- beta + combine ----------------
__global__ void combine(float* __restrict__ out) {
    float m0 = g_wsum[0] / (float)N_NODES;
    float m1 = g_wsum[1] / (float)N_NODES;
    float mx = fmaxf(m0, m1);
    float e0 = expf(m0 - mx), e1 = expf(m1 - mx);
    float b0 = e0 / (e0 + e1), b1 = e1 / (e0 + e1);
    size_t i = (size_t)blockIdx.x * 256 + threadIdx.x;
    if (i >= (size_t)N_NODES * OUTF) return;
    out[i] = b0 * g_y[0][i] + b1 * g_y[1][i];
}

// ---------------- launch ----------------
extern "C" void kernel_launch(void* const* d_in, const int* in_sizes, int n_in,
                              void* d_out, int out_size) {
    const float* ent   = (const float*)d_in[0];
    const float* rel   = (const float*)d_in[1];
    const int*   el    = (const int*)d_in[2];
    const int*   et    = (const int*)d_in[3];
    const float* eemb  = (const float*)d_in[4];
    const int*   eln   = (const int*)d_in[5];
    const int*   etn   = (const int*)d_in[6];
    const float* a_in  = (const float*)d_in[7];
    const float* a2_in = (const float*)d_in[8];
    const float* a_out = (const float*)d_in[9];
    const float* a2_out= (const float*)d_in[10];
    const float* a_o   = (const float*)d_in[11];
    const float* a2_o  = (const float*)d_in[12];
    const float* W     = (const float*)d_in[13];
    const float* We    = (const float*)d_in[14];
    const float* be    = (const float*)d_in[15];
    const float* qe    = (const float*)d_in[16];
    float* out = (float*)d_out;

    float *p1 = 0, *p2 = 0, *wp1 = 0;
    float *a2c1 = 0, *a2c2 = 0, *s1 = 0, *s2 = 0;
    cudaGetSymbolAddress((void**)&p1, g_P1all);
    cudaGetSymbolAddress((void**)&p2, g_P2all);
    cudaGetSymbolAddress((void**)&wp1, g_Wp1);
    cudaGetSymbolAddress((void**)&a2c1, g_a2cat1);
    cudaGetSymbolAddress((void**)&a2c2, g_a2cat2);
    cudaGetSymbolAddress((void**)&s1, g_S1);
    cudaGetSymbolAddress((void**)&s2, g_S2);

    cudaStream_t sB;
    cudaStreamCreateWithFlags(&sB, cudaStreamNonBlocking);
    cudaEvent_t evFork, evJoin;
    cudaEventCreateWithFlags(&evFork, cudaEventDisableTiming);
    cudaEventCreateWithFlags(&evJoin, cudaEventDisableTiming);

    cudaEventRecord(evFork, 0);
    cudaStreamWaitEvent(sB, evFork, 0);
    setupB<<<712, 256, 0, sB>>>(a_in, a_out, a_o, a2_in, a2_out, a2_o, rel, W, out);
    cudaEventRecord(evJoin, sB);

    setupA<<<13, 256>>>(a_in, a_out, a_o, a2_in, a2_out, a2_o, We);
    gemm_f32x2<<<dim3((N_NODES + 127) / 128, 4), 256>>>(ent, wp1, p1, a2c1, s1,
                                                        N_NODES, 512, 64);
    cudaStreamWaitEvent(0, evJoin, 0);

    gemm_q<<<dim3(QBLK64 + E_NHOP / 8, 2), 256>>>(eemb, el, eln, etn);

    gemm_x2<<<dim3((2 * N_NODES + 127) / 128, 2), 256>>>(p2, a2c2, s2);

    edge_pass2<<<dim3(E_ALL / 8, 2), 256>>>(el, eln, et, etn);

    gemm_we<<<(2 * N_NODES + 127) / 128, 256>>>(be, qe);
    combine<<<(N_NODES * OUTF + 255) / 256, 256>>>(out);

    cudaStreamDestroy(sB);
    cudaEventDestroy(evFork);
    cudaEventDestroy(evJoin);
}

// round 17
// speedup vs baseline: 1.2382x; 1.0030x over previous
#include <cuda_runtime.h>
#include <math.h>

#define N_NODES 50000
#define NFEAT   64
#define NHID    64
#define E_REAL  200000
#define E_NHOP  40000
#define E_ALL   240000
#define N_REL   200
#define OUTF    128
#define ALPHA   0.2f
#define QBLK64  3125   // (E_REAL+63)/64

typedef unsigned long long ull;

// ---------------- device scratch ----------------
__device__ __align__(16) float g_P1all[(size_t)N_NODES * 512];     // [i][dir*256+role*128+h*64+j]
__device__ __align__(16) float g_R1proj[N_REL * 256];              // [r*256 + c*64 + j]
__device__ __align__(16) float g_R2proj[N_REL * OUTF];
__device__ __align__(16) float g_rowsum1T[(size_t)N_NODES * 4];    // [i*4 + dir*2 + h]
__device__ __align__(16) float g_hp1[2][(size_t)N_NODES * 128];
__device__ __align__(16) float g_P2all[2][(size_t)N_NODES * 256];
__device__ float g_rowsum2[2][N_NODES];
__device__ __align__(16) float g_hp2[2][(size_t)N_NODES * OUTF];
__device__ __align__(16) float g_y[2][(size_t)N_NODES * OUTF];
__device__ float g_wsum[2];
// packed weights (row-major [n][K])
__device__ __align__(16) float g_Wp1[512 * 64];
__device__ __align__(16) float g_WpQ[256 * 64];
__device__ __align__(16) float g_Wp2[256 * 128];
__device__ __align__(16) float g_WeP[64 * 128];                    // [j][k]
// factorized attention scalars
__device__ __align__(16) float g_S1[(size_t)N_NODES * 8];          // [i*8 + dir*4 + role*2 + h]
__device__ __align__(16) float g_Sr1[N_REL * 4];
__device__ __align__(16) float g_S2[2][(size_t)N_NODES * 4];
__device__ float g_Srel2[N_REL];
// per-column dot weights
__device__ __align__(16) float g_a2cat1[512];
__device__ __align__(16) float g_a2catQ[256];
__device__ __align__(16) float g_a2cat2[256];

#define RED4(ptr, a, b, c, d) \
    asm volatile("red.global.add.v4.f32 [%0], {%1, %2, %3, %4};" :: "l"(ptr), "f"(a), "f"(b), "f"(c), "f"(d) : "memory")

// ---------------- setupA: weight packing (13 blocks, main stream) ----------------
__global__ void setupA(const float* __restrict__ a_in, const float* __restrict__ a_out,
                       const float* __restrict__ a_o,
                       const float* __restrict__ a2_in, const float* __restrict__ a2_out,
                       const float* __restrict__ a2_o, const float* __restrict__ We) {
    int b = blockIdx.x, t = threadIdx.x;
    if (b < 4) {
        for (int idx = b * 256 + t; idx < 512 * 64; idx += 4 * 256) {
            int n = idx >> 6, k = idx & 63;
            int dir = n >> 8, role = (n >> 7) & 1, h = (n >> 6) & 1, j = n & 63;
            const float* A = (dir ? a_out : a_in) + (size_t)h * 64 * 192;
            g_Wp1[idx] = A[j * 192 + role * 64 + k];
        }
    } else if (b < 6) {
        for (int idx = (b - 4) * 256 + t; idx < 256 * 64; idx += 2 * 256) {
            int n = idx >> 6, k = idx & 63;
            int c = n >> 6, j = n & 63;
            const float* A = ((c >> 1) ? a_out : a_in) + (size_t)(c & 1) * 64 * 192;
            g_WpQ[idx] = A[j * 192 + 128 + k];
        }
    } else if (b < 10) {
        for (int idx = (b - 6) * 256 + t; idx < 256 * 128; idx += 4 * 256) {
            int n = idx >> 7, k = idx & 127;
            int role = n >> 7, j = n & 127;
            g_Wp2[idx] = a_o[j * 384 + role * 128 + k];
        }
    } else if (b < 12) {
        for (int idx = (b - 10) * 256 + t; idx < 64 * 128; idx += 2 * 256) {
            int j = idx >> 7, k = idx & 127;
            g_WeP[idx] = We[k * 64 + j];
        }
    } else {
        for (int n = t; n < 512; n += 256) {
            int dir = n >> 8, h = (n >> 6) & 1, j = n & 63;
            g_a2cat1[n] = (dir ? a2_out : a2_in)[h * 64 + j];
        }
        for (int n = t; n < 256; n += 256) {
            int c = n >> 6, j = n & 63;
            g_a2catQ[n] = ((c >> 1) ? a2_out : a2_in)[(c & 1) * 64 + j];
        }
        if (t < 256) g_a2cat2[t] = a2_o[t & 127];
    }
}

// ---------------- setupB: zero accumulators + relation tables (parallel stream) ------
__global__ void setupB(const float* __restrict__ a_in, const float* __restrict__ a_out,
                       const float* __restrict__ a_o,
                       const float* __restrict__ a2_in, const float* __restrict__ a2_out,
                       const float* __restrict__ a2_o,
                       const float* __restrict__ rel, const float* __restrict__ W,
                       float* __restrict__ out_tail) {
    int b = blockIdx.x, t = threadIdx.x;
    if (b < 512) {
        size_t tid = (size_t)b * 256 + t, stride = (size_t)512 * 256;
        float4 z = make_float4(0.f, 0.f, 0.f, 0.f);
        float4* hp1 = (float4*)&g_hp1[0][0];
        for (size_t i = tid; i < (size_t)2 * N_NODES * 32; i += stride) hp1[i] = z;
        float4* hp2 = (float4*)&g_hp2[0][0];
        for (size_t i = tid; i < (size_t)2 * N_NODES * 32; i += stride) hp2[i] = z;
        float4* rs1 = (float4*)&g_rowsum1T[0];
        for (size_t i = tid; i < (size_t)N_NODES; i += stride) rs1[i] = z;
        float4* rs2 = (float4*)&g_rowsum2[0][0];
        for (size_t i = tid; i < (size_t)N_NODES / 2; i += stride) rs2[i] = z;
        if (tid < 2) g_wsum[tid] = 0.f;
    } else {
        int r = b - 512;  // [0, 200)
        __shared__ float relrow[64];
        __shared__ float rel2row[128];
        __shared__ float red[8];
        if (t < 64) relrow[t] = rel[r * 64 + t];
        __syncthreads();
        if (t < 128) {
            float acc = 0.f;
            #pragma unroll
            for (int k = 0; k < 64; k++) acc += relrow[k] * W[k * 128 + t];
            rel2row[t] = acc;
            out_tail[(size_t)N_NODES * OUTF + r * 128 + t] = acc;
        }
        __syncthreads();
        {
            int c = t >> 6, j = t & 63;
            const float* A = ((c >> 1) ? a_out : a_in) + (size_t)(c & 1) * 64 * 192;
            float acc = 0.f;
            #pragma unroll
            for (int k = 0; k < 64; k++) acc += relrow[k] * A[j * 192 + 128 + k];
            g_R1proj[r * 256 + t] = acc;
            float part = acc * ((c >> 1) ? a2_out : a2_in)[(c & 1) * 64 + j];
            #pragma unroll
            for (int o = 16; o; o >>= 1) part += __shfl_xor_sync(0xffffffffu, part, o);
            if ((t & 31) == 0) red[t >> 5] = part;
        }
        __syncthreads();
        if (t < 4) g_Sr1[r * 4 + t] = red[2 * t] + red[2 * t + 1];
        __syncthreads();
        {
            float part = 0.f;
            if (t < 128) {
                float acc = 0.f;
                #pragma unroll 16
                for (int k = 0; k < 128; k++) acc += rel2row[k] * a_o[t * 384 + 256 + k];
                g_R2proj[r * 128 + t] = acc;
                part = acc * a2_o[t];
            }
            #pragma unroll
            for (int o = 16; o; o >>= 1) part += __shfl_xor_sync(0xffffffffu, part, o);
            if ((t & 31) == 0 && t < 128) red[t >> 5] = part;
        }
        __syncthreads();
        if (t == 0) g_Srel2[r] = red[0] + red[1] + red[2] + red[3];
    }
}

// ---------------- f32x2 GEMM (projection variant, register prefetch) ----------------
#define KC 16
__global__ void __launch_bounds__(256, 2)
gemm_f32x2(const float* __restrict__ X,
           const float* __restrict__ Wp,
           float* __restrict__ C,
           const float* __restrict__ a2cat,
           float* __restrict__ sOut,
           int M, int N, int K) {
    __shared__ __align__(16) float2 Xs2[KC][130];
    __shared__ __align__(16) float  As[KC][132];
    int t = threadIdx.x;
    int tx = t & 15, ty = t >> 4;
    int ib = blockIdx.x * 128;
    int jb = blockIdx.y * 128;
    ull acc[8][4];
    #pragma unroll
    for (int ii = 0; ii < 8; ii++)
        #pragma unroll
        for (int q = 0; q < 4; q++) acc[ii][q] = 0ull;

    float4 xb[2], ab[2];
    int pi0 = t & 127, pk0 = (t >> 7) * 4;
    int pk1 = pk0 + 8;
    {
        int gi = ib + pi0;
        xb[0] = make_float4(0.f, 0.f, 0.f, 0.f);
        xb[1] = make_float4(0.f, 0.f, 0.f, 0.f);
        if (gi < M) {
            xb[0] = *(const float4*)&X[(size_t)gi * K + pk0];
            xb[1] = *(const float4*)&X[(size_t)gi * K + pk1];
        }
        ab[0] = *(const float4*)&Wp[(size_t)(jb + pi0) * K + pk0];
        ab[1] = *(const float4*)&Wp[(size_t)(jb + pi0) * K + pk1];
    }

    for (int kc = 0; kc < K; kc += KC) {
        #pragma unroll
        for (int u = 0; u < 2; u++) {
            int kq = u ? pk1 : pk0;
            float4 v = xb[u];
            Xs2[kq + 0][pi0] = make_float2(v.x, v.x);
            Xs2[kq + 1][pi0] = make_float2(v.y, v.y);
            Xs2[kq + 2][pi0] = make_float2(v.z, v.z);
            Xs2[kq + 3][pi0] = make_float2(v.w, v.w);
            float4 a = ab[u];
            As[kq + 0][pi0] = a.x; As[kq + 1][pi0] = a.y;
            As[kq + 2][pi0] = a.z; As[kq + 3][pi0] = a.w;
        }
        __syncthreads();
        if (kc + KC < K) {
            int gi = ib + pi0;
            xb[0] = make_float4(0.f, 0.f, 0.f, 0.f);
            xb[1] = make_float4(0.f, 0.f, 0.f, 0.f);
            if (gi < M) {
                xb[0] = *(const float4*)&X[(size_t)gi * K + kc + KC + pk0];
                xb[1] = *(const float4*)&X[(size_t)gi * K + kc + KC + pk1];
            }
            ab[0] = *(const float4*)&Wp[(size_t)(jb + pi0) * K + kc + KC + pk0];
            ab[1] = *(const float4*)&Wp[(size_t)(jb + pi0) * K + kc + KC + pk1];
        }
        #pragma unroll
        for (int kk = 0; kk < KC; kk++) {
            ull av[4];
            #pragma unroll
            for (int q = 0; q < 4; q++)
                av[q] = *(const ull*)&As[kk][2 * (tx + 16 * q)];
            // X fragment: 8 contiguous float2 -> 4 x LDS.128
            ulonglong2 x01 = *(const ulonglong2*)&Xs2[kk][ty * 8];
            ulonglong2 x23 = *(const ulonglong2*)&Xs2[kk][ty * 8 + 2];
            ulonglong2 x45 = *(const ulonglong2*)&Xs2[kk][ty * 8 + 4];
            ulonglong2 x67 = *(const ulonglong2*)&Xs2[kk][ty * 8 + 6];
            ull xs[8] = {x01.x, x01.y, x23.x, x23.y, x45.x, x45.y, x67.x, x67.y};
            #pragma unroll
            for (int ii = 0; ii < 8; ii++) {
                #pragma unroll
                for (int q = 0; q < 4; q++)
                    asm("fma.rn.f32x2 %0, %1, %2, %0;"
                        : "+l"(acc[ii][q]) : "l"(xs[ii]), "l"(av[q]));
            }
        }
        __syncthreads();
    }
    int nBlk = N >> 6;
    float2 w[4];
    #pragma unroll
    for (int q = 0; q < 4; q++)
        w[q] = *(const float2*)&a2cat[jb + 2 * (tx + 16 * q)];
    #pragma unroll
    for (int ii = 0; ii < 8; ii++) {
        int gi = ib + ty * 8 + ii;
        float lo[4], hi[4];
        #pragma unroll
        for (int q = 0; q < 4; q++)
            asm("mov.b64 {%0, %1}, %2;" : "=f"(lo[q]), "=f"(hi[q]) : "l"(acc[ii][q]));
        if (gi < M) {
            #pragma unroll
            for (int q = 0; q < 4; q++)
                *(float2*)&C[(size_t)gi * N + jb + 2 * (tx + 16 * q)] = make_float2(lo[q], hi[q]);
        }
        float s0 = lo[0] * w[0].x + hi[0] * w[0].y + lo[1] * w[1].x + hi[1] * w[1].y;
        float s1 = lo[2] * w[2].x + hi[2] * w[2].y + lo[3] * w[3].x + hi[3] * w[3].y;
        #pragma unroll
        for (int o = 8; o; o >>= 1) {
            s0 += __shfl_xor_sync(0xffffffffu, s0, o);
            s1 += __shfl_xor_sync(0xffffffffu, s1, o);
        }
        if (tx == 0 && gi < M) {
            size_t base = (size_t)gi * nBlk + (jb >> 6);
            sOut[base] = s0;
            sOut[base + 1] = s1;
        }
    }
}

// ---------------- gemm_x2: layer-2 projection with FUSED norm1 in the X loader ------
__global__ void __launch_bounds__(256, 2)
gemm_x2(float* __restrict__ C, const float* __restrict__ a2cat,
        float* __restrict__ sOut) {
    __shared__ __align__(16) float2 Xs2[KC][130];
    __shared__ __align__(16) float  As[KC][132];
    int t = threadIdx.x;
    int tx = t & 15, ty = t >> 4;
    int ib = blockIdx.x * 128;
    int jb = blockIdx.y * 128;
    const int M = 2 * N_NODES, N = 256, K = 128;
    ull acc[8][4];
    #pragma unroll
    for (int ii = 0; ii < 8; ii++)
        #pragma unroll
        for (int q = 0; q < 4; q++) acc[ii][q] = 0ull;

    for (int kc = 0; kc < K; kc += KC) {
        #pragma unroll
        for (int p = t; p < 512; p += 256) {
            int i = p & 127, kq = (p >> 7) * 4;
            int gi = ib + i;
            float4 v = make_float4(0.f, 0.f, 0.f, 0.f);
            if (gi < M) {
                int dir = gi >= N_NODES;
                int i2 = dir ? gi - N_NODES : gi;
                int kk = kc + kq;
                float rs = g_rowsum1T[(size_t)i2 * 4 + dir * 2 + (kk >> 6)];
                if (rs > 0.f) {
                    float inv = 1.f / rs;
                    float4 hv = *(const float4*)&g_hp1[dir][(size_t)i2 * 128 + kk];
                    float4 pv = *(const float4*)&g_P1all[(size_t)i2 * 512 + dir * 256 + kk];
                    v.x = hv.x * inv + pv.x;
                    v.y = hv.y * inv + pv.y;
                    v.z = hv.z * inv + pv.z;
                    v.w = hv.w * inv + pv.w;
                }
                v.x = (v.x > 0.f) ? v.x : expm1f(v.x);
                v.y = (v.y > 0.f) ? v.y : expm1f(v.y);
                v.z = (v.z > 0.f) ? v.z : expm1f(v.z);
                v.w = (v.w > 0.f) ? v.w : expm1f(v.w);
            }
            Xs2[kq + 0][i] = make_float2(v.x, v.x);
            Xs2[kq + 1][i] = make_float2(v.y, v.y);
            Xs2[kq + 2][i] = make_float2(v.z, v.z);
            Xs2[kq + 3][i] = make_float2(v.w, v.w);
        }
        #pragma unroll
        for (int p = t; p < 512; p += 256) {
            int j = p & 127, kq = (p >> 7) * 4;
            float4 v = *(const float4*)&g_Wp2[(size_t)(jb + j) * K + kc + kq];
            As[kq + 0][j] = v.x; As[kq + 1][j] = v.y;
            As[kq + 2][j] = v.z; As[kq + 3][j] = v.w;
        }
        __syncthreads();
        #pragma unroll
        for (int kk = 0; kk < KC; kk++) {
            ull av[4];
            #pragma unroll
            for (int q = 0; q < 4; q++)
                av[q] = *(const ull*)&As[kk][2 * (tx + 16 * q)];
            ulonglong2 x01 = *(const ulonglong2*)&Xs2[kk][ty * 8];
            ulonglong2 x23 = *(const ulonglong2*)&Xs2[kk][ty * 8 + 2];
            ulonglong2 x45 = *(const ulonglong2*)&Xs2[kk][ty * 8 + 4];
            ulonglong2 x67 = *(const ulonglong2*)&Xs2[kk][ty * 8 + 6];
            ull xs[8] = {x01.x, x01.y, x23.x, x23.y, x45.x, x45.y, x67.x, x67.y};
            #pragma unroll
            for (int ii = 0; ii < 8; ii++) {
                #pragma unroll
                for (int q = 0; q < 4; q++)
                    asm("fma.rn.f32x2 %0, %1, %2, %0;"
                        : "+l"(acc[ii][q]) : "l"(xs[ii]), "l"(av[q]));
            }
        }
        __syncthreads();
    }
    int nBlk = N >> 6;
    float2 w[4];
    #pragma unroll
    for (int q = 0; q < 4; q++)
        w[q] = *(const float2*)&a2cat[jb + 2 * (tx + 16 * q)];
    #pragma unroll
    for (int ii = 0; ii < 8; ii++) {
        int gi = ib + ty * 8 + ii;
        float lo[4], hi[4];
        #pragma unroll
        for (int q = 0; q < 4; q++)
            asm("mov.b64 {%0, %1}, %2;" : "=f"(lo[q]), "=f"(hi[q]) : "l"(acc[ii][q]));
        if (gi < M) {
            #pragma unroll
            for (int q = 0; q < 4; q++)
                *(float2*)&C[(size_t)gi * N + jb + 2 * (tx + 16 * q)] = make_float2(lo[q], hi[q]);
        }
        float s0 = lo[0] * w[0].x + hi[0] * w[0].y + lo[1] * w[1].x + hi[1] * w[1].y;
        float s1 = lo[2] * w[2].x + hi[2] * w[2].y + lo[3] * w[3].x + hi[3] * w[3].y;
        #pragma unroll
        for (int o = 8; o; o >>= 1) {
            s0 += __shfl_xor_sync(0xffffffffu, s0, o);
            s1 += __shfl_xor_sync(0xffffffffu, s1, o);
        }
        if (tx == 0 && gi < M) {
            size_t base = (size_t)gi * nBlk + (jb >> 6);
            sOut[base] = s0;
            sOut[base + 1] = s1;
        }
    }
}

// ---------------- gemm_q: contiguous-4 columns, LDS.128 X-fragments, 3 CTAs/SM ----
__global__ void __launch_bounds__(256, 3)
gemm_q(const float* __restrict__ X, const int* __restrict__ el,
       const int* __restrict__ eln, const int* __restrict__ etn) {
    __shared__ __align__(16) float2 Xs2[KC][66];
    __shared__ __align__(16) float  As[KC][132];
    int t = threadIdx.x;
    int dir = blockIdx.y;

    if (blockIdx.x >= QBLK64) {
        // ---- nhop edge pass ----
        int e = (blockIdx.x - QBLK64) * 8 + (t >> 5);   // [0, E_NHOP)
        int lane = t & 31;
        int h = lane >> 4;
        int jj = 4 * (lane & 15);
        int i0 = eln[e], i1 = eln[E_NHOP + e];
        int t0 = etn[2 * e], t1 = etn[2 * e + 1];
        float4 qa = *(const float4*)&g_R1proj[t0 * 256 + dir * 128 + h * 64 + jj];
        float4 qb = *(const float4*)&g_R1proj[t1 * 256 + dir * 128 + h * 64 + jj];
        float4 q;
        q.x = qa.x + qb.x; q.y = qa.y + qb.y; q.z = qa.z + qb.z; q.w = qa.w + qb.w;
        float sq = g_Sr1[t0 * 4 + dir * 2 + h] + g_Sr1[t1 * 4 + dir * 2 + h];
        int src = dir ? i1 : i0;
        int dst = dir ? i0 : i1;
        float score = g_S1[(size_t)src * 8 + dir * 4 + h]
                    + g_S1[(size_t)dst * 8 + dir * 4 + 2 + h] + sq;
        float lk = score > 0.f ? score : ALPHA * score;
        float ev = __expf(-lk);
        float4 d = *(const float4*)&g_P1all[(size_t)dst * 512 + dir * 256 + 128 + h * 64 + jj];
        float* hp = &g_hp1[dir][(size_t)src * 128 + h * 64 + jj];
        RED4(hp, ev * (d.x + q.x), ev * (d.y + q.y), ev * (d.z + q.z), ev * (d.w + q.w));
        if ((lane & 15) == 0) atomicAdd(&g_rowsum1T[(size_t)src * 4 + dir * 2 + h], ev);
        return;
    }

    int tx = t & 15, ty = t >> 4;   // ty 0..15, 4 rows each -> 64 rows
    int ib = blockIdx.x * 64;
    int jb = dir * 128;
    const int M = E_REAL, K = 64;
    // acc[ii][0..1]: cols 4tx..4tx+3 (h0); acc[ii][2..3]: cols 4tx+64..+67 (h1)
    ull acc[4][4];
    #pragma unroll
    for (int ii = 0; ii < 4; ii++)
        #pragma unroll
        for (int q = 0; q < 4; q++) acc[ii][q] = 0ull;

    for (int kc = 0; kc < K; kc += KC) {
        {
            int i = t & 63, kq = (t >> 6) * 4;
            int gi = ib + i;
            float4 v = make_float4(0.f, 0.f, 0.f, 0.f);
            if (gi < M) v = *(const float4*)&X[(size_t)gi * K + kc + kq];
            Xs2[kq + 0][i] = make_float2(v.x, v.x);
            Xs2[kq + 1][i] = make_float2(v.y, v.y);
            Xs2[kq + 2][i] = make_float2(v.z, v.z);
            Xs2[kq + 3][i] = make_float2(v.w, v.w);
        }
        #pragma unroll
        for (int p = t; p < 512; p += 256) {
            int j = p & 127, kq = (p >> 7) * 4;
            float4 v = *(const float4*)&g_WpQ[(size_t)(jb + j) * K + kc + kq];
            As[kq + 0][j] = v.x; As[kq + 1][j] = v.y;
            As[kq + 2][j] = v.z; As[kq + 3][j] = v.w;
        }
        __syncthreads();
        #pragma unroll
        for (int kk = 0; kk < KC; kk++) {
            ulonglong2 a01 = *(const ulonglong2*)&As[kk][4 * tx];
            ulonglong2 a23 = *(const ulonglong2*)&As[kk][4 * tx + 64];
            ulonglong2 x01 = *(const ulonglong2*)&Xs2[kk][ty * 4];
            ulonglong2 x23 = *(const ulonglong2*)&Xs2[kk][ty * 4 + 2];
            ull xs[4] = {x01.x, x01.y, x23.x, x23.y};
            #pragma unroll
            for (int ii = 0; ii < 4; ii++) {
                asm("fma.rn.f32x2 %0, %1, %2, %0;" : "+l"(acc[ii][0]) : "l"(xs[ii]), "l"(a01.x));
                asm("fma.rn.f32x2 %0, %1, %2, %0;" : "+l"(acc[ii][1]) : "l"(xs[ii]), "l"(a01.y));
                asm("fma.rn.f32x2 %0, %1, %2, %0;" : "+l"(acc[ii][2]) : "l"(xs[ii]), "l"(a23.x));
                asm("fma.rn.f32x2 %0, %1, %2, %0;" : "+l"(acc[ii][3]) : "l"(xs[ii]), "l"(a23.y));
            }
        }
        __syncthreads();
    }
    // epilogue: fused real-edge attention scatter (contiguous-4, RED4)
    float4 w0 = *(const float4*)&g_a2catQ[jb + 4 * tx];         // h0 cols
    float4 w1 = *(const float4*)&g_a2catQ[jb + 4 * tx + 64];    // h1 cols
    #pragma unroll
    for (int ii = 0; ii < 4; ii++) {
        int gi = ib + ty * 4 + ii;   // edge index
        float f[8];
        #pragma unroll
        for (int q = 0; q < 4; q++)
            asm("mov.b64 {%0, %1}, %2;" : "=f"(f[2 * q]), "=f"(f[2 * q + 1]) : "l"(acc[ii][q]));
        float s0 = f[0] * w0.x + f[1] * w0.y + f[2] * w0.z + f[3] * w0.w;
        float s1 = f[4] * w1.x + f[5] * w1.y + f[6] * w1.z + f[7] * w1.w;
        #pragma unroll
        for (int o = 8; o; o >>= 1) {
            s0 += __shfl_xor_sync(0xffffffffu, s0, o);
            s1 += __shfl_xor_sync(0xffffffffu, s1, o);
        }
        if (gi < M) {
            int i0 = el[gi], i1 = el[E_REAL + gi];
            int src = dir ? i1 : i0;
            int dst = dir ? i0 : i1;
            float4 sv = *(const float4*)&g_S1[(size_t)src * 8 + dir * 4];
            float4 dv = *(const float4*)&g_S1[(size_t)dst * 8 + dir * 4];
            float sc0 = sv.x + dv.z + s0;
            float sc1 = sv.y + dv.w + s1;
            float lk0 = sc0 > 0.f ? sc0 : ALPHA * sc0;
            float lk1 = sc1 > 0.f ? sc1 : ALPHA * sc1;
            float ev0 = __expf(-lk0);
            float ev1 = __expf(-lk1);
            const float* pd = &g_P1all[(size_t)dst * 512 + dir * 256 + 128];
            float* hp = &g_hp1[dir][(size_t)src * 128];
            float4 d0 = *(const float4*)&pd[4 * tx];
            float4 d1 = *(const float4*)&pd[4 * tx + 64];
            RED4(&hp[4 * tx],
                 ev0 * (d0.x + f[0]), ev0 * (d0.y + f[1]),
                 ev0 * (d0.z + f[2]), ev0 * (d0.w + f[3]));
            RED4(&hp[4 * tx + 64],
                 ev1 * (d1.x + f[4]), ev1 * (d1.y + f[5]),
                 ev1 * (d1.z + f[6]), ev1 * (d1.w + f[7]));
            if (tx == 0) {
                atomicAdd(&g_rowsum1T[(size_t)src * 4 + dir * 2], ev0);
                atomicAdd(&g_rowsum1T[(size_t)src * 4 + dir * 2 + 1], ev1);
            }
        }
    }
}

// ---------------- gemm_we: norm2 fused into loader + tanh-dot epilogue ----------------
__global__ void __launch_bounds__(256, 2)
gemm_we(const float* __restrict__ be, const float* __restrict__ qe) {
    __shared__ __align__(16) float2 Xs2[KC][130];
    __shared__ __align__(16) float  As[KC][68];
    __shared__ float s_sh[2];
    int t = threadIdx.x;
    int tx = t & 7, ty = t >> 3;
    int lane = t & 31;
    int ib = blockIdx.x * 128;
    const int M = 2 * N_NODES;
    if (t < 2) s_sh[t] = 0.f;
    const float* hp2f = &g_hp2[0][0];
    const float* rs2f = &g_rowsum2[0][0];
    float* yf = &g_y[0][0];
    ull acc[4][4];
    #pragma unroll
    for (int ii = 0; ii < 4; ii++)
        #pragma unroll
        for (int q = 0; q < 4; q++) acc[ii][q] = 0ull;

    for (int kc = 0; kc < 128; kc += KC) {
        #pragma unroll
        for (int p = t; p < 512; p += 256) {
            int i = p & 127, kq = (p >> 7) * 4;
            int gi = ib + i;
            float4 v = make_float4(0.f, 0.f, 0.f, 0.f);
            if (gi < M) {
                int xs = gi >= N_NODES;
                int ii2 = xs ? gi - N_NODES : gi;
                float rs = rs2f[gi];
                if (rs > 0.f) {
                    float inv = 1.f / rs;
                    float4 hv = *(const float4*)&hp2f[(size_t)gi * 128 + kc + kq];
                    float4 pv = *(const float4*)&g_P2all[xs][(size_t)ii2 * 256 + kc + kq];
                    v.x = hv.x * inv + pv.x;
                    v.y = hv.y * inv + pv.y;
                    v.z = hv.z * inv + pv.z;
                    v.w = hv.w * inv + pv.w;
                }
                v.x = (v.x > 0.f) ? v.x : expm1f(v.x);
                v.y = (v.y > 0.f) ? v.y : expm1f(v.y);
                v.z = (v.z > 0.f) ? v.z : expm1f(v.z);
                v.w = (v.w > 0.f) ? v.w : expm1f(v.w);
                *(float4*)&yf[(size_t)gi * 128 + kc + kq] = v;
            }
            Xs2[kq + 0][i] = make_float2(v.x, v.x);
            Xs2[kq + 1][i] = make_float2(v.y, v.y);
            Xs2[kq + 2][i] = make_float2(v.z, v.z);
            Xs2[kq + 3][i] = make_float2(v.w, v.w);
        }
        {
            int j = t & 63, kq = ((t >> 6) & 3) * 4;
            float4 w = *(const float4*)&g_WeP[j * 128 + kc + kq];
            As[kq + 0][j] = w.x; As[kq + 1][j] = w.y;
            As[kq + 2][j] = w.z; As[kq + 3][j] = w.w;
        }
        __syncthreads();
        #pragma unroll
        for (int kk = 0; kk < KC; kk++) {
            ull av[4];
            #pragma unroll
            for (int q = 0; q < 4; q++)
                av[q] = *(const ull*)&As[kk][2 * (tx + 8 * q)];
            ulonglong2 x01 = *(const ulonglong2*)&Xs2[kk][ty * 4];
            ulonglong2 x23 = *(const ulonglong2*)&Xs2[kk][ty * 4 + 2];
            ull xs[4] = {x01.x, x01.y, x23.x, x23.y};
            #pragma unroll
            for (int ii = 0; ii < 4; ii++) {
                #pragma unroll
                for (int q = 0; q < 4; q++)
                    asm("fma.rn.f32x2 %0, %1, %2, %0;"
                        : "+l"(acc[ii][q]) : "l"(xs[ii]), "l"(av[q]));
            }
        }
        __syncthreads();
    }
    float2 bb[4], qq[4];
    #pragma unroll
    for (int q = 0; q < 4; q++) {
        bb[q] = *(const float2*)&be[2 * (tx + 8 * q)];
        qq[q] = *(const float2*)&qe[2 * (tx + 8 * q)];
    }
    #pragma unroll
    for (int ii = 0; ii < 4; ii++) {
        int gi = ib + ty * 4 + ii;
        float lo[4], hi[4];
        #pragma unroll
        for (int q = 0; q < 4; q++)
            asm("mov.b64 {%0, %1}, %2;" : "=f"(lo[q]), "=f"(hi[q]) : "l"(acc[ii][q]));
        float s = 0.f;
        #pragma unroll
        for (int q = 0; q < 4; q++)
            s += tanhf(lo[q] + bb[q].x) * qq[q].x + tanhf(hi[q] + bb[q].y) * qq[q].y;
        #pragma unroll
        for (int o = 4; o; o >>= 1) s += __shfl_xor_sync(0xffffffffu, s, o);
        if ((lane & 7) == 0 && gi < M)
            atomicAdd(&s_sh[gi >= N_NODES], s);
    }
    __syncthreads();
    if (t < 2) atomicAdd(&g_wsum[t], s_sh[t]);
}

// ---------------- layer-2 edge pass ----------------
__global__ void edge_pass2(const int* __restrict__ el, const int* __restrict__ eln,
                           const int* __restrict__ et, const int* __restrict__ etn) {
    int dir = blockIdx.y;
    int e = blockIdx.x * 8 + (threadIdx.x >> 5);
    if (e >= E_ALL) return;
    int lane = threadIdx.x & 31;
    int i0, i1;
    float q0, q1, q2, q3, sq;
    if (e < E_REAL) {
        i0 = el[e]; i1 = el[E_REAL + e];
        int ty = et[e];
        float4 qv = *(const float4*)&g_R2proj[ty * 128 + 4 * lane];
        q0 = qv.x; q1 = qv.y; q2 = qv.z; q3 = qv.w;
        sq = g_Srel2[ty];
    } else {
        int en = e - E_REAL;
        i0 = eln[en]; i1 = eln[E_NHOP + en];
        int t0 = etn[2 * en], t1 = etn[2 * en + 1];
        float4 qa = *(const float4*)&g_R2proj[t0 * 128 + 4 * lane];
        float4 qb = *(const float4*)&g_R2proj[t1 * 128 + 4 * lane];
        q0 = qa.x + qb.x; q1 = qa.y + qb.y; q2 = qa.z + qb.z; q3 = qa.w + qb.w;
        sq = g_Srel2[t0] + g_Srel2[t1];
    }
    int seg = dir ? i1 : i0;
    int nbr = dir ? i0 : i1;
    float4 sA = *(const float4*)&g_S2[dir][(size_t)seg * 4];
    float4 sB = *(const float4*)&g_S2[dir][(size_t)nbr * 4];
    float score = sA.x + sA.y + sB.z + sB.w + sq;
    float lk = score > 0.f ? score : ALPHA * score;
    float ev = __expf(-lk);
    float4 dv = *(const float4*)&g_P2all[dir][(size_t)nbr * 256 + 128 + 4 * lane];
    float* hp = &g_hp2[dir][(size_t)seg * 128 + 4 * lane];
    RED4(hp, ev * (dv.x + q0), ev * (dv.y + q1), ev * (dv.z + q2), ev * (dv.w + q3));
    if (lane == 0) atomicAdd(&g_rowsum2[dir][seg], ev);
}

// ---------------- beta + combine ----------------
__global__ void combine(float* __restrict__ out) {
    float m0 = g_wsum[0] / (float)N_NODES;
    float m1 = g_wsum[1] / (float)N_NODES;
    float mx = fmaxf(m0, m1);
    float e0 = expf(m0 - mx), e1 = expf(m1 - mx);
    float b0 = e0 / (e0 + e1), b1 = e1 / (e0 + e1);
    size_t i = (size_t)blockIdx.x * 256 + threadIdx.x;
    if (i >= (size_t)N_NODES * OUTF) return;
    out[i] = b0 * g_y[0][i] + b1 * g_y[1][i];
}

// ---------------- launch ----------------
extern "C" void kernel_launch(void* const* d_in, const int* in_sizes, int n_in,
                              void* d_out, int out_size) {
    const float* ent   = (const float*)d_in[0];
    const float* rel   = (const float*)d_in[1];
    const int*   el    = (const int*)d_in[2];
    const int*   et    = (const int*)d_in[3];
    const float* eemb  = (const float*)d_in[4];
    const int*   eln   = (const int*)d_in[5];
    const int*   etn   = (const int*)d_in[6];
    const float* a_in  = (const float*)d_in[7];
    const float* a2_in = (const float*)d_in[8];
    const float* a_out = (const float*)d_in[9];
    const float* a2_out= (const float*)d_in[10];
    const float* a_o   = (const float*)d_in[11];
    const float* a2_o  = (const float*)d_in[12];
    const float* W     = (const float*)d_in[13];
    const float* We    = (const float*)d_in[14];
    const float* be    = (const float*)d_in[15];
    const float* qe    = (const float*)d_in[16];
    float* out = (float*)d_out;

    float *p1 = 0, *p2 = 0, *wp1 = 0;
    float *a2c1 = 0, *a2c2 = 0, *s1 = 0, *s2 = 0;
    cudaGetSymbolAddress((void**)&p1, g_P1all);
    cudaGetSymbolAddress((void**)&p2, g_P2all);
    cudaGetSymbolAddress((void**)&wp1, g_Wp1);
    cudaGetSymbolAddress((void**)&a2c1, g_a2cat1);
    cudaGetSymbolAddress((void**)&a2c2, g_a2cat2);
    cudaGetSymbolAddress((void**)&s1, g_S1);
    cudaGetSymbolAddress((void**)&s2, g_S2);

    cudaStream_t sB;
    cudaStreamCreateWithFlags(&sB, cudaStreamNonBlocking);
    cudaEvent_t evFork, evJoin;
    cudaEventCreateWithFlags(&evFork, cudaEventDisableTiming);
    cudaEventCreateWithFlags(&evJoin, cudaEventDisableTiming);

    cudaEventRecord(evFork, 0);
    cudaStreamWaitEvent(sB, evFork, 0);
    setupB<<<712, 256, 0, sB>>>(a_in, a_out, a_o, a2_in, a2_out, a2_o, rel, W, out);
    cudaEventRecord(evJoin, sB);

    setupA<<<13, 256>>>(a_in, a_out, a_o, a2_in, a2_out, a2_o, We);
    gemm_f32x2<<<dim3((N_NODES + 127) / 128, 4), 256>>>(ent, wp1, p1, a2c1, s1,
                                                        N_NODES, 512, 64);
    cudaStreamWaitEvent(0, evJoin, 0);

    gemm_q<<<dim3(QBLK64 + E_NHOP / 8, 2), 256>>>(eemb, el, eln, etn);

    gemm_x2<<<dim3((2 * N_NODES + 127) / 128, 2), 256>>>(p2, a2c2, s2);

    edge_pass2<<<dim3(E_ALL / 8, 2), 256>>>(el, eln, et, etn);

    gemm_we<<<(2 * N_NODES + 127) / 128, 256>>>(be, qe);
    combine<<<(N_NODES * OUTF + 255) / 256, 256>>>(out);

    cudaStreamDestroy(sB);
    cudaEventDestroy(evFork);
    cudaEventDestroy(evJoin);
}